// round 10
// baseline (speedup 1.0000x reference)
#include <cuda_runtime.h>
#include <cuda_bf16.h>
#include <math.h>

// ---------------------------------------------------------------------------
// Problem constants
// ---------------------------------------------------------------------------
#define NB 8
#define NPTS 2048
#define BNTOT (NB*NPTS)          // 16384
#define KNN 20
#define MEDGE (BNTOT*KNN)        // 327680
#define NEG_SLOPE 0.2f
#define BN_EPS 1e-5f
#define NT 16                    // 2048/128 tiles per dim
#define NPAIRS (NT*(NT+1)/2)     // 136

typedef unsigned long long u64;

// ---------------------------------------------------------------------------
// Packed fp32x2 helpers: per-half rounding identical to scalar ops.
// ---------------------------------------------------------------------------
__device__ __forceinline__ u64 f2_pack(float lo, float hi) {
    u64 d;
    asm("mov.b64 %0, {%1, %2};" : "=l"(d)
        : "r"(__float_as_uint(lo)), "r"(__float_as_uint(hi)));
    return d;
}
__device__ __forceinline__ float2 f2_unpack(u64 d) {
    unsigned lo, hi;
    asm("mov.b64 {%0, %1}, %2;" : "=r"(lo), "=r"(hi) : "l"(d));
    return make_float2(__uint_as_float(lo), __uint_as_float(hi));
}
__device__ __forceinline__ u64 f2_fma(u64 a, u64 b, u64 c) {
    u64 d;
    asm("fma.rn.f32x2 %0, %1, %2, %3;" : "=l"(d) : "l"(a), "l"(b), "l"(c));
    return d;
}
__device__ __forceinline__ u64 f2_add(u64 a, u64 b) {
    u64 d;
    asm("add.rn.f32x2 %0, %1, %2;" : "=l"(d) : "l"(a), "l"(b));
    return d;
}

// ---------------------------------------------------------------------------
// Scratch (device globals -- no allocation allowed)
// ---------------------------------------------------------------------------
__device__ float g_f0  [BNTOT*3];
__device__ float g_x1  [BNTOT*64];
__device__ float g_x2  [BNTOT*64];
__device__ float g_x3  [BNTOT*128];
__device__ float g_x4  [BNTOT*256];
__device__ float g_pd  [(size_t)NB*NPTS*NPTS];       // 134 MB
__device__ int   g_idx [MEDGE];
__device__ float g_wa  [256*128];
__device__ float g_wd  [256*128];
__device__ float g_T   [BNTOT*256];
__device__ float g_hmax[BNTOT*256];
__device__ float g_hmin[BNTOT*256];
__device__ float g_P   [BNTOT*256];
__device__ float g_cat [BNTOT*768];
__device__ float g_gmax[NB*256];
__device__ double g_sum [256];
__device__ double g_sum2[256];
__device__ float g_scale[256];
__device__ float g_shift[256];

// ---------------------------------------------------------------------------
// Small elementwise kernels
// ---------------------------------------------------------------------------
__global__ void transpose_in_kernel(const float* __restrict__ x, float* __restrict__ f) {
    int i = blockIdx.x*256 + threadIdx.x;                 // B*3*N = 49152
    if (i >= NB*3*NPTS) return;
    int b = i / (3*NPTS);
    int rem = i - b*3*NPTS;
    int c = rem / NPTS;
    int n = rem - c*NPTS;
    f[(b*NPTS + n)*3 + c] = x[i];
}

// prep_w also zeroes the BN stat accumulators (block 0) -- saves a launch.
__global__ void prep_w_kernel(const float* __restrict__ W, int O, int C,
                              float* __restrict__ wa, float* __restrict__ wd,
                              double* __restrict__ s0, double* __restrict__ s2) {
    int i = blockIdx.x*256 + threadIdx.x;
    if (blockIdx.x == 0) { s0[threadIdx.x] = 0.0; s2[threadIdx.x] = 0.0; }
    if (i >= O*C) return;
    int o = i / C, c = i - o*C;
    float a = W[o*2*C + c];
    wa[i] = a;
    wd[i] = W[o*2*C + C + c] - a;
}

__global__ void zero_stats_kernel(double* s, double* s2) {
    int t = threadIdx.x;
    if (t < 256) { s[t] = 0.0; s2[t] = 0.0; }
}

// ---------------------------------------------------------------------------
// SYMMETRIC squared-distance kernel: pd[b,i,j] = -sum_c (x_i[c]-x_j[c])^2
// A staged as duplicated (a,a) u64 pairs (pack once); B staged negated.
// Inner loop: 4 LDS.128 (a-pairs) + 2 LDS.128 (b) + 32 add2 + 32 fma2.
// Bitwise identical to the scalar full computation.
// ---------------------------------------------------------------------------
#define ADS 268   // duplicated-A row stride (floats); 268*4 % 16 == 0

template<int KS>
__global__ __launch_bounds__(256, 2)
void dist_sym_kernel(const float* __restrict__ feat, float* __restrict__ pd, int C) {
    __shared__ __align__(16) float As[KS][ADS];    // (a,a) pairs: [k][2r],[k][2r+1]
    __shared__ __align__(16) float Bs[KS][132];    // negated
    int b = blockIdx.z;
    int Lp = blockIdx.x;
    int ti = 0;
    while (Lp >= NT - ti) { Lp -= NT - ti; ti++; }
    int tj = ti + Lp;
    int m0 = ti*128, n0 = tj*128;
    bool diag = (ti == tj);

    const float* F = feat + (size_t)b*NPTS*C;
    int tid = threadIdx.x;
    int tx = tid & 15, ty = tid >> 4;

    u64 acc2[8][4];
#pragma unroll
    for (int i = 0; i < 8; i++)
#pragma unroll
        for (int j = 0; j < 4; j++) acc2[i][j] = 0ull;

    for (int k0 = 0; k0 < C; k0 += KS) {
#pragma unroll
        for (int e = tid; e < 128*KS; e += 256) {
            int c = e % KS, r = e / KS;
            float va = 0.f, vb = 0.f;
            if (k0 + c < C) {
                va = F[(size_t)(m0 + r)*C + k0 + c];
                vb = F[(size_t)(n0 + r)*C + k0 + c];
            }
            *(u64*)&As[c][2*r] = f2_pack(va, va);
            Bs[c][r] = -vb;
        }
        __syncthreads();
#pragma unroll
        for (int k = 0; k < KS; k++) {
            const ulonglong2* ap = (const ulonglong2*)&As[k][ty*16];
            ulonglong2 ap0 = ap[0], ap1 = ap[1], ap2v = ap[2], ap3 = ap[3];
            u64 a2[8] = { ap0.x, ap0.y, ap1.x, ap1.y, ap2v.x, ap2v.y, ap3.x, ap3.y };
            const ulonglong2* bp = (const ulonglong2*)&Bs[k][tx*8];
            ulonglong2 bq0 = bp[0], bq1 = bp[1];
            u64 b2[4] = { bq0.x, bq0.y, bq1.x, bq1.y };
#pragma unroll
            for (int i = 0; i < 8; i++)
#pragma unroll
                for (int jp = 0; jp < 4; jp++) {
                    u64 d2 = f2_add(a2[i], b2[jp]);       // (a-b0, a-b1)
                    acc2[i][jp] = f2_fma(d2, d2, acc2[i][jp]);
                }
        }
        __syncthreads();
    }

    float neg[8][8];
#pragma unroll
    for (int i = 0; i < 8; i++)
#pragma unroll
        for (int jp = 0; jp < 4; jp++) {
            float2 v = f2_unpack(acc2[i][jp]);
            neg[i][2*jp]   = -v.x;
            neg[i][2*jp+1] = -v.y;
        }

    float* pdb = pd + (size_t)b*NPTS*NPTS;
#pragma unroll
    for (int i = 0; i < 8; i++) {
        int m = m0 + ty*8 + i;
        float4 w0 = make_float4(neg[i][0], neg[i][1], neg[i][2], neg[i][3]);
        float4 w1 = make_float4(neg[i][4], neg[i][5], neg[i][6], neg[i][7]);
        float4* dst = (float4*)&pdb[(size_t)m*NPTS + n0 + tx*8];
        dst[0] = w0;
        dst[1] = w1;
    }
    if (!diag) {
#pragma unroll
        for (int j = 0; j < 8; j++) {
            int n = n0 + tx*8 + j;
            float4 w0 = make_float4(neg[0][j], neg[1][j], neg[2][j], neg[3][j]);
            float4 w1 = make_float4(neg[4][j], neg[5][j], neg[6][j], neg[7][j]);
            float4* dst = (float4*)&pdb[(size_t)n*NPTS + m0 + ty*8];
            dst[0] = w0;
            dst[1] = w1;
        }
    }
}

// ---------------------------------------------------------------------------
// WARP-PER-ROW top-K (selection order == jax top_k)
// ---------------------------------------------------------------------------
__global__ __launch_bounds__(256)
void topk_warp_kernel(const float* __restrict__ pd, int* __restrict__ idx) {
    int w = threadIdx.x >> 5, l = threadIdx.x & 31;
    int bn = blockIdx.x*8 + w;
    const float* row = pd + (size_t)bn*NPTS;

    float vals[64];
#pragma unroll
    for (int m = 0; m < 16; m++) {
        float4 v = *(const float4*)(row + m*128 + l*4);
        vals[m*4+0] = v.x; vals[m*4+1] = v.y; vals[m*4+2] = v.z; vals[m*4+3] = v.w;
    }

    unsigned long long excl = 0ull;
    float gv[4]; int gm[4];
#pragma unroll
    for (int g = 0; g < 4; g++) {
        float bv = -INFINITY; int bm = g*16;
#pragma unroll
        for (int m = g*16; m < (g+1)*16; m++)
            if (vals[m] > bv) { bv = vals[m]; bm = m; }
        gv[g] = bv; gm[g] = bm;
    }

    int my_out = 0;
    for (int it = 0; it < KNN; it++) {
        float bv = gv[0]; int bm = gm[0];
#pragma unroll
        for (int g = 1; g < 4; g++)
            if (gv[g] > bv) { bv = gv[g]; bm = gm[g]; }
        int gidx = ((bm >> 2) << 7) + (l << 2) + (bm & 3);

        float v = bv; int ix = gidx;
#pragma unroll
        for (int s = 16; s > 0; s >>= 1) {
            float ov = __shfl_xor_sync(0xffffffff, v, s);
            int   oi = __shfl_xor_sync(0xffffffff, ix, s);
            if (ov > v || (ov == v && oi < ix)) { v = ov; ix = oi; }
        }
        if (l == it) my_out = ix;

        int owner = (ix >> 2) & 31;
        if (l == owner) {
            int sl = ((ix >> 7) << 2) | (ix & 3);
            excl |= 1ull << sl;
            int g = sl >> 4;
            float bv2 = -INFINITY; int bm2 = g*16;
#pragma unroll
            for (int m = 0; m < 16; m++) {
                int mm = 0;
                switch (g) { case 0: mm = m; break; case 1: mm = 16+m; break;
                             case 2: mm = 32+m; break; default: mm = 48+m; }
                if (!((excl >> mm) & 1ull) && vals[mm] > bv2) { bv2 = vals[mm]; bm2 = mm; }
            }
            gv[g] = bv2; gm[g] = bm2;
        }
    }
    if (l < KNN) idx[bn*KNN + l] = my_out;
}

// ---------------------------------------------------------------------------
// Generic NT GEMM (T + point convs): C[m,n] = sum_k A[m,k]*B[n,k], f32x2 inner
// ---------------------------------------------------------------------------
__global__ __launch_bounds__(256)
void gemm_nt_kernel(const float* __restrict__ A, const float* __restrict__ B,
                    float* __restrict__ C, int M, int N, int K) {
    __shared__ __align__(16) float As[16][129];
    __shared__ __align__(16) float Bs[16][66];
    int tid = threadIdx.x;
    int tx = tid & 15;
    int ty = tid >> 4;
    int m0 = blockIdx.x * 128;
    int n0 = blockIdx.y * 64;

    u64 acc2[8][2];
#pragma unroll
    for (int i = 0; i < 8; i++) { acc2[i][0] = 0ull; acc2[i][1] = 0ull; }

    for (int k0 = 0; k0 < K; k0 += 16) {
#pragma unroll
        for (int i = 0; i < 8; i++) {
            int e = tid + i*256;
            int c = e & 15, r = e >> 4;
            int m = m0 + r;
            float v = 0.f;
            if (m < M && k0 + c < K) v = A[(size_t)m*K + k0 + c];
            As[c][r] = v;
        }
#pragma unroll
        for (int i = 0; i < 4; i++) {
            int e = tid + i*256;
            int c = e & 15, r = e >> 4;
            float v = 0.f;
            if (k0 + c < K) v = B[(size_t)(n0 + r)*K + k0 + c];
            Bs[c][r] = v;
        }
        __syncthreads();
#pragma unroll
        for (int k = 0; k < 16; k++) {
            const u64* bp = (const u64*)&Bs[k][tx*4];
            u64 b0 = bp[0], b1 = bp[1];
#pragma unroll
            for (int i = 0; i < 8; i++) {
                float a = As[k][ty*8 + i];
                u64 a2 = f2_pack(a, a);
                acc2[i][0] = f2_fma(a2, b0, acc2[i][0]);
                acc2[i][1] = f2_fma(a2, b1, acc2[i][1]);
            }
        }
        __syncthreads();
    }

#pragma unroll
    for (int i = 0; i < 8; i++) {
        int m = m0 + ty*8 + i;
        if (m >= M) continue;
        float2 v0 = f2_unpack(acc2[i][0]);
        float2 v1 = f2_unpack(acc2[i][1]);
        float* dst = &C[(size_t)m*N + n0 + tx*4];
        dst[0] = v0.x; dst[1] = v0.y; dst[2] = v1.x; dst[3] = v1.y;
    }
}

// ---------------------------------------------------------------------------
// FUSED edge-conv: 8 points x 20 neighbors (160 rows) x 64 channels.
// A staged as duplicated (a,a) u64 pairs; inner: 5 LDS.64 + 2 LDS.128 + 20 fma2.
// ---------------------------------------------------------------------------
#define FP    8
#define FROWS (FP*KNN)            // 160
#define AD_STRIDE 322             // duplicated-A row stride (floats), even
#define BS_BASE   5152            // floats; 5152*4 % 16 == 0; A max idx 5149
#define BS_STRIDE 68
#define STG_STRIDE 66

__global__ __launch_bounds__(256, 2)
void fused_edge_kernel(const float* __restrict__ feat,   // [BNTOT, C]
                       const float* __restrict__ wa,     // [O, C]
                       const float* __restrict__ T,      // [BNTOT, O]
                       const int* __restrict__ idx,      // [BNTOT, KNN]
                       int C, int O,
                       float* __restrict__ hmax, float* __restrict__ hmin,
                       double* __restrict__ gsum, double* __restrict__ gsum2) {
    __shared__ __align__(16) float pool[FROWS*STG_STRIDE];   // 10560 floats
    __shared__ int   sidx[FROWS];
    __shared__ float sT[FP*64];

    int tid = threadIdx.x;
    int p0  = blockIdx.x * FP;
    int n0  = blockIdx.y * 64;

    if (tid < FROWS) {
        int p  = tid / KNN;
        int k  = tid - p*KNN;
        int bn = p0 + p;
        sidx[tid] = (bn >> 11)*NPTS + idx[bn*KNN + k];
    }
    {
        int e = tid;
        sT[e] = T[(size_t)(p0 + (e >> 6))*O + n0 + (e & 63)];
        e += 256;
        sT[e] = T[(size_t)(p0 + (e >> 6))*O + n0 + (e & 63)];
    }
    __syncthreads();

    int tx = tid & 7;
    int ty = tid >> 3;

    u64 acc2[5][4];
#pragma unroll
    for (int i = 0; i < 5; i++)
#pragma unroll
        for (int j = 0; j < 4; j++) acc2[i][j] = 0ull;

    for (int k0 = 0; k0 < C; k0 += 16) {
        // A (gathered), staged as duplicated pairs: pack once per element
#pragma unroll
        for (int i = 0; i < 10; i++) {
            int e = tid + i*256;
            int c = e & 15, r = e >> 4;
            float v = 0.f;
            if (k0 + c < C) v = feat[(size_t)sidx[r]*C + k0 + c];
            *(u64*)&pool[c*AD_STRIDE + 2*r] = f2_pack(v, v);
        }
#pragma unroll
        for (int i = 0; i < 4; i++) {
            int e = tid + i*256;
            int c = e & 15, r = e >> 4;
            float v = 0.f;
            if (k0 + c < C) v = wa[(size_t)(n0 + r)*C + k0 + c];
            pool[BS_BASE + c*BS_STRIDE + r] = v;
        }
        __syncthreads();
#pragma unroll
        for (int k = 0; k < 16; k++) {
            const u64* ap = (const u64*)&pool[k*AD_STRIDE + ty*10];
            const ulonglong2* bp = (const ulonglong2*)&pool[BS_BASE + k*BS_STRIDE + tx*8];
            ulonglong2 bq0 = bp[0], bq1 = bp[1];
            u64 b2[4] = { bq0.x, bq0.y, bq1.x, bq1.y };
#pragma unroll
            for (int i = 0; i < 5; i++) {
                u64 a2 = ap[i];
#pragma unroll
                for (int jp = 0; jp < 4; jp++)
                    acc2[i][jp] = f2_fma(a2, b2[jp], acc2[i][jp]);
            }
        }
        __syncthreads();
    }

#pragma unroll
    for (int i = 0; i < 5; i++) {
        int r = ty*5 + i;
        int p = r / KNN;
#pragma unroll
        for (int jp = 0; jp < 4; jp++) {
            float2 v = f2_unpack(acc2[i][jp]);
            pool[r*STG_STRIDE + tx*8 + 2*jp]     = v.x + sT[p*64 + tx*8 + 2*jp];
            pool[r*STG_STRIDE + tx*8 + 2*jp + 1] = v.y + sT[p*64 + tx*8 + 2*jp + 1];
        }
    }
    __syncthreads();

    int ol = tid & 63;
    int gi = tid >> 6;
    float s = 0.f, s2 = 0.f;
#pragma unroll
    for (int half = 0; half < 2; half++) {
        int p = gi + half*4;
        float mx = -INFINITY, mn = INFINITY;
#pragma unroll
        for (int k = 0; k < KNN; k++) {
            float v = pool[(p*KNN + k)*STG_STRIDE + ol];
            mx = fmaxf(mx, v); mn = fminf(mn, v);
            s += v; s2 += v*v;
        }
        size_t oi = (size_t)(p0 + p)*O + n0 + ol;
        hmax[oi] = mx;
        hmin[oi] = mn;
    }
    __syncthreads();
    sT[gi*64 + ol] = s;
    sT[256 + gi*64 + ol] = s2;
    __syncthreads();
    if (gi == 0) {
        float ts  = sT[ol] + sT[64+ol] + sT[128+ol] + sT[192+ol];
        float ts2 = sT[256+ol] + sT[320+ol] + sT[384+ol] + sT[448+ol];
        atomicAdd(&gsum[n0 + ol],  (double)ts);
        atomicAdd(&gsum2[n0 + ol], (double)ts2);
    }
}

// ---------------------------------------------------------------------------
// Column reduce for point convs (sum/sumsq per channel)
// ---------------------------------------------------------------------------
__global__ __launch_bounds__(256)
void colreduce_kernel(const float* __restrict__ P, int O,
                      double* __restrict__ gsum, double* __restrict__ gsum2) {
    int ol = threadIdx.x & 63;
    int gi = threadIdx.x >> 6;
    int o  = blockIdx.x*64 + ol;
    int r0 = blockIdx.y*256 + gi*64;
    float s = 0.f, s2 = 0.f;
    for (int r = r0; r < r0 + 64; r++) {
        float v = P[(size_t)r*O + o];
        s += v; s2 += v*v;
    }
    __shared__ float ss[4][64], ssq[4][64];
    ss[gi][ol] = s; ssq[gi][ol] = s2;
    __syncthreads();
    if (gi == 0) {
        atomicAdd(&gsum[o],  (double)(ss[0][ol]+ss[1][ol]+ss[2][ol]+ss[3][ol]));
        atomicAdd(&gsum2[o], (double)(ssq[0][ol]+ssq[1][ol]+ssq[2][ol]+ssq[3][ol]));
    }
}

__global__ void bn_params_kernel(const double* __restrict__ gsum, const double* __restrict__ gsum2,
                                 const float* __restrict__ g, const float* __restrict__ b,
                                 int O, double cnt,
                                 float* __restrict__ scale, float* __restrict__ shift) {
    int o = threadIdx.x;
    if (o >= O) return;
    double m   = gsum[o] / cnt;
    double var = gsum2[o] / cnt - m*m;
    float sc = g[o] * rsqrtf((float)var + BN_EPS);
    scale[o] = sc;
    shift[o] = b[o] - (float)m * sc;
}

__global__ void edge_finalize_kernel(const float* __restrict__ hmax, const float* __restrict__ hmin,
                                     const float* __restrict__ scale, const float* __restrict__ shift,
                                     float* __restrict__ out, int O) {
    int i = blockIdx.x*256 + threadIdx.x;
    if (i >= BNTOT*O) return;
    int o = i & (O - 1);
    float sc = scale[o];
    float v = (sc >= 0.f ? hmax[i] : hmin[i]) * sc + shift[o];
    out[i] = v >= 0.f ? v : NEG_SLOPE*v;
}

// h6: act + global max over n per (b,o)
__global__ __launch_bounds__(256)
void h6_finalize_kernel(const float* __restrict__ P,
                        const float* __restrict__ scale, const float* __restrict__ shift,
                        float* __restrict__ gmax) {
    int ol = threadIdx.x & 63;
    int gi = threadIdx.x >> 6;
    int o = blockIdx.x*64 + ol;
    int b = blockIdx.y;
    float sc = scale[o], sh = shift[o];
    float mx = -INFINITY;
    for (int n = gi*512; n < (gi+1)*512; n++) {
        float v = P[((size_t)(b*NPTS + n))*256 + o]*sc + sh;
        v = v >= 0.f ? v : NEG_SLOPE*v;
        mx = fmaxf(mx, v);
    }
    __shared__ float sm[4][64];
    sm[gi][ol] = mx;
    __syncthreads();
    if (gi == 0)
        gmax[b*256 + o] = fmaxf(fmaxf(sm[0][ol], sm[1][ol]), fmaxf(sm[2][ol], sm[3][ol]));
}

__global__ void cat_kernel(const float* __restrict__ x1, const float* __restrict__ x2,
                           const float* __restrict__ x3, const float* __restrict__ x4,
                           const float* __restrict__ gmax, float* __restrict__ cat) {
    size_t i = (size_t)blockIdx.x*256 + threadIdx.x;
    if (i >= (size_t)BNTOT*768) return;
    int bn = (int)(i / 768);
    int c  = (int)(i - (size_t)bn*768);
    float v;
    if      (c < 64)  v = x1[bn*64  + c];
    else if (c < 128) v = x2[bn*64  + c - 64];
    else if (c < 256) v = x3[bn*128 + c - 128];
    else if (c < 512) v = x4[bn*256 + c - 256];
    else              v = gmax[(bn >> 11)*256 + c - 512];
    cat[i] = v;
}

// final: act + transpose (B,N,256) -> (B,256,N)
__global__ void out_transpose_kernel(const float* __restrict__ P,
                                     const float* __restrict__ scale, const float* __restrict__ shift,
                                     float* __restrict__ out) {
    __shared__ float tile[32][33];
    int b  = blockIdx.z;
    int n0 = blockIdx.x*32, o0 = blockIdx.y*32;
    int tx = threadIdx.x, ty = threadIdx.y;
    int o = o0 + tx;
    float v = P[((size_t)(b*NPTS + n0 + ty))*256 + o]*scale[o] + shift[o];
    v = v >= 0.f ? v : NEG_SLOPE*v;
    tile[ty][tx] = v;
    __syncthreads();
    out[(size_t)b*256*NPTS + (size_t)(o0 + ty)*NPTS + n0 + tx] = tile[tx][ty];
}

// ---------------------------------------------------------------------------
// Host side
// ---------------------------------------------------------------------------
static void* sym(const void* s) { void* p = nullptr; cudaGetSymbolAddress(&p, s); return p; }

extern "C" void kernel_launch(void* const* d_in, const int* in_sizes, int n_in,
                              void* d_out, int out_size) {
    const float* x  = (const float*)d_in[0];
    const float* W[4] = { (const float*)d_in[1], (const float*)d_in[4],
                          (const float*)d_in[7], (const float*)d_in[10] };
    const float* G[4] = { (const float*)d_in[2], (const float*)d_in[5],
                          (const float*)d_in[8], (const float*)d_in[11] };
    const float* Bb[4] = { (const float*)d_in[3], (const float*)d_in[6],
                           (const float*)d_in[9], (const float*)d_in[12] };
    const float* W6 = (const float*)d_in[13];
    const float* g6 = (const float*)d_in[14];
    const float* b6 = (const float*)d_in[15];
    const float* W5 = (const float*)d_in[16];
    const float* g5 = (const float*)d_in[17];
    const float* b5 = (const float*)d_in[18];

    float*  f0   = (float*)sym(g_f0);
    float*  x1   = (float*)sym(g_x1);
    float*  x2   = (float*)sym(g_x2);
    float*  x3   = (float*)sym(g_x3);
    float*  x4   = (float*)sym(g_x4);
    float*  pd   = (float*)sym(g_pd);
    int*    idx  = (int*)  sym(g_idx);
    float*  wa   = (float*)sym(g_wa);
    float*  wd   = (float*)sym(g_wd);
    float*  Tb   = (float*)sym(g_T);
    float*  hmax = (float*)sym(g_hmax);
    float*  hmin = (float*)sym(g_hmin);
    float*  Pb   = (float*)sym(g_P);
    float*  cat  = (float*)sym(g_cat);
    float*  gmax = (float*)sym(g_gmax);
    double* s0   = (double*)sym(g_sum);
    double* s2   = (double*)sym(g_sum2);
    float*  sc   = (float*)sym(g_scale);
    float*  sh   = (float*)sym(g_shift);

    // input transpose (B,3,N) -> (B,N,3)
    transpose_in_kernel<<<(NB*3*NPTS + 255)/256, 256>>>(x, f0);

    const float* feats[4] = { f0, x1, x2, x3 };
    float*       outs [4] = { x1, x2, x3, x4 };
    const int    Cs[4] = { 3, 64, 64, 128 };
    const int    Os[4] = { 64, 64, 128, 256 };

    for (int L = 0; L < 4; L++) {
        int C = Cs[L], O = Os[L];
        const float* feat = feats[L];

        prep_w_kernel<<<(O*C + 255)/256, 256>>>(W[L], O, C, wa, wd, s0, s2);
        gemm_nt_kernel<<<dim3((BNTOT + 127)/128, O/64), 256>>>(feat, wd, Tb, BNTOT, O, C);

        // kNN: symmetric negative squared distance + warp-per-row top-20
        dim3 ggrid(NPAIRS, 1, NB);
        if (C == 3) dist_sym_kernel<4><<<ggrid, 256>>>(feat, pd, C);
        else        dist_sym_kernel<16><<<ggrid, 256>>>(feat, pd, C);
        topk_warp_kernel<<<BNTOT/8, 256>>>(pd, idx);

        fused_edge_kernel<<<dim3(BNTOT/FP, O/64), 256>>>(
            feat, wa, Tb, idx, C, O, hmax, hmin, s0, s2);
        bn_params_kernel<<<1, 256>>>(s0, s2, G[L], Bb[L], O, (double)MEDGE, sc, sh);
        edge_finalize_kernel<<<(BNTOT*O + 255)/256, 256>>>(hmax, hmin, sc, sh, outs[L], O);
    }

    // --- point conv h6 = lrelu(bn(x4 . W6^T)), then x5 = max over n ---
    gemm_nt_kernel<<<dim3(BNTOT/128, 256/64), 256>>>(x4, W6, Pb, BNTOT, 256, 256);
    zero_stats_kernel<<<1, 256>>>(s0, s2);
    colreduce_kernel<<<dim3(256/64, BNTOT/256), 256>>>(Pb, 256, s0, s2);
    bn_params_kernel<<<1, 256>>>(s0, s2, g6, b6, 256, (double)BNTOT, sc, sh);
    h6_finalize_kernel<<<dim3(256/64, NB), 256>>>(Pb, sc, sh, gmax);

    // --- concat [x1,x2,x3,x4,x5] -> 768 ---
    cat_kernel<<<(int)(((size_t)BNTOT*768 + 255)/256), 256>>>(x1, x2, x3, x4, gmax, cat);

    // --- final point conv + transpose output ---
    gemm_nt_kernel<<<dim3(BNTOT/128, 256/64), 256>>>(cat, W5, Pb, BNTOT, 256, 768);
    zero_stats_kernel<<<1, 256>>>(s0, s2);
    colreduce_kernel<<<dim3(256/64, BNTOT/256), 256>>>(Pb, 256, s0, s2);
    bn_params_kernel<<<1, 256>>>(s0, s2, g5, b5, 256, (double)BNTOT, sc, sh);
    out_transpose_kernel<<<dim3(NPTS/32, 256/32, NB), dim3(32, 32)>>>(Pb, sc, sh, (float*)d_out);
}

// round 11
// speedup vs baseline: 1.0782x; 1.0782x over previous
#include <cuda_runtime.h>
#include <cuda_bf16.h>
#include <math.h>

// ---------------------------------------------------------------------------
// Problem constants
// ---------------------------------------------------------------------------
#define NB 8
#define NPTS 2048
#define BNTOT (NB*NPTS)          // 16384
#define KNN 20
#define MEDGE (BNTOT*KNN)        // 327680
#define NEG_SLOPE 0.2f
#define BN_EPS 1e-5f
#define NT 16                    // 2048/128 tiles per dim
#define NPAIRS (NT*(NT+1)/2)     // 136

typedef unsigned long long u64;

// ---------------------------------------------------------------------------
// Packed fp32x2 helpers: per-half rounding identical to scalar ops.
// ---------------------------------------------------------------------------
__device__ __forceinline__ u64 f2_pack(float lo, float hi) {
    u64 d;
    asm("mov.b64 %0, {%1, %2};" : "=l"(d)
        : "r"(__float_as_uint(lo)), "r"(__float_as_uint(hi)));
    return d;
}
__device__ __forceinline__ float2 f2_unpack(u64 d) {
    unsigned lo, hi;
    asm("mov.b64 {%0, %1}, %2;" : "=r"(lo), "=r"(hi) : "l"(d));
    return make_float2(__uint_as_float(lo), __uint_as_float(hi));
}
__device__ __forceinline__ u64 f2_fma(u64 a, u64 b, u64 c) {
    u64 d;
    asm("fma.rn.f32x2 %0, %1, %2, %3;" : "=l"(d) : "l"(a), "l"(b), "l"(c));
    return d;
}
__device__ __forceinline__ u64 f2_add(u64 a, u64 b) {
    u64 d;
    asm("add.rn.f32x2 %0, %1, %2;" : "=l"(d) : "l"(a), "l"(b));
    return d;
}

// ---------------------------------------------------------------------------
// Scratch (device globals -- no allocation allowed)
// ---------------------------------------------------------------------------
__device__ float g_f0  [BNTOT*3];
__device__ float g_x1  [BNTOT*64];
__device__ float g_x2  [BNTOT*64];
__device__ float g_x3  [BNTOT*128];
__device__ float g_x4  [BNTOT*256];
__device__ float g_pd  [(size_t)NB*NPTS*NPTS];       // 134 MB
__device__ int   g_idx [MEDGE];
__device__ float g_wa  [256*128];
__device__ float g_wd  [256*128];
__device__ float g_T   [BNTOT*256];
__device__ float g_hmax[BNTOT*256];
__device__ float g_hmin[BNTOT*256];
__device__ float g_P   [BNTOT*256];
__device__ float g_cat [BNTOT*768];
__device__ float g_gmax[NB*256];
__device__ double g_sum [256];
__device__ double g_sum2[256];
__device__ float g_scale[256];
__device__ float g_shift[256];

// ---------------------------------------------------------------------------
// Small elementwise kernels
// ---------------------------------------------------------------------------
__global__ void transpose_in_kernel(const float* __restrict__ x, float* __restrict__ f) {
    int i = blockIdx.x*256 + threadIdx.x;                 // B*3*N = 49152
    if (i >= NB*3*NPTS) return;
    int b = i / (3*NPTS);
    int rem = i - b*3*NPTS;
    int c = rem / NPTS;
    int n = rem - c*NPTS;
    f[(b*NPTS + n)*3 + c] = x[i];
}

// prep_w also zeroes the BN stat accumulators (block 0) -- saves a launch.
__global__ void prep_w_kernel(const float* __restrict__ W, int O, int C,
                              float* __restrict__ wa, float* __restrict__ wd,
                              double* __restrict__ s0, double* __restrict__ s2) {
    int i = blockIdx.x*256 + threadIdx.x;
    if (blockIdx.x == 0) { s0[threadIdx.x] = 0.0; s2[threadIdx.x] = 0.0; }
    if (i >= O*C) return;
    int o = i / C, c = i - o*C;
    float a = W[o*2*C + c];
    wa[i] = a;
    wd[i] = W[o*2*C + C + c] - a;
}

__global__ void zero_stats_kernel(double* s, double* s2) {
    int t = threadIdx.x;
    if (t < 256) { s[t] = 0.0; s2[t] = 0.0; }
}

// ---------------------------------------------------------------------------
// SYMMETRIC squared-distance kernel: pd[b,i,j] = -sum_c (x_i[c]-x_j[c])^2
// (R9 form -- bitwise identical to scalar full computation.)
// ---------------------------------------------------------------------------
template<int KS>
__global__ __launch_bounds__(256)
void dist_sym_kernel(const float* __restrict__ feat, float* __restrict__ pd, int C) {
    __shared__ __align__(16) float As[KS][132];
    __shared__ __align__(16) float Bs[KS][132];
    int b = blockIdx.z;
    int Lp = blockIdx.x;
    int ti = 0;
    while (Lp >= NT - ti) { Lp -= NT - ti; ti++; }
    int tj = ti + Lp;
    int m0 = ti*128, n0 = tj*128;
    bool diag = (ti == tj);

    const float* F = feat + (size_t)b*NPTS*C;
    int tid = threadIdx.x;
    int tx = tid & 15, ty = tid >> 4;

    u64 acc2[8][4];
#pragma unroll
    for (int i = 0; i < 8; i++)
#pragma unroll
        for (int j = 0; j < 4; j++) acc2[i][j] = 0ull;

    for (int k0 = 0; k0 < C; k0 += KS) {
#pragma unroll
        for (int e = tid; e < 128*KS; e += 256) {
            int c = e % KS, r = e / KS;
            float va = 0.f, vb = 0.f;
            if (k0 + c < C) {
                va = F[(size_t)(m0 + r)*C + k0 + c];
                vb = F[(size_t)(n0 + r)*C + k0 + c];
            }
            As[c][r] = va;
            Bs[c][r] = -vb;          // negate so inner loop uses add.f32x2
        }
        __syncthreads();
#pragma unroll
        for (int k = 0; k < KS; k++) {
            float af[8];
#pragma unroll
            for (int i = 0; i < 8; i++) af[i] = As[k][ty*8 + i];
            const u64* bp = (const u64*)&Bs[k][tx*8];
            u64 b2[4] = { bp[0], bp[1], bp[2], bp[3] };
#pragma unroll
            for (int i = 0; i < 8; i++) {
                u64 a2 = f2_pack(af[i], af[i]);
#pragma unroll
                for (int jp = 0; jp < 4; jp++) {
                    u64 d2 = f2_add(a2, b2[jp]);       // (a-b0, a-b1)
                    acc2[i][jp] = f2_fma(d2, d2, acc2[i][jp]);
                }
            }
        }
        __syncthreads();
    }

    float neg[8][8];
#pragma unroll
    for (int i = 0; i < 8; i++)
#pragma unroll
        for (int jp = 0; jp < 4; jp++) {
            float2 v = f2_unpack(acc2[i][jp]);
            neg[i][2*jp]   = -v.x;
            neg[i][2*jp+1] = -v.y;
        }

    float* pdb = pd + (size_t)b*NPTS*NPTS;
#pragma unroll
    for (int i = 0; i < 8; i++) {
        int m = m0 + ty*8 + i;
        float4 w0 = make_float4(neg[i][0], neg[i][1], neg[i][2], neg[i][3]);
        float4 w1 = make_float4(neg[i][4], neg[i][5], neg[i][6], neg[i][7]);
        float4* dst = (float4*)&pdb[(size_t)m*NPTS + n0 + tx*8];
        dst[0] = w0;
        dst[1] = w1;
    }
    if (!diag) {
#pragma unroll
        for (int j = 0; j < 8; j++) {
            int n = n0 + tx*8 + j;
            float4 w0 = make_float4(neg[0][j], neg[1][j], neg[2][j], neg[3][j]);
            float4 w1 = make_float4(neg[4][j], neg[5][j], neg[6][j], neg[7][j]);
            float4* dst = (float4*)&pdb[(size_t)n*NPTS + m0 + ty*8];
            dst[0] = w0;
            dst[1] = w1;
        }
    }
}

// ---------------------------------------------------------------------------
// WARP-PER-ROW top-K (selection order == jax top_k)
// ---------------------------------------------------------------------------
__global__ __launch_bounds__(256)
void topk_warp_kernel(const float* __restrict__ pd, int* __restrict__ idx) {
    int w = threadIdx.x >> 5, l = threadIdx.x & 31;
    int bn = blockIdx.x*8 + w;
    const float* row = pd + (size_t)bn*NPTS;

    float vals[64];
#pragma unroll
    for (int m = 0; m < 16; m++) {
        float4 v = *(const float4*)(row + m*128 + l*4);
        vals[m*4+0] = v.x; vals[m*4+1] = v.y; vals[m*4+2] = v.z; vals[m*4+3] = v.w;
    }

    unsigned long long excl = 0ull;
    float gv[4]; int gm[4];
#pragma unroll
    for (int g = 0; g < 4; g++) {
        float bv = -INFINITY; int bm = g*16;
#pragma unroll
        for (int m = g*16; m < (g+1)*16; m++)
            if (vals[m] > bv) { bv = vals[m]; bm = m; }
        gv[g] = bv; gm[g] = bm;
    }

    int my_out = 0;
    for (int it = 0; it < KNN; it++) {
        float bv = gv[0]; int bm = gm[0];
#pragma unroll
        for (int g = 1; g < 4; g++)
            if (gv[g] > bv) { bv = gv[g]; bm = gm[g]; }
        int gidx = ((bm >> 2) << 7) + (l << 2) + (bm & 3);

        float v = bv; int ix = gidx;
#pragma unroll
        for (int s = 16; s > 0; s >>= 1) {
            float ov = __shfl_xor_sync(0xffffffff, v, s);
            int   oi = __shfl_xor_sync(0xffffffff, ix, s);
            if (ov > v || (ov == v && oi < ix)) { v = ov; ix = oi; }
        }
        if (l == it) my_out = ix;

        int owner = (ix >> 2) & 31;
        if (l == owner) {
            int sl = ((ix >> 7) << 2) | (ix & 3);
            excl |= 1ull << sl;
            int g = sl >> 4;
            float bv2 = -INFINITY; int bm2 = g*16;
#pragma unroll
            for (int m = 0; m < 16; m++) {
                int mm = 0;
                switch (g) { case 0: mm = m; break; case 1: mm = 16+m; break;
                             case 2: mm = 32+m; break; default: mm = 48+m; }
                if (!((excl >> mm) & 1ull) && vals[mm] > bv2) { bv2 = vals[mm]; bm2 = mm; }
            }
            gv[g] = bv2; gm[g] = bm2;
        }
    }
    if (l < KNN) idx[bn*KNN + l] = my_out;
}

// ---------------------------------------------------------------------------
// Generic NT GEMM (T + point convs): C[m,n] = sum_k A[m,k]*B[n,k], f32x2 inner,
// with register-prefetch pipelining of the global loads.
// ---------------------------------------------------------------------------
__global__ __launch_bounds__(256)
void gemm_nt_kernel(const float* __restrict__ A, const float* __restrict__ B,
                    float* __restrict__ C, int M, int N, int K) {
    __shared__ __align__(16) float As[16][129];
    __shared__ __align__(16) float Bs[16][66];
    int tid = threadIdx.x;
    int tx = tid & 15;
    int ty = tid >> 4;
    int m0 = blockIdx.x * 128;
    int n0 = blockIdx.y * 64;

    u64 acc2[8][2];
#pragma unroll
    for (int i = 0; i < 8; i++) { acc2[i][0] = 0ull; acc2[i][1] = 0ull; }

    float pa[8], pb[4];
    // prefetch slice k0 = 0
#pragma unroll
    for (int i = 0; i < 8; i++) {
        int e = tid + i*256;
        int c = e & 15, r = e >> 4;
        int m = m0 + r;
        pa[i] = (m < M && c < K) ? A[(size_t)m*K + c] : 0.f;
    }
#pragma unroll
    for (int i = 0; i < 4; i++) {
        int e = tid + i*256;
        int c = e & 15, r = e >> 4;
        pb[i] = (c < K) ? B[(size_t)(n0 + r)*K + c] : 0.f;
    }

    for (int k0 = 0; k0 < K; k0 += 16) {
        // store prefetched slice to smem
#pragma unroll
        for (int i = 0; i < 8; i++) {
            int e = tid + i*256;
            As[e & 15][e >> 4] = pa[i];
        }
#pragma unroll
        for (int i = 0; i < 4; i++) {
            int e = tid + i*256;
            Bs[e & 15][e >> 4] = pb[i];
        }
        __syncthreads();
        // prefetch next slice (overlaps with compute below)
        int kn = k0 + 16;
        if (kn < K) {
#pragma unroll
            for (int i = 0; i < 8; i++) {
                int e = tid + i*256;
                int c = e & 15, r = e >> 4;
                int m = m0 + r;
                pa[i] = (m < M && kn + c < K) ? A[(size_t)m*K + kn + c] : 0.f;
            }
#pragma unroll
            for (int i = 0; i < 4; i++) {
                int e = tid + i*256;
                int c = e & 15, r = e >> 4;
                pb[i] = (kn + c < K) ? B[(size_t)(n0 + r)*K + kn + c] : 0.f;
            }
        }
#pragma unroll
        for (int k = 0; k < 16; k++) {
            const u64* bp = (const u64*)&Bs[k][tx*4];
            u64 b0 = bp[0], b1 = bp[1];
#pragma unroll
            for (int i = 0; i < 8; i++) {
                float a = As[k][ty*8 + i];
                u64 a2 = f2_pack(a, a);
                acc2[i][0] = f2_fma(a2, b0, acc2[i][0]);
                acc2[i][1] = f2_fma(a2, b1, acc2[i][1]);
            }
        }
        __syncthreads();
    }

#pragma unroll
    for (int i = 0; i < 8; i++) {
        int m = m0 + ty*8 + i;
        if (m >= M) continue;
        float2 v0 = f2_unpack(acc2[i][0]);
        float2 v1 = f2_unpack(acc2[i][1]);
        float* dst = &C[(size_t)m*N + n0 + tx*4];
        dst[0] = v0.x; dst[1] = v0.y; dst[2] = v1.x; dst[3] = v1.y;
    }
}

// ---------------------------------------------------------------------------
// FUSED edge-conv: 8 points x 20 neighbors (160 rows) x 64 channels, f32x2,
// with register-prefetch pipelining of the gathered global loads.
// ---------------------------------------------------------------------------
#define FP    8
#define FROWS (FP*KNN)            // 160
#define AS_STRIDE 161             // 161 % 32 == 1  -> conflict-free
#define BS_BASE   (16*AS_STRIDE)  // 2576 floats (16B aligned)
#define BS_STRIDE 68              // rows 16B aligned
#define STG_STRIDE 66

__global__ __launch_bounds__(256)
void fused_edge_kernel(const float* __restrict__ feat,   // [BNTOT, C]
                       const float* __restrict__ wa,     // [O, C]
                       const float* __restrict__ T,      // [BNTOT, O]
                       const int* __restrict__ idx,      // [BNTOT, KNN]
                       int C, int O,
                       float* __restrict__ hmax, float* __restrict__ hmin,
                       double* __restrict__ gsum, double* __restrict__ gsum2) {
    __shared__ __align__(16) float pool[FROWS*STG_STRIDE];   // 10560 floats
    __shared__ int   sidx[FROWS];
    __shared__ float sT[FP*64];

    int tid = threadIdx.x;
    int p0  = blockIdx.x * FP;
    int n0  = blockIdx.y * 64;

    if (tid < FROWS) {
        int p  = tid / KNN;
        int k  = tid - p*KNN;
        int bn = p0 + p;
        sidx[tid] = (bn >> 11)*NPTS + idx[bn*KNN + k];
    }
    {
        int e = tid;
        sT[e] = T[(size_t)(p0 + (e >> 6))*O + n0 + (e & 63)];
        e += 256;
        sT[e] = T[(size_t)(p0 + (e >> 6))*O + n0 + (e & 63)];
    }
    __syncthreads();

    int tx = tid & 7;
    int ty = tid >> 3;

    u64 acc2[5][4];
#pragma unroll
    for (int i = 0; i < 5; i++)
#pragma unroll
        for (int j = 0; j < 4; j++) acc2[i][j] = 0ull;

    float pa[10], pb[4];
    // prefetch slice k0 = 0
#pragma unroll
    for (int i = 0; i < 10; i++) {
        int e = tid + i*256;
        int c = e & 15, r = e >> 4;
        pa[i] = (c < C) ? feat[(size_t)sidx[r]*C + c] : 0.f;
    }
#pragma unroll
    for (int i = 0; i < 4; i++) {
        int e = tid + i*256;
        int c = e & 15, r = e >> 4;
        pb[i] = (c < C) ? wa[(size_t)(n0 + r)*C + c] : 0.f;
    }

    for (int k0 = 0; k0 < C; k0 += 16) {
        // store prefetched slice
#pragma unroll
        for (int i = 0; i < 10; i++) {
            int e = tid + i*256;
            pool[(e & 15)*AS_STRIDE + (e >> 4)] = pa[i];
        }
#pragma unroll
        for (int i = 0; i < 4; i++) {
            int e = tid + i*256;
            pool[BS_BASE + (e & 15)*BS_STRIDE + (e >> 4)] = pb[i];
        }
        __syncthreads();
        // prefetch next slice (overlaps with compute below)
        int kn = k0 + 16;
        if (kn < C) {
#pragma unroll
            for (int i = 0; i < 10; i++) {
                int e = tid + i*256;
                int c = e & 15, r = e >> 4;
                pa[i] = (kn + c < C) ? feat[(size_t)sidx[r]*C + kn + c] : 0.f;
            }
#pragma unroll
            for (int i = 0; i < 4; i++) {
                int e = tid + i*256;
                int c = e & 15, r = e >> 4;
                pb[i] = (kn + c < C) ? wa[(size_t)(n0 + r)*C + kn + c] : 0.f;
            }
        }
#pragma unroll
        for (int k = 0; k < 16; k++) {
            const u64* bp = (const u64*)&pool[BS_BASE + k*BS_STRIDE + tx*8];
            u64 b2[4] = { bp[0], bp[1], bp[2], bp[3] };
#pragma unroll
            for (int i = 0; i < 5; i++) {
                float a = pool[k*AS_STRIDE + ty*5 + i];
                u64 a2 = f2_pack(a, a);
#pragma unroll
                for (int jp = 0; jp < 4; jp++)
                    acc2[i][jp] = f2_fma(a2, b2[jp], acc2[i][jp]);
            }
        }
        __syncthreads();
    }

#pragma unroll
    for (int i = 0; i < 5; i++) {
        int r = ty*5 + i;
        int p = r / KNN;
#pragma unroll
        for (int jp = 0; jp < 4; jp++) {
            float2 v = f2_unpack(acc2[i][jp]);
            pool[r*STG_STRIDE + tx*8 + 2*jp]     = v.x + sT[p*64 + tx*8 + 2*jp];
            pool[r*STG_STRIDE + tx*8 + 2*jp + 1] = v.y + sT[p*64 + tx*8 + 2*jp + 1];
        }
    }
    __syncthreads();

    int ol = tid & 63;
    int gi = tid >> 6;
    float s = 0.f, s2 = 0.f;
#pragma unroll
    for (int half = 0; half < 2; half++) {
        int p = gi + half*4;
        float mx = -INFINITY, mn = INFINITY;
#pragma unroll
        for (int k = 0; k < KNN; k++) {
            float v = pool[(p*KNN + k)*STG_STRIDE + ol];
            mx = fmaxf(mx, v); mn = fminf(mn, v);
            s += v; s2 += v*v;
        }
        size_t oi = (size_t)(p0 + p)*O + n0 + ol;
        hmax[oi] = mx;
        hmin[oi] = mn;
    }
    __syncthreads();
    sT[gi*64 + ol] = s;
    sT[256 + gi*64 + ol] = s2;
    __syncthreads();
    if (gi == 0) {
        float ts  = sT[ol] + sT[64+ol] + sT[128+ol] + sT[192+ol];
        float ts2 = sT[256+ol] + sT[320+ol] + sT[384+ol] + sT[448+ol];
        atomicAdd(&gsum[n0 + ol],  (double)ts);
        atomicAdd(&gsum2[n0 + ol], (double)ts2);
    }
}

// ---------------------------------------------------------------------------
// Column reduce for point convs (sum/sumsq per channel)
// ---------------------------------------------------------------------------
__global__ __launch_bounds__(256)
void colreduce_kernel(const float* __restrict__ P, int O,
                      double* __restrict__ gsum, double* __restrict__ gsum2) {
    int ol = threadIdx.x & 63;
    int gi = threadIdx.x >> 6;
    int o  = blockIdx.x*64 + ol;
    int r0 = blockIdx.y*256 + gi*64;
    float s = 0.f, s2 = 0.f;
    for (int r = r0; r < r0 + 64; r++) {
        float v = P[(size_t)r*O + o];
        s += v; s2 += v*v;
    }
    __shared__ float ss[4][64], ssq[4][64];
    ss[gi][ol] = s; ssq[gi][ol] = s2;
    __syncthreads();
    if (gi == 0) {
        atomicAdd(&gsum[o],  (double)(ss[0][ol]+ss[1][ol]+ss[2][ol]+ss[3][ol]));
        atomicAdd(&gsum2[o], (double)(ssq[0][ol]+ssq[1][ol]+ssq[2][ol]+ssq[3][ol]));
    }
}

__global__ void bn_params_kernel(const double* __restrict__ gsum, const double* __restrict__ gsum2,
                                 const float* __restrict__ g, const float* __restrict__ b,
                                 int O, double cnt,
                                 float* __restrict__ scale, float* __restrict__ shift) {
    int o = threadIdx.x;
    if (o >= O) return;
    double m   = gsum[o] / cnt;
    double var = gsum2[o] / cnt - m*m;
    float sc = g[o] * rsqrtf((float)var + BN_EPS);
    scale[o] = sc;
    shift[o] = b[o] - (float)m * sc;
}

__global__ void edge_finalize_kernel(const float* __restrict__ hmax, const float* __restrict__ hmin,
                                     const float* __restrict__ scale, const float* __restrict__ shift,
                                     float* __restrict__ out, int O) {
    int i = blockIdx.x*256 + threadIdx.x;
    if (i >= BNTOT*O) return;
    int o = i & (O - 1);
    float sc = scale[o];
    float v = (sc >= 0.f ? hmax[i] : hmin[i]) * sc + shift[o];
    out[i] = v >= 0.f ? v : NEG_SLOPE*v;
}

// h6: act + global max over n per (b,o)
__global__ __launch_bounds__(256)
void h6_finalize_kernel(const float* __restrict__ P,
                        const float* __restrict__ scale, const float* __restrict__ shift,
                        float* __restrict__ gmax) {
    int ol = threadIdx.x & 63;
    int gi = threadIdx.x >> 6;
    int o = blockIdx.x*64 + ol;
    int b = blockIdx.y;
    float sc = scale[o], sh = shift[o];
    float mx = -INFINITY;
    for (int n = gi*512; n < (gi+1)*512; n++) {
        float v = P[((size_t)(b*NPTS + n))*256 + o]*sc + sh;
        v = v >= 0.f ? v : NEG_SLOPE*v;
        mx = fmaxf(mx, v);
    }
    __shared__ float sm[4][64];
    sm[gi][ol] = mx;
    __syncthreads();
    if (gi == 0)
        gmax[b*256 + o] = fmaxf(fmaxf(sm[0][ol], sm[1][ol]), fmaxf(sm[2][ol], sm[3][ol]));
}

__global__ void cat_kernel(const float* __restrict__ x1, const float* __restrict__ x2,
                           const float* __restrict__ x3, const float* __restrict__ x4,
                           const float* __restrict__ gmax, float* __restrict__ cat) {
    size_t i = (size_t)blockIdx.x*256 + threadIdx.x;
    if (i >= (size_t)BNTOT*768) return;
    int bn = (int)(i / 768);
    int c  = (int)(i - (size_t)bn*768);
    float v;
    if      (c < 64)  v = x1[bn*64  + c];
    else if (c < 128) v = x2[bn*64  + c - 64];
    else if (c < 256) v = x3[bn*128 + c - 128];
    else if (c < 512) v = x4[bn*256 + c - 256];
    else              v = gmax[(bn >> 11)*256 + c - 512];
    cat[i] = v;
}

// final: act + transpose (B,N,256) -> (B,256,N)
__global__ void out_transpose_kernel(const float* __restrict__ P,
                                     const float* __restrict__ scale, const float* __restrict__ shift,
                                     float* __restrict__ out) {
    __shared__ float tile[32][33];
    int b  = blockIdx.z;
    int n0 = blockIdx.x*32, o0 = blockIdx.y*32;
    int tx = threadIdx.x, ty = threadIdx.y;
    int o = o0 + tx;
    float v = P[((size_t)(b*NPTS + n0 + ty))*256 + o]*scale[o] + shift[o];
    v = v >= 0.f ? v : NEG_SLOPE*v;
    tile[ty][tx] = v;
    __syncthreads();
    out[(size_t)b*256*NPTS + (size_t)(o0 + ty)*NPTS + n0 + tx] = tile[tx][ty];
}

// ---------------------------------------------------------------------------
// Host side
// ---------------------------------------------------------------------------
static void* sym(const void* s) { void* p = nullptr; cudaGetSymbolAddress(&p, s); return p; }

extern "C" void kernel_launch(void* const* d_in, const int* in_sizes, int n_in,
                              void* d_out, int out_size) {
    const float* x  = (const float*)d_in[0];
    const float* W[4] = { (const float*)d_in[1], (const float*)d_in[4],
                          (const float*)d_in[7], (const float*)d_in[10] };
    const float* G[4] = { (const float*)d_in[2], (const float*)d_in[5],
                          (const float*)d_in[8], (const float*)d_in[11] };
    const float* Bb[4] = { (const float*)d_in[3], (const float*)d_in[6],
                           (const float*)d_in[9], (const float*)d_in[12] };
    const float* W6 = (const float*)d_in[13];
    const float* g6 = (const float*)d_in[14];
    const float* b6 = (const float*)d_in[15];
    const float* W5 = (const float*)d_in[16];
    const float* g5 = (const float*)d_in[17];
    const float* b5 = (const float*)d_in[18];

    float*  f0   = (float*)sym(g_f0);
    float*  x1   = (float*)sym(g_x1);
    float*  x2   = (float*)sym(g_x2);
    float*  x3   = (float*)sym(g_x3);
    float*  x4   = (float*)sym(g_x4);
    float*  pd   = (float*)sym(g_pd);
    int*    idx  = (int*)  sym(g_idx);
    float*  wa   = (float*)sym(g_wa);
    float*  wd   = (float*)sym(g_wd);
    float*  Tb   = (float*)sym(g_T);
    float*  hmax = (float*)sym(g_hmax);
    float*  hmin = (float*)sym(g_hmin);
    float*  Pb   = (float*)sym(g_P);
    float*  cat  = (float*)sym(g_cat);
    float*  gmax = (float*)sym(g_gmax);
    double* s0   = (double*)sym(g_sum);
    double* s2   = (double*)sym(g_sum2);
    float*  sc   = (float*)sym(g_scale);
    float*  sh   = (float*)sym(g_shift);

    // input transpose (B,3,N) -> (B,N,3)
    transpose_in_kernel<<<(NB*3*NPTS + 255)/256, 256>>>(x, f0);

    const float* feats[4] = { f0, x1, x2, x3 };
    float*       outs [4] = { x1, x2, x3, x4 };
    const int    Cs[4] = { 3, 64, 64, 128 };
    const int    Os[4] = { 64, 64, 128, 256 };

    for (int L = 0; L < 4; L++) {
        int C = Cs[L], O = Os[L];
        const float* feat = feats[L];

        prep_w_kernel<<<(O*C + 255)/256, 256>>>(W[L], O, C, wa, wd, s0, s2);
        gemm_nt_kernel<<<dim3((BNTOT + 127)/128, O/64), 256>>>(feat, wd, Tb, BNTOT, O, C);

        // kNN: symmetric negative squared distance + warp-per-row top-20
        dim3 ggrid(NPAIRS, 1, NB);
        if (C == 3) dist_sym_kernel<4><<<ggrid, 256>>>(feat, pd, C);
        else        dist_sym_kernel<16><<<ggrid, 256>>>(feat, pd, C);
        topk_warp_kernel<<<BNTOT/8, 256>>>(pd, idx);

        fused_edge_kernel<<<dim3(BNTOT/FP, O/64), 256>>>(
            feat, wa, Tb, idx, C, O, hmax, hmin, s0, s2);
        bn_params_kernel<<<1, 256>>>(s0, s2, G[L], Bb[L], O, (double)MEDGE, sc, sh);
        edge_finalize_kernel<<<(BNTOT*O + 255)/256, 256>>>(hmax, hmin, sc, sh, outs[L], O);
    }

    // --- point conv h6 = lrelu(bn(x4 . W6^T)), then x5 = max over n ---
    gemm_nt_kernel<<<dim3(BNTOT/128, 256/64), 256>>>(x4, W6, Pb, BNTOT, 256, 256);
    zero_stats_kernel<<<1, 256>>>(s0, s2);
    colreduce_kernel<<<dim3(256/64, BNTOT/256), 256>>>(Pb, 256, s0, s2);
    bn_params_kernel<<<1, 256>>>(s0, s2, g6, b6, 256, (double)BNTOT, sc, sh);
    h6_finalize_kernel<<<dim3(256/64, NB), 256>>>(Pb, sc, sh, gmax);

    // --- concat [x1,x2,x3,x4,x5] -> 768 ---
    cat_kernel<<<(int)(((size_t)BNTOT*768 + 255)/256), 256>>>(x1, x2, x3, x4, gmax, cat);

    // --- final point conv + transpose output ---
    gemm_nt_kernel<<<dim3(BNTOT/128, 256/64), 256>>>(cat, W5, Pb, BNTOT, 256, 768);
    zero_stats_kernel<<<1, 256>>>(s0, s2);
    colreduce_kernel<<<dim3(256/64, BNTOT/256), 256>>>(Pb, 256, s0, s2);
    bn_params_kernel<<<1, 256>>>(s0, s2, g5, b5, 256, (double)BNTOT, sc, sh);
    out_transpose_kernel<<<dim3(NPTS/32, 256/32, NB), dim3(32, 32)>>>(Pb, sc, sh, (float*)d_out);
}

// round 12
// speedup vs baseline: 1.0827x; 1.0041x over previous
#include <cuda_runtime.h>
#include <cuda_bf16.h>
#include <math.h>

// ---------------------------------------------------------------------------
// Problem constants
// ---------------------------------------------------------------------------
#define NB 8
#define NPTS 2048
#define BNTOT (NB*NPTS)          // 16384
#define KNN 20
#define MEDGE (BNTOT*KNN)        // 327680
#define NEG_SLOPE 0.2f
#define BN_EPS 1e-5f
#define NT 16                    // 2048/128 tiles per dim
#define NPAIRS (NT*(NT+1)/2)     // 136

typedef unsigned long long u64;

// ---------------------------------------------------------------------------
// Packed fp32x2 helpers: per-half rounding identical to scalar ops.
// ---------------------------------------------------------------------------
__device__ __forceinline__ u64 f2_pack(float lo, float hi) {
    u64 d;
    asm("mov.b64 %0, {%1, %2};" : "=l"(d)
        : "r"(__float_as_uint(lo)), "r"(__float_as_uint(hi)));
    return d;
}
__device__ __forceinline__ float2 f2_unpack(u64 d) {
    unsigned lo, hi;
    asm("mov.b64 {%0, %1}, %2;" : "=r"(lo), "=r"(hi) : "l"(d));
    return make_float2(__uint_as_float(lo), __uint_as_float(hi));
}
__device__ __forceinline__ u64 f2_fma(u64 a, u64 b, u64 c) {
    u64 d;
    asm("fma.rn.f32x2 %0, %1, %2, %3;" : "=l"(d) : "l"(a), "l"(b), "l"(c));
    return d;
}
__device__ __forceinline__ u64 f2_add(u64 a, u64 b) {
    u64 d;
    asm("add.rn.f32x2 %0, %1, %2;" : "=l"(d) : "l"(a), "l"(b));
    return d;
}

// ---------------------------------------------------------------------------
// Scratch (device globals -- no allocation allowed)
// ---------------------------------------------------------------------------
__device__ float g_f0  [BNTOT*3];
__device__ float g_x1  [BNTOT*64];
__device__ float g_x2  [BNTOT*64];
__device__ float g_x3  [BNTOT*128];
__device__ float g_x4  [BNTOT*256];
__device__ float g_pd  [(size_t)NB*NPTS*NPTS];       // 134 MB
__device__ int   g_idx [MEDGE];
__device__ float g_wa  [256*128];
__device__ float g_wd  [256*128];
__device__ float g_T   [BNTOT*256];
__device__ float g_hmax[BNTOT*256];
__device__ float g_hmin[BNTOT*256];
__device__ float g_P   [BNTOT*256];
__device__ float g_gmax[NB*256];
__device__ double g_sum [256];
__device__ double g_sum2[256];
__device__ float g_scale[256];
__device__ float g_shift[256];

// ---------------------------------------------------------------------------
// Small elementwise kernels
// ---------------------------------------------------------------------------
__global__ void transpose_in_kernel(const float* __restrict__ x, float* __restrict__ f) {
    int i = blockIdx.x*256 + threadIdx.x;                 // B*3*N = 49152
    if (i >= NB*3*NPTS) return;
    int b = i / (3*NPTS);
    int rem = i - b*3*NPTS;
    int c = rem / NPTS;
    int n = rem - c*NPTS;
    f[(b*NPTS + n)*3 + c] = x[i];
}

// prep_w also zeroes the BN stat accumulators (block 0) -- saves a launch.
__global__ void prep_w_kernel(const float* __restrict__ W, int O, int C,
                              float* __restrict__ wa, float* __restrict__ wd,
                              double* __restrict__ s0, double* __restrict__ s2) {
    int i = blockIdx.x*256 + threadIdx.x;
    if (blockIdx.x == 0) { s0[threadIdx.x] = 0.0; s2[threadIdx.x] = 0.0; }
    if (i >= O*C) return;
    int o = i / C, c = i - o*C;
    float a = W[o*2*C + c];
    wa[i] = a;
    wd[i] = W[o*2*C + C + c] - a;
}

__global__ void zero_stats_kernel(double* s, double* s2) {
    int t = threadIdx.x;
    if (t < 256) { s[t] = 0.0; s2[t] = 0.0; }
}

// ---------------------------------------------------------------------------
// SYMMETRIC squared-distance kernel: pd[b,i,j] = -sum_c (x_i[c]-x_j[c])^2
// (R9/R11 form -- bitwise identical to scalar full computation.)
// ---------------------------------------------------------------------------
template<int KS>
__global__ __launch_bounds__(256)
void dist_sym_kernel(const float* __restrict__ feat, float* __restrict__ pd, int C) {
    __shared__ __align__(16) float As[KS][132];
    __shared__ __align__(16) float Bs[KS][132];
    int b = blockIdx.z;
    int Lp = blockIdx.x;
    int ti = 0;
    while (Lp >= NT - ti) { Lp -= NT - ti; ti++; }
    int tj = ti + Lp;
    int m0 = ti*128, n0 = tj*128;
    bool diag = (ti == tj);

    const float* F = feat + (size_t)b*NPTS*C;
    int tid = threadIdx.x;
    int tx = tid & 15, ty = tid >> 4;

    u64 acc2[8][4];
#pragma unroll
    for (int i = 0; i < 8; i++)
#pragma unroll
        for (int j = 0; j < 4; j++) acc2[i][j] = 0ull;

    for (int k0 = 0; k0 < C; k0 += KS) {
#pragma unroll
        for (int e = tid; e < 128*KS; e += 256) {
            int c = e % KS, r = e / KS;
            float va = 0.f, vb = 0.f;
            if (k0 + c < C) {
                va = F[(size_t)(m0 + r)*C + k0 + c];
                vb = F[(size_t)(n0 + r)*C + k0 + c];
            }
            As[c][r] = va;
            Bs[c][r] = -vb;          // negate so inner loop uses add.f32x2
        }
        __syncthreads();
#pragma unroll
        for (int k = 0; k < KS; k++) {
            float af[8];
#pragma unroll
            for (int i = 0; i < 8; i++) af[i] = As[k][ty*8 + i];
            const u64* bp = (const u64*)&Bs[k][tx*8];
            u64 b2[4] = { bp[0], bp[1], bp[2], bp[3] };
#pragma unroll
            for (int i = 0; i < 8; i++) {
                u64 a2 = f2_pack(af[i], af[i]);
#pragma unroll
                for (int jp = 0; jp < 4; jp++) {
                    u64 d2 = f2_add(a2, b2[jp]);       // (a-b0, a-b1)
                    acc2[i][jp] = f2_fma(d2, d2, acc2[i][jp]);
                }
            }
        }
        __syncthreads();
    }

    float neg[8][8];
#pragma unroll
    for (int i = 0; i < 8; i++)
#pragma unroll
        for (int jp = 0; jp < 4; jp++) {
            float2 v = f2_unpack(acc2[i][jp]);
            neg[i][2*jp]   = -v.x;
            neg[i][2*jp+1] = -v.y;
        }

    float* pdb = pd + (size_t)b*NPTS*NPTS;
#pragma unroll
    for (int i = 0; i < 8; i++) {
        int m = m0 + ty*8 + i;
        float4 w0 = make_float4(neg[i][0], neg[i][1], neg[i][2], neg[i][3]);
        float4 w1 = make_float4(neg[i][4], neg[i][5], neg[i][6], neg[i][7]);
        float4* dst = (float4*)&pdb[(size_t)m*NPTS + n0 + tx*8];
        dst[0] = w0;
        dst[1] = w1;
    }
    if (!diag) {
#pragma unroll
        for (int j = 0; j < 8; j++) {
            int n = n0 + tx*8 + j;
            float4 w0 = make_float4(neg[0][j], neg[1][j], neg[2][j], neg[3][j]);
            float4 w1 = make_float4(neg[4][j], neg[5][j], neg[6][j], neg[7][j]);
            float4* dst = (float4*)&pdb[(size_t)n*NPTS + m0 + ty*8];
            dst[0] = w0;
            dst[1] = w1;
        }
    }
}

// ---------------------------------------------------------------------------
// WARP-PER-ROW top-K (selection order == jax top_k)
// ---------------------------------------------------------------------------
__global__ __launch_bounds__(256)
void topk_warp_kernel(const float* __restrict__ pd, int* __restrict__ idx) {
    int w = threadIdx.x >> 5, l = threadIdx.x & 31;
    int bn = blockIdx.x*8 + w;
    const float* row = pd + (size_t)bn*NPTS;

    float vals[64];
#pragma unroll
    for (int m = 0; m < 16; m++) {
        float4 v = *(const float4*)(row + m*128 + l*4);
        vals[m*4+0] = v.x; vals[m*4+1] = v.y; vals[m*4+2] = v.z; vals[m*4+3] = v.w;
    }

    unsigned long long excl = 0ull;
    float gv[4]; int gm[4];
#pragma unroll
    for (int g = 0; g < 4; g++) {
        float bv = -INFINITY; int bm = g*16;
#pragma unroll
        for (int m = g*16; m < (g+1)*16; m++)
            if (vals[m] > bv) { bv = vals[m]; bm = m; }
        gv[g] = bv; gm[g] = bm;
    }

    int my_out = 0;
    for (int it = 0; it < KNN; it++) {
        float bv = gv[0]; int bm = gm[0];
#pragma unroll
        for (int g = 1; g < 4; g++)
            if (gv[g] > bv) { bv = gv[g]; bm = gm[g]; }
        int gidx = ((bm >> 2) << 7) + (l << 2) + (bm & 3);

        float v = bv; int ix = gidx;
#pragma unroll
        for (int s = 16; s > 0; s >>= 1) {
            float ov = __shfl_xor_sync(0xffffffff, v, s);
            int   oi = __shfl_xor_sync(0xffffffff, ix, s);
            if (ov > v || (ov == v && oi < ix)) { v = ov; ix = oi; }
        }
        if (l == it) my_out = ix;

        int owner = (ix >> 2) & 31;
        if (l == owner) {
            int sl = ((ix >> 7) << 2) | (ix & 3);
            excl |= 1ull << sl;
            int g = sl >> 4;
            float bv2 = -INFINITY; int bm2 = g*16;
#pragma unroll
            for (int m = 0; m < 16; m++) {
                int mm = 0;
                switch (g) { case 0: mm = m; break; case 1: mm = 16+m; break;
                             case 2: mm = 32+m; break; default: mm = 48+m; }
                if (!((excl >> mm) & 1ull) && vals[mm] > bv2) { bv2 = vals[mm]; bm2 = mm; }
            }
            gv[g] = bv2; gm[g] = bm2;
        }
    }
    if (l < KNN) idx[bn*KNN + l] = my_out;
}

// ---------------------------------------------------------------------------
// Generic NT GEMM: C[m,n] = sum_k A[m,k]*B[n,k], f32x2 inner, LDG prefetch.
// Optional fused per-channel sum/sumsq (BN stats) via block partials + atomics.
// ---------------------------------------------------------------------------
__global__ __launch_bounds__(256)
void gemm_nt_kernel(const float* __restrict__ A, const float* __restrict__ B,
                    float* __restrict__ C, int M, int N, int K,
                    double* __restrict__ gsum, double* __restrict__ gsum2) {
    __shared__ __align__(16) float As[16][129];
    __shared__ __align__(16) float Bs[16][66];
    int tid = threadIdx.x;
    int tx = tid & 15;
    int ty = tid >> 4;
    int m0 = blockIdx.x * 128;
    int n0 = blockIdx.y * 64;

    u64 acc2[8][2];
#pragma unroll
    for (int i = 0; i < 8; i++) { acc2[i][0] = 0ull; acc2[i][1] = 0ull; }

    float pa[8], pb[4];
#pragma unroll
    for (int i = 0; i < 8; i++) {
        int e = tid + i*256;
        int c = e & 15, r = e >> 4;
        int m = m0 + r;
        pa[i] = (m < M && c < K) ? A[(size_t)m*K + c] : 0.f;
    }
#pragma unroll
    for (int i = 0; i < 4; i++) {
        int e = tid + i*256;
        int c = e & 15, r = e >> 4;
        pb[i] = (c < K) ? B[(size_t)(n0 + r)*K + c] : 0.f;
    }

    for (int k0 = 0; k0 < K; k0 += 16) {
#pragma unroll
        for (int i = 0; i < 8; i++) {
            int e = tid + i*256;
            As[e & 15][e >> 4] = pa[i];
        }
#pragma unroll
        for (int i = 0; i < 4; i++) {
            int e = tid + i*256;
            Bs[e & 15][e >> 4] = pb[i];
        }
        __syncthreads();
        int kn = k0 + 16;
        if (kn < K) {
#pragma unroll
            for (int i = 0; i < 8; i++) {
                int e = tid + i*256;
                int c = e & 15, r = e >> 4;
                int m = m0 + r;
                pa[i] = (m < M && kn + c < K) ? A[(size_t)m*K + kn + c] : 0.f;
            }
#pragma unroll
            for (int i = 0; i < 4; i++) {
                int e = tid + i*256;
                int c = e & 15, r = e >> 4;
                pb[i] = (kn + c < K) ? B[(size_t)(n0 + r)*K + kn + c] : 0.f;
            }
        }
#pragma unroll
        for (int k = 0; k < 16; k++) {
            const u64* bp = (const u64*)&Bs[k][tx*4];
            u64 b0 = bp[0], b1 = bp[1];
#pragma unroll
            for (int i = 0; i < 8; i++) {
                float a = As[k][ty*8 + i];
                u64 a2 = f2_pack(a, a);
                acc2[i][0] = f2_fma(a2, b0, acc2[i][0]);
                acc2[i][1] = f2_fma(a2, b1, acc2[i][1]);
            }
        }
        __syncthreads();
    }

    float cs[4] = {0.f,0.f,0.f,0.f}, cq[4] = {0.f,0.f,0.f,0.f};
#pragma unroll
    for (int i = 0; i < 8; i++) {
        int m = m0 + ty*8 + i;
        if (m >= M) continue;
        float2 v0 = f2_unpack(acc2[i][0]);
        float2 v1 = f2_unpack(acc2[i][1]);
        float* dst = &C[(size_t)m*N + n0 + tx*4];
        dst[0] = v0.x; dst[1] = v0.y; dst[2] = v1.x; dst[3] = v1.y;
        cs[0] += v0.x; cq[0] += v0.x*v0.x;
        cs[1] += v0.y; cq[1] += v0.y*v0.y;
        cs[2] += v1.x; cq[2] += v1.x*v1.x;
        cs[3] += v1.y; cq[3] += v1.y*v1.y;
    }

    if (gsum) {
        // block-level channel partials via smem (reuse As storage: 2064 >= 2048)
        float* sred = &As[0][0];
#pragma unroll
        for (int j = 0; j < 4; j++) {
            sred[ty*64 + tx*4 + j]        = cs[j];
            sred[1024 + ty*64 + tx*4 + j] = cq[j];
        }
        __syncthreads();
        if (tid < 64) {
            float S = 0.f, Q = 0.f;
#pragma unroll
            for (int t = 0; t < 16; t++) {
                S += sred[t*64 + tid];
                Q += sred[1024 + t*64 + tid];
            }
            atomicAdd(&gsum[n0 + tid],  (double)S);
            atomicAdd(&gsum2[n0 + tid], (double)Q);
        }
    }
}

// ---------------------------------------------------------------------------
// GEMM over the virtual concat [x1|x2|x3|x4|gmax] (K=768), fused BN stats.
// Region boundaries (64,128,256,512) are 16-aligned -> uniform per-slice fetch.
// ---------------------------------------------------------------------------
__device__ __forceinline__ float cat_fetch(int m, int c,
                                           const float* __restrict__ x1,
                                           const float* __restrict__ x2,
                                           const float* __restrict__ x3,
                                           const float* __restrict__ x4,
                                           const float* __restrict__ gmax) {
    if (c < 64)   return x1[m*64 + c];
    if (c < 128)  return x2[m*64 + c - 64];
    if (c < 256)  return x3[m*128 + c - 128];
    if (c < 512)  return x4[m*256 + c - 256];
    return gmax[(m >> 11)*256 + c - 512];
}

__global__ __launch_bounds__(256)
void gemm_cat_kernel(const float* __restrict__ x1, const float* __restrict__ x2,
                     const float* __restrict__ x3, const float* __restrict__ x4,
                     const float* __restrict__ gmax,
                     const float* __restrict__ B,
                     float* __restrict__ C,
                     double* __restrict__ gsum, double* __restrict__ gsum2) {
    const int N = 256, K = 768;
    __shared__ __align__(16) float As[16][129];
    __shared__ __align__(16) float Bs[16][66];
    int tid = threadIdx.x;
    int tx = tid & 15;
    int ty = tid >> 4;
    int m0 = blockIdx.x * 128;
    int n0 = blockIdx.y * 64;

    u64 acc2[8][2];
#pragma unroll
    for (int i = 0; i < 8; i++) { acc2[i][0] = 0ull; acc2[i][1] = 0ull; }

    float pa[8], pb[4];
#pragma unroll
    for (int i = 0; i < 8; i++) {
        int e = tid + i*256;
        int c = e & 15, r = e >> 4;
        pa[i] = cat_fetch(m0 + r, c, x1, x2, x3, x4, gmax);
    }
#pragma unroll
    for (int i = 0; i < 4; i++) {
        int e = tid + i*256;
        int c = e & 15, r = e >> 4;
        pb[i] = B[(size_t)(n0 + r)*K + c];
    }

    for (int k0 = 0; k0 < K; k0 += 16) {
#pragma unroll
        for (int i = 0; i < 8; i++) {
            int e = tid + i*256;
            As[e & 15][e >> 4] = pa[i];
        }
#pragma unroll
        for (int i = 0; i < 4; i++) {
            int e = tid + i*256;
            Bs[e & 15][e >> 4] = pb[i];
        }
        __syncthreads();
        int kn = k0 + 16;
        if (kn < K) {
#pragma unroll
            for (int i = 0; i < 8; i++) {
                int e = tid + i*256;
                int c = e & 15, r = e >> 4;
                pa[i] = cat_fetch(m0 + r, kn + c, x1, x2, x3, x4, gmax);
            }
#pragma unroll
            for (int i = 0; i < 4; i++) {
                int e = tid + i*256;
                int c = e & 15, r = e >> 4;
                pb[i] = B[(size_t)(n0 + r)*K + kn + c];
            }
        }
#pragma unroll
        for (int k = 0; k < 16; k++) {
            const u64* bp = (const u64*)&Bs[k][tx*4];
            u64 b0 = bp[0], b1 = bp[1];
#pragma unroll
            for (int i = 0; i < 8; i++) {
                float a = As[k][ty*8 + i];
                u64 a2 = f2_pack(a, a);
                acc2[i][0] = f2_fma(a2, b0, acc2[i][0]);
                acc2[i][1] = f2_fma(a2, b1, acc2[i][1]);
            }
        }
        __syncthreads();
    }

    float cs[4] = {0.f,0.f,0.f,0.f}, cq[4] = {0.f,0.f,0.f,0.f};
#pragma unroll
    for (int i = 0; i < 8; i++) {
        int m = m0 + ty*8 + i;
        float2 v0 = f2_unpack(acc2[i][0]);
        float2 v1 = f2_unpack(acc2[i][1]);
        float* dst = &C[(size_t)m*N + n0 + tx*4];
        dst[0] = v0.x; dst[1] = v0.y; dst[2] = v1.x; dst[3] = v1.y;
        cs[0] += v0.x; cq[0] += v0.x*v0.x;
        cs[1] += v0.y; cq[1] += v0.y*v0.y;
        cs[2] += v1.x; cq[2] += v1.x*v1.x;
        cs[3] += v1.y; cq[3] += v1.y*v1.y;
    }

    float* sred = &As[0][0];
#pragma unroll
    for (int j = 0; j < 4; j++) {
        sred[ty*64 + tx*4 + j]        = cs[j];
        sred[1024 + ty*64 + tx*4 + j] = cq[j];
    }
    __syncthreads();
    if (tid < 64) {
        float S = 0.f, Q = 0.f;
#pragma unroll
        for (int t = 0; t < 16; t++) {
            S += sred[t*64 + tid];
            Q += sred[1024 + t*64 + tid];
        }
        atomicAdd(&gsum[n0 + tid],  (double)S);
        atomicAdd(&gsum2[n0 + tid], (double)Q);
    }
}

// ---------------------------------------------------------------------------
// FUSED edge-conv: 8 points x 20 neighbors (160 rows) x 64 channels, f32x2,
// register-prefetch pipelined gathered loads. (R11 form.)
// ---------------------------------------------------------------------------
#define FP    8
#define FROWS (FP*KNN)            // 160
#define AS_STRIDE 161             // 161 % 32 == 1  -> conflict-free
#define BS_BASE   (16*AS_STRIDE)  // 2576 floats (16B aligned)
#define BS_STRIDE 68              // rows 16B aligned
#define STG_STRIDE 66

__global__ __launch_bounds__(256)
void fused_edge_kernel(const float* __restrict__ feat,   // [BNTOT, C]
                       const float* __restrict__ wa,     // [O, C]
                       const float* __restrict__ T,      // [BNTOT, O]
                       const int* __restrict__ idx,      // [BNTOT, KNN]
                       int C, int O,
                       float* __restrict__ hmax, float* __restrict__ hmin,
                       double* __restrict__ gsum, double* __restrict__ gsum2) {
    __shared__ __align__(16) float pool[FROWS*STG_STRIDE];   // 10560 floats
    __shared__ int   sidx[FROWS];
    __shared__ float sT[FP*64];

    int tid = threadIdx.x;
    int p0  = blockIdx.x * FP;
    int n0  = blockIdx.y * 64;

    if (tid < FROWS) {
        int p  = tid / KNN;
        int k  = tid - p*KNN;
        int bn = p0 + p;
        sidx[tid] = (bn >> 11)*NPTS + idx[bn*KNN + k];
    }
    {
        int e = tid;
        sT[e] = T[(size_t)(p0 + (e >> 6))*O + n0 + (e & 63)];
        e += 256;
        sT[e] = T[(size_t)(p0 + (e >> 6))*O + n0 + (e & 63)];
    }
    __syncthreads();

    int tx = tid & 7;
    int ty = tid >> 3;

    u64 acc2[5][4];
#pragma unroll
    for (int i = 0; i < 5; i++)
#pragma unroll
        for (int j = 0; j < 4; j++) acc2[i][j] = 0ull;

    float pa[10], pb[4];
#pragma unroll
    for (int i = 0; i < 10; i++) {
        int e = tid + i*256;
        int c = e & 15, r = e >> 4;
        pa[i] = (c < C) ? feat[(size_t)sidx[r]*C + c] : 0.f;
    }
#pragma unroll
    for (int i = 0; i < 4; i++) {
        int e = tid + i*256;
        int c = e & 15, r = e >> 4;
        pb[i] = (c < C) ? wa[(size_t)(n0 + r)*C + c] : 0.f;
    }

    for (int k0 = 0; k0 < C; k0 += 16) {
#pragma unroll
        for (int i = 0; i < 10; i++) {
            int e = tid + i*256;
            pool[(e & 15)*AS_STRIDE + (e >> 4)] = pa[i];
        }
#pragma unroll
        for (int i = 0; i < 4; i++) {
            int e = tid + i*256;
            pool[BS_BASE + (e & 15)*BS_STRIDE + (e >> 4)] = pb[i];
        }
        __syncthreads();
        int kn = k0 + 16;
        if (kn < C) {
#pragma unroll
            for (int i = 0; i < 10; i++) {
                int e = tid + i*256;
                int c = e & 15, r = e >> 4;
                pa[i] = (kn + c < C) ? feat[(size_t)sidx[r]*C + kn + c] : 0.f;
            }
#pragma unroll
            for (int i = 0; i < 4; i++) {
                int e = tid + i*256;
                int c = e & 15, r = e >> 4;
                pb[i] = (kn + c < C) ? wa[(size_t)(n0 + r)*C + kn + c] : 0.f;
            }
        }
#pragma unroll
        for (int k = 0; k < 16; k++) {
            const u64* bp = (const u64*)&pool[BS_BASE + k*BS_STRIDE + tx*8];
            u64 b2[4] = { bp[0], bp[1], bp[2], bp[3] };
#pragma unroll
            for (int i = 0; i < 5; i++) {
                float a = pool[k*AS_STRIDE + ty*5 + i];
                u64 a2 = f2_pack(a, a);
#pragma unroll
                for (int jp = 0; jp < 4; jp++)
                    acc2[i][jp] = f2_fma(a2, b2[jp], acc2[i][jp]);
            }
        }
        __syncthreads();
    }

#pragma unroll
    for (int i = 0; i < 5; i++) {
        int r = ty*5 + i;
        int p = r / KNN;
#pragma unroll
        for (int jp = 0; jp < 4; jp++) {
            float2 v = f2_unpack(acc2[i][jp]);
            pool[r*STG_STRIDE + tx*8 + 2*jp]     = v.x + sT[p*64 + tx*8 + 2*jp];
            pool[r*STG_STRIDE + tx*8 + 2*jp + 1] = v.y + sT[p*64 + tx*8 + 2*jp + 1];
        }
    }
    __syncthreads();

    int ol = tid & 63;
    int gi = tid >> 6;
    float s = 0.f, s2 = 0.f;
#pragma unroll
    for (int half = 0; half < 2; half++) {
        int p = gi + half*4;
        float mx = -INFINITY, mn = INFINITY;
#pragma unroll
        for (int k = 0; k < KNN; k++) {
            float v = pool[(p*KNN + k)*STG_STRIDE + ol];
            mx = fmaxf(mx, v); mn = fminf(mn, v);
            s += v; s2 += v*v;
        }
        size_t oi = (size_t)(p0 + p)*O + n0 + ol;
        hmax[oi] = mx;
        hmin[oi] = mn;
    }
    __syncthreads();
    sT[gi*64 + ol] = s;
    sT[256 + gi*64 + ol] = s2;
    __syncthreads();
    if (gi == 0) {
        float ts  = sT[ol] + sT[64+ol] + sT[128+ol] + sT[192+ol];
        float ts2 = sT[256+ol] + sT[320+ol] + sT[384+ol] + sT[448+ol];
        atomicAdd(&gsum[n0 + ol],  (double)ts);
        atomicAdd(&gsum2[n0 + ol], (double)ts2);
    }
}

__global__ void bn_params_kernel(const double* __restrict__ gsum, const double* __restrict__ gsum2,
                                 const float* __restrict__ g, const float* __restrict__ b,
                                 int O, double cnt,
                                 float* __restrict__ scale, float* __restrict__ shift) {
    int o = threadIdx.x;
    if (o >= O) return;
    double m   = gsum[o] / cnt;
    double var = gsum2[o] / cnt - m*m;
    float sc = g[o] * rsqrtf((float)var + BN_EPS);
    scale[o] = sc;
    shift[o] = b[o] - (float)m * sc;
}

__global__ void edge_finalize_kernel(const float* __restrict__ hmax, const float* __restrict__ hmin,
                                     const float* __restrict__ scale, const float* __restrict__ shift,
                                     float* __restrict__ out, int O) {
    int i = blockIdx.x*256 + threadIdx.x;
    if (i >= BNTOT*O) return;
    int o = i & (O - 1);
    float sc = scale[o];
    float v = (sc >= 0.f ? hmax[i] : hmin[i]) * sc + shift[o];
    out[i] = v >= 0.f ? v : NEG_SLOPE*v;
}

// h6: act + global max over n per (b,o)
__global__ __launch_bounds__(256)
void h6_finalize_kernel(const float* __restrict__ P,
                        const float* __restrict__ scale, const float* __restrict__ shift,
                        float* __restrict__ gmax) {
    int ol = threadIdx.x & 63;
    int gi = threadIdx.x >> 6;
    int o = blockIdx.x*64 + ol;
    int b = blockIdx.y;
    float sc = scale[o], sh = shift[o];
    float mx = -INFINITY;
    for (int n = gi*512; n < (gi+1)*512; n++) {
        float v = P[((size_t)(b*NPTS + n))*256 + o]*sc + sh;
        v = v >= 0.f ? v : NEG_SLOPE*v;
        mx = fmaxf(mx, v);
    }
    __shared__ float sm[4][64];
    sm[gi][ol] = mx;
    __syncthreads();
    if (gi == 0)
        gmax[b*256 + o] = fmaxf(fmaxf(sm[0][ol], sm[1][ol]), fmaxf(sm[2][ol], sm[3][ol]));
}

// final: act + transpose (B,N,256) -> (B,256,N)
__global__ void out_transpose_kernel(const float* __restrict__ P,
                                     const float* __restrict__ scale, const float* __restrict__ shift,
                                     float* __restrict__ out) {
    __shared__ float tile[32][33];
    int b  = blockIdx.z;
    int n0 = blockIdx.x*32, o0 = blockIdx.y*32;
    int tx = threadIdx.x, ty = threadIdx.y;
    int o = o0 + tx;
    float v = P[((size_t)(b*NPTS + n0 + ty))*256 + o]*scale[o] + shift[o];
    v = v >= 0.f ? v : NEG_SLOPE*v;
    tile[ty][tx] = v;
    __syncthreads();
    out[(size_t)b*256*NPTS + (size_t)(o0 + ty)*NPTS + n0 + tx] = tile[tx][ty];
}

// ---------------------------------------------------------------------------
// Host side
// ---------------------------------------------------------------------------
static void* sym(const void* s) { void* p = nullptr; cudaGetSymbolAddress(&p, s); return p; }

extern "C" void kernel_launch(void* const* d_in, const int* in_sizes, int n_in,
                              void* d_out, int out_size) {
    const float* x  = (const float*)d_in[0];
    const float* W[4] = { (const float*)d_in[1], (const float*)d_in[4],
                          (const float*)d_in[7], (const float*)d_in[10] };
    const float* G[4] = { (const float*)d_in[2], (const float*)d_in[5],
                          (const float*)d_in[8], (const float*)d_in[11] };
    const float* Bb[4] = { (const float*)d_in[3], (const float*)d_in[6],
                           (const float*)d_in[9], (const float*)d_in[12] };
    const float* W6 = (const float*)d_in[13];
    const float* g6 = (const float*)d_in[14];
    const float* b6 = (const float*)d_in[15];
    const float* W5 = (const float*)d_in[16];
    const float* g5 = (const float*)d_in[17];
    const float* b5 = (const float*)d_in[18];

    float*  f0   = (float*)sym(g_f0);
    float*  x1   = (float*)sym(g_x1);
    float*  x2   = (float*)sym(g_x2);
    float*  x3   = (float*)sym(g_x3);
    float*  x4   = (float*)sym(g_x4);
    float*  pd   = (float*)sym(g_pd);
    int*    idx  = (int*)  sym(g_idx);
    float*  wa   = (float*)sym(g_wa);
    float*  wd   = (float*)sym(g_wd);
    float*  Tb   = (float*)sym(g_T);
    float*  hmax = (float*)sym(g_hmax);
    float*  hmin = (float*)sym(g_hmin);
    float*  Pb   = (float*)sym(g_P);
    float*  gmax = (float*)sym(g_gmax);
    double* s0   = (double*)sym(g_sum);
    double* s2   = (double*)sym(g_sum2);
    float*  sc   = (float*)sym(g_scale);
    float*  sh   = (float*)sym(g_shift);

    // input transpose (B,3,N) -> (B,N,3)
    transpose_in_kernel<<<(NB*3*NPTS + 255)/256, 256>>>(x, f0);

    const float* feats[4] = { f0, x1, x2, x3 };
    float*       outs [4] = { x1, x2, x3, x4 };
    const int    Cs[4] = { 3, 64, 64, 128 };
    const int    Os[4] = { 64, 64, 128, 256 };

    for (int L = 0; L < 4; L++) {
        int C = Cs[L], O = Os[L];
        const float* feat = feats[L];

        // order: prep_w(2), dist(3), topk(4 on L0 -> ncu capture slot), gemmT(5)
        prep_w_kernel<<<(O*C + 255)/256, 256>>>(W[L], O, C, wa, wd, s0, s2);

        dim3 ggrid(NPAIRS, 1, NB);
        if (C == 3) dist_sym_kernel<4><<<ggrid, 256>>>(feat, pd, C);
        else        dist_sym_kernel<16><<<ggrid, 256>>>(feat, pd, C);
        topk_warp_kernel<<<BNTOT/8, 256>>>(pd, idx);

        gemm_nt_kernel<<<dim3((BNTOT + 127)/128, O/64), 256>>>(
            feat, wd, Tb, BNTOT, O, C, nullptr, nullptr);

        fused_edge_kernel<<<dim3(BNTOT/FP, O/64), 256>>>(
            feat, wa, Tb, idx, C, O, hmax, hmin, s0, s2);
        bn_params_kernel<<<1, 256>>>(s0, s2, G[L], Bb[L], O, (double)MEDGE, sc, sh);
        edge_finalize_kernel<<<(BNTOT*O + 255)/256, 256>>>(hmax, hmin, sc, sh, outs[L], O);
    }

    // --- point conv h6 = lrelu(bn(x4 . W6^T)), then x5 = max over n ---
    zero_stats_kernel<<<1, 256>>>(s0, s2);
    gemm_nt_kernel<<<dim3(BNTOT/128, 256/64), 256>>>(x4, W6, Pb, BNTOT, 256, 256, s0, s2);
    bn_params_kernel<<<1, 256>>>(s0, s2, g6, b6, 256, (double)BNTOT, sc, sh);
    h6_finalize_kernel<<<dim3(256/64, NB), 256>>>(Pb, sc, sh, gmax);

    // --- final point conv over virtual concat + BN stats fused ---
    zero_stats_kernel<<<1, 256>>>(s0, s2);
    gemm_cat_kernel<<<dim3(BNTOT/128, 256/64), 256>>>(
        x1, x2, x3, x4, gmax, W5, Pb, s0, s2);
    bn_params_kernel<<<1, 256>>>(s0, s2, g5, b5, 256, (double)BNTOT, sc, sh);
    out_transpose_kernel<<<dim3(NPTS/32, 256/32, NB), dim3(32, 32)>>>(Pb, sc, sh, (float*)d_out);
}

// round 14
// speedup vs baseline: 1.2962x; 1.1973x over previous
#include <cuda_runtime.h>
#include <cuda_bf16.h>
#include <math.h>

// ---------------------------------------------------------------------------
// Problem constants
// ---------------------------------------------------------------------------
#define NB 8
#define NPTS 2048
#define BNTOT (NB*NPTS)          // 16384
#define KNN 20
#define MEDGE (BNTOT*KNN)        // 327680
#define NEG_SLOPE 0.2f
#define BN_EPS 1e-5f
#define NT 16                    // 2048/128 tiles per dim
#define NPAIRS (NT*(NT+1)/2)     // 136

typedef unsigned long long u64;

// ---------------------------------------------------------------------------
// Packed fp32x2 helpers: per-half rounding identical to scalar ops.
// ---------------------------------------------------------------------------
__device__ __forceinline__ u64 f2_pack(float lo, float hi) {
    u64 d;
    asm("mov.b64 %0, {%1, %2};" : "=l"(d)
        : "r"(__float_as_uint(lo)), "r"(__float_as_uint(hi)));
    return d;
}
__device__ __forceinline__ float2 f2_unpack(u64 d) {
    unsigned lo, hi;
    asm("mov.b64 {%0, %1}, %2;" : "=r"(lo), "=r"(hi) : "l"(d));
    return make_float2(__uint_as_float(lo), __uint_as_float(hi));
}
__device__ __forceinline__ u64 f2_fma(u64 a, u64 b, u64 c) {
    u64 d;
    asm("fma.rn.f32x2 %0, %1, %2, %3;" : "=l"(d) : "l"(a), "l"(b), "l"(c));
    return d;
}
__device__ __forceinline__ u64 f2_add(u64 a, u64 b) {
    u64 d;
    asm("add.rn.f32x2 %0, %1, %2;" : "=l"(d) : "l"(a), "l"(b));
    return d;
}

// ---------------------------------------------------------------------------
// Scratch (device globals -- no allocation allowed)
// ---------------------------------------------------------------------------
__device__ float g_f0  [BNTOT*3];
__device__ float g_x1  [BNTOT*64];
__device__ float g_x2  [BNTOT*64];
__device__ float g_x3  [BNTOT*128];
__device__ float g_x4  [BNTOT*256];
__device__ float g_pd  [(size_t)NB*NPTS*NPTS];       // 134 MB
__device__ int   g_idx [MEDGE];
__device__ float g_wa  [256*128];
__device__ float g_wd  [256*128];
__device__ float g_T   [BNTOT*256];
__device__ float g_hmax[BNTOT*256];
__device__ float g_hmin[BNTOT*256];
__device__ float g_P   [BNTOT*256];
__device__ float g_gmax[NB*256];
__device__ double g_sum [256];
__device__ double g_sum2[256];
__device__ float g_scale[256];
__device__ float g_shift[256];

// ---------------------------------------------------------------------------
// Small elementwise kernels
// ---------------------------------------------------------------------------
__global__ void transpose_in_kernel(const float* __restrict__ x, float* __restrict__ f) {
    int i = blockIdx.x*256 + threadIdx.x;                 // B*3*N = 49152
    if (i >= NB*3*NPTS) return;
    int b = i / (3*NPTS);
    int rem = i - b*3*NPTS;
    int c = rem / NPTS;
    int n = rem - c*NPTS;
    f[(b*NPTS + n)*3 + c] = x[i];
}

// prep_w also zeroes the BN stat accumulators (block 0) -- saves a launch.
__global__ void prep_w_kernel(const float* __restrict__ W, int O, int C,
                              float* __restrict__ wa, float* __restrict__ wd,
                              double* __restrict__ s0, double* __restrict__ s2) {
    int i = blockIdx.x*256 + threadIdx.x;
    if (blockIdx.x == 0) { s0[threadIdx.x] = 0.0; s2[threadIdx.x] = 0.0; }
    if (i >= O*C) return;
    int o = i / C, c = i - o*C;
    float a = W[o*2*C + c];
    wa[i] = a;
    wd[i] = W[o*2*C + C + c] - a;
}

__global__ void zero_stats_kernel(double* s, double* s2) {
    int t = threadIdx.x;
    if (t < 256) { s[t] = 0.0; s2[t] = 0.0; }
}

// ---------------------------------------------------------------------------
// SYMMETRIC squared-distance kernel: pd[b,i,j] = -sum_c (x_i[c]-x_j[c])^2
// (R9/R11 form -- bitwise identical to scalar full computation.)
// ---------------------------------------------------------------------------
template<int KS>
__global__ __launch_bounds__(256)
void dist_sym_kernel(const float* __restrict__ feat, float* __restrict__ pd, int C) {
    __shared__ __align__(16) float As[KS][132];
    __shared__ __align__(16) float Bs[KS][132];
    int b = blockIdx.z;
    int Lp = blockIdx.x;
    int ti = 0;
    while (Lp >= NT - ti) { Lp -= NT - ti; ti++; }
    int tj = ti + Lp;
    int m0 = ti*128, n0 = tj*128;
    bool diag = (ti == tj);

    const float* F = feat + (size_t)b*NPTS*C;
    int tid = threadIdx.x;
    int tx = tid & 15, ty = tid >> 4;

    u64 acc2[8][4];
#pragma unroll
    for (int i = 0; i < 8; i++)
#pragma unroll
        for (int j = 0; j < 4; j++) acc2[i][j] = 0ull;

    for (int k0 = 0; k0 < C; k0 += KS) {
#pragma unroll
        for (int e = tid; e < 128*KS; e += 256) {
            int c = e % KS, r = e / KS;
            float va = 0.f, vb = 0.f;
            if (k0 + c < C) {
                va = F[(size_t)(m0 + r)*C + k0 + c];
                vb = F[(size_t)(n0 + r)*C + k0 + c];
            }
            As[c][r] = va;
            Bs[c][r] = -vb;          // negate so inner loop uses add.f32x2
        }
        __syncthreads();
#pragma unroll
        for (int k = 0; k < KS; k++) {
            float af[8];
#pragma unroll
            for (int i = 0; i < 8; i++) af[i] = As[k][ty*8 + i];
            const u64* bp = (const u64*)&Bs[k][tx*8];
            u64 b2[4] = { bp[0], bp[1], bp[2], bp[3] };
#pragma unroll
            for (int i = 0; i < 8; i++) {
                u64 a2 = f2_pack(af[i], af[i]);
#pragma unroll
                for (int jp = 0; jp < 4; jp++) {
                    u64 d2 = f2_add(a2, b2[jp]);       // (a-b0, a-b1)
                    acc2[i][jp] = f2_fma(d2, d2, acc2[i][jp]);
                }
            }
        }
        __syncthreads();
    }

    float neg[8][8];
#pragma unroll
    for (int i = 0; i < 8; i++)
#pragma unroll
        for (int jp = 0; jp < 4; jp++) {
            float2 v = f2_unpack(acc2[i][jp]);
            neg[i][2*jp]   = -v.x;
            neg[i][2*jp+1] = -v.y;
        }

    float* pdb = pd + (size_t)b*NPTS*NPTS;
#pragma unroll
    for (int i = 0; i < 8; i++) {
        int m = m0 + ty*8 + i;
        float4 w0 = make_float4(neg[i][0], neg[i][1], neg[i][2], neg[i][3]);
        float4 w1 = make_float4(neg[i][4], neg[i][5], neg[i][6], neg[i][7]);
        float4* dst = (float4*)&pdb[(size_t)m*NPTS + n0 + tx*8];
        dst[0] = w0;
        dst[1] = w1;
    }
    if (!diag) {
#pragma unroll
        for (int j = 0; j < 8; j++) {
            int n = n0 + tx*8 + j;
            float4 w0 = make_float4(neg[0][j], neg[1][j], neg[2][j], neg[3][j]);
            float4 w1 = make_float4(neg[4][j], neg[5][j], neg[6][j], neg[7][j]);
            float4* dst = (float4*)&pdb[(size_t)n*NPTS + m0 + ty*8];
            dst[0] = w0;
            dst[1] = w1;
        }
    }
}

// ---------------------------------------------------------------------------
// WARP-PER-ROW top-K, values in SHARED memory (no local-memory spill).
// Lane l owns elements {off*32 + l : off in 0..63} -> STS/LDS bank == l,
// conflict-free; dynamic rescan base is native LDS addressing.
// Selection: global argmax, ties -> lowest global index (== jax top_k order);
// partition-independent -> idx bitwise identical to prior rounds.
// ---------------------------------------------------------------------------
#define TK_WARPS 4
__global__ __launch_bounds__(TK_WARPS*32)
void topk_warp_kernel(const float* __restrict__ pd, int* __restrict__ idx) {
    __shared__ float sv[TK_WARPS][NPTS];
    int w = threadIdx.x >> 5, l = threadIdx.x & 31;
    int bn = blockIdx.x*TK_WARPS + w;
    const float* row = pd + (size_t)bn*NPTS;
    float* v = sv[w];

    // load row (coalesced) + per-lane group maxima (4 groups of 16 offs)
    float gv[4]; int gm[4];
#pragma unroll
    for (int g = 0; g < 4; g++) { gv[g] = -INFINITY; gm[g] = g*16; }
#pragma unroll
    for (int off = 0; off < 64; off++) {
        float x = row[off*32 + l];
        v[off*32 + l] = x;
        int g = off >> 4;                  // compile-time after unroll
        if (x > gv[g]) { gv[g] = x; gm[g] = off; }   // strict > keeps lowest off
    }
    // warp-private smem region, each lane reads only its own slots: no sync needed

    unsigned long long excl = 0ull;
    int my_out = 0;
    for (int it = 0; it < KNN; it++) {
        // lane-local best across groups (ascending scan keeps lowest off on ties)
        float bv = gv[0]; int bo = gm[0];
#pragma unroll
        for (int g = 1; g < 4; g++)
            if (gv[g] > bv) { bv = gv[g]; bo = gm[g]; }
        float val = bv; int ix = bo*32 + l;          // global column index
#pragma unroll
        for (int s = 16; s > 0; s >>= 1) {
            float ov = __shfl_xor_sync(0xffffffff, val, s);
            int   oi = __shfl_xor_sync(0xffffffff, ix, s);
            if (ov > val || (ov == val && oi < ix)) { val = ov; ix = oi; }
        }
        if (l == it) my_out = ix;

        int owner = ix & 31;
        if (l == owner) {
            int off = ix >> 5;
            excl |= 1ull << off;
            int g = off >> 4;
            int base = g*16;
            float bv2 = -INFINITY; int bo2 = base;
#pragma unroll
            for (int m = 0; m < 16; m++) {
                int o2 = base + m;
                float x = v[o2*32 + l];              // LDS, dynamic base OK
                bool ok = !((excl >> o2) & 1ull);
                if (ok && x > bv2) { bv2 = x; bo2 = o2; }
            }
            gv[g] = bv2; gm[g] = bo2;
        }
    }
    if (l < KNN) idx[bn*KNN + l] = my_out;
}

// ---------------------------------------------------------------------------
// Generic NT GEMM: C[m,n] = sum_k A[m,k]*B[n,k], f32x2 inner, LDG prefetch.
// Optional fused per-channel sum/sumsq (BN stats) via block partials + atomics.
// ---------------------------------------------------------------------------
__global__ __launch_bounds__(256)
void gemm_nt_kernel(const float* __restrict__ A, const float* __restrict__ B,
                    float* __restrict__ C, int M, int N, int K,
                    double* __restrict__ gsum, double* __restrict__ gsum2) {
    __shared__ __align__(16) float As[16][129];
    __shared__ __align__(16) float Bs[16][66];
    int tid = threadIdx.x;
    int tx = tid & 15;
    int ty = tid >> 4;
    int m0 = blockIdx.x * 128;
    int n0 = blockIdx.y * 64;

    u64 acc2[8][2];
#pragma unroll
    for (int i = 0; i < 8; i++) { acc2[i][0] = 0ull; acc2[i][1] = 0ull; }

    float pa[8], pb[4];
#pragma unroll
    for (int i = 0; i < 8; i++) {
        int e = tid + i*256;
        int c = e & 15, r = e >> 4;
        int m = m0 + r;
        pa[i] = (m < M && c < K) ? A[(size_t)m*K + c] : 0.f;
    }
#pragma unroll
    for (int i = 0; i < 4; i++) {
        int e = tid + i*256;
        int c = e & 15, r = e >> 4;
        pb[i] = (c < K) ? B[(size_t)(n0 + r)*K + c] : 0.f;
    }

    for (int k0 = 0; k0 < K; k0 += 16) {
#pragma unroll
        for (int i = 0; i < 8; i++) {
            int e = tid + i*256;
            As[e & 15][e >> 4] = pa[i];
        }
#pragma unroll
        for (int i = 0; i < 4; i++) {
            int e = tid + i*256;
            Bs[e & 15][e >> 4] = pb[i];
        }
        __syncthreads();
        int kn = k0 + 16;
        if (kn < K) {
#pragma unroll
            for (int i = 0; i < 8; i++) {
                int e = tid + i*256;
                int c = e & 15, r = e >> 4;
                int m = m0 + r;
                pa[i] = (m < M && kn + c < K) ? A[(size_t)m*K + kn + c] : 0.f;
            }
#pragma unroll
            for (int i = 0; i < 4; i++) {
                int e = tid + i*256;
                int c = e & 15, r = e >> 4;
                pb[i] = (kn + c < K) ? B[(size_t)(n0 + r)*K + kn + c] : 0.f;
            }
        }
#pragma unroll
        for (int k = 0; k < 16; k++) {
            const u64* bp = (const u64*)&Bs[k][tx*4];
            u64 b0 = bp[0], b1 = bp[1];
#pragma unroll
            for (int i = 0; i < 8; i++) {
                float a = As[k][ty*8 + i];
                u64 a2 = f2_pack(a, a);
                acc2[i][0] = f2_fma(a2, b0, acc2[i][0]);
                acc2[i][1] = f2_fma(a2, b1, acc2[i][1]);
            }
        }
        __syncthreads();
    }

    float cs[4] = {0.f,0.f,0.f,0.f}, cq[4] = {0.f,0.f,0.f,0.f};
#pragma unroll
    for (int i = 0; i < 8; i++) {
        int m = m0 + ty*8 + i;
        if (m >= M) continue;
        float2 v0 = f2_unpack(acc2[i][0]);
        float2 v1 = f2_unpack(acc2[i][1]);
        float* dst = &C[(size_t)m*N + n0 + tx*4];
        dst[0] = v0.x; dst[1] = v0.y; dst[2] = v1.x; dst[3] = v1.y;
        cs[0] += v0.x; cq[0] += v0.x*v0.x;
        cs[1] += v0.y; cq[1] += v0.y*v0.y;
        cs[2] += v1.x; cq[2] += v1.x*v1.x;
        cs[3] += v1.y; cq[3] += v1.y*v1.y;
    }

    if (gsum) {
        float* sred = &As[0][0];
#pragma unroll
        for (int j = 0; j < 4; j++) {
            sred[ty*64 + tx*4 + j]        = cs[j];
            sred[1024 + ty*64 + tx*4 + j] = cq[j];
        }
        __syncthreads();
        if (tid < 64) {
            float S = 0.f, Q = 0.f;
#pragma unroll
            for (int t = 0; t < 16; t++) {
                S += sred[t*64 + tid];
                Q += sred[1024 + t*64 + tid];
            }
            atomicAdd(&gsum[n0 + tid],  (double)S);
            atomicAdd(&gsum2[n0 + tid], (double)Q);
        }
    }
}

// ---------------------------------------------------------------------------
// GEMM over the virtual concat [x1|x2|x3|x4|gmax] (K=768), fused BN stats.
// ---------------------------------------------------------------------------
__device__ __forceinline__ float cat_fetch(int m, int c,
                                           const float* __restrict__ x1,
                                           const float* __restrict__ x2,
                                           const float* __restrict__ x3,
                                           const float* __restrict__ x4,
                                           const float* __restrict__ gmax) {
    if (c < 64)   return x1[m*64 + c];
    if (c < 128)  return x2[m*64 + c - 64];
    if (c < 256)  return x3[m*128 + c - 128];
    if (c < 512)  return x4[m*256 + c - 256];
    return gmax[(m >> 11)*256 + c - 512];
}

__global__ __launch_bounds__(256)
void gemm_cat_kernel(const float* __restrict__ x1, const float* __restrict__ x2,
                     const float* __restrict__ x3, const float* __restrict__ x4,
                     const float* __restrict__ gmax,
                     const float* __restrict__ B,
                     float* __restrict__ C,
                     double* __restrict__ gsum, double* __restrict__ gsum2) {
    const int N = 256, K = 768;
    __shared__ __align__(16) float As[16][129];
    __shared__ __align__(16) float Bs[16][66];
    int tid = threadIdx.x;
    int tx = tid & 15;
    int ty = tid >> 4;
    int m0 = blockIdx.x * 128;
    int n0 = blockIdx.y * 64;

    u64 acc2[8][2];
#pragma unroll
    for (int i = 0; i < 8; i++) { acc2[i][0] = 0ull; acc2[i][1] = 0ull; }

    float pa[8], pb[4];
#pragma unroll
    for (int i = 0; i < 8; i++) {
        int e = tid + i*256;
        int c = e & 15, r = e >> 4;
        pa[i] = cat_fetch(m0 + r, c, x1, x2, x3, x4, gmax);
    }
#pragma unroll
    for (int i = 0; i < 4; i++) {
        int e = tid + i*256;
        int c = e & 15, r = e >> 4;
        pb[i] = B[(size_t)(n0 + r)*K + c];
    }

    for (int k0 = 0; k0 < K; k0 += 16) {
#pragma unroll
        for (int i = 0; i < 8; i++) {
            int e = tid + i*256;
            As[e & 15][e >> 4] = pa[i];
        }
#pragma unroll
        for (int i = 0; i < 4; i++) {
            int e = tid + i*256;
            Bs[e & 15][e >> 4] = pb[i];
        }
        __syncthreads();
        int kn = k0 + 16;
        if (kn < K) {
#pragma unroll
            for (int i = 0; i < 8; i++) {
                int e = tid + i*256;
                int c = e & 15, r = e >> 4;
                pa[i] = cat_fetch(m0 + r, kn + c, x1, x2, x3, x4, gmax);
            }
#pragma unroll
            for (int i = 0; i < 4; i++) {
                int e = tid + i*256;
                int c = e & 15, r = e >> 4;
                pb[i] = B[(size_t)(n0 + r)*K + kn + c];
            }
        }
#pragma unroll
        for (int k = 0; k < 16; k++) {
            const u64* bp = (const u64*)&Bs[k][tx*4];
            u64 b0 = bp[0], b1 = bp[1];
#pragma unroll
            for (int i = 0; i < 8; i++) {
                float a = As[k][ty*8 + i];
                u64 a2 = f2_pack(a, a);
                acc2[i][0] = f2_fma(a2, b0, acc2[i][0]);
                acc2[i][1] = f2_fma(a2, b1, acc2[i][1]);
            }
        }
        __syncthreads();
    }

    float cs[4] = {0.f,0.f,0.f,0.f}, cq[4] = {0.f,0.f,0.f,0.f};
#pragma unroll
    for (int i = 0; i < 8; i++) {
        int m = m0 + ty*8 + i;
        float2 v0 = f2_unpack(acc2[i][0]);
        float2 v1 = f2_unpack(acc2[i][1]);
        float* dst = &C[(size_t)m*N + n0 + tx*4];
        dst[0] = v0.x; dst[1] = v0.y; dst[2] = v1.x; dst[3] = v1.y;
        cs[0] += v0.x; cq[0] += v0.x*v0.x;
        cs[1] += v0.y; cq[1] += v0.y*v0.y;
        cs[2] += v1.x; cq[2] += v1.x*v1.x;
        cs[3] += v1.y; cq[3] += v1.y*v1.y;
    }

    float* sred = &As[0][0];
#pragma unroll
    for (int j = 0; j < 4; j++) {
        sred[ty*64 + tx*4 + j]        = cs[j];
        sred[1024 + ty*64 + tx*4 + j] = cq[j];
    }
    __syncthreads();
    if (tid < 64) {
        float S = 0.f, Q = 0.f;
#pragma unroll
        for (int t = 0; t < 16; t++) {
            S += sred[t*64 + tid];
            Q += sred[1024 + t*64 + tid];
        }
        atomicAdd(&gsum[n0 + tid],  (double)S);
        atomicAdd(&gsum2[n0 + tid], (double)Q);
    }
}

// ---------------------------------------------------------------------------
// FUSED edge-conv: 8 points x 20 neighbors (160 rows) x 64 channels, f32x2,
// register-prefetch pipelined gathered loads. (R11 form.)
// ---------------------------------------------------------------------------
#define FP    8
#define FROWS (FP*KNN)            // 160
#define AS_STRIDE 161             // 161 % 32 == 1  -> conflict-free
#define BS_BASE   (16*AS_STRIDE)  // 2576 floats (16B aligned)
#define BS_STRIDE 68              // rows 16B aligned
#define STG_STRIDE 66

__global__ __launch_bounds__(256)
void fused_edge_kernel(const float* __restrict__ feat,   // [BNTOT, C]
                       const float* __restrict__ wa,     // [O, C]
                       const float* __restrict__ T,      // [BNTOT, O]
                       const int* __restrict__ idx,      // [BNTOT, KNN]
                       int C, int O,
                       float* __restrict__ hmax, float* __restrict__ hmin,
                       double* __restrict__ gsum, double* __restrict__ gsum2) {
    __shared__ __align__(16) float pool[FROWS*STG_STRIDE];   // 10560 floats
    __shared__ int   sidx[FROWS];
    __shared__ float sT[FP*64];

    int tid = threadIdx.x;
    int p0  = blockIdx.x * FP;
    int n0  = blockIdx.y * 64;

    if (tid < FROWS) {
        int p  = tid / KNN;
        int k  = tid - p*KNN;
        int bn = p0 + p;
        sidx[tid] = (bn >> 11)*NPTS + idx[bn*KNN + k];
    }
    {
        int e = tid;
        sT[e] = T[(size_t)(p0 + (e >> 6))*O + n0 + (e & 63)];
        e += 256;
        sT[e] = T[(size_t)(p0 + (e >> 6))*O + n0 + (e & 63)];
    }
    __syncthreads();

    int tx = tid & 7;
    int ty = tid >> 3;

    u64 acc2[5][4];
#pragma unroll
    for (int i = 0; i < 5; i++)
#pragma unroll
        for (int j = 0; j < 4; j++) acc2[i][j] = 0ull;

    float pa[10], pb[4];
#pragma unroll
    for (int i = 0; i < 10; i++) {
        int e = tid + i*256;
        int c = e & 15, r = e >> 4;
        pa[i] = (c < C) ? feat[(size_t)sidx[r]*C + c] : 0.f;
    }
#pragma unroll
    for (int i = 0; i < 4; i++) {
        int e = tid + i*256;
        int c = e & 15, r = e >> 4;
        pb[i] = (c < C) ? wa[(size_t)(n0 + r)*C + c] : 0.f;
    }

    for (int k0 = 0; k0 < C; k0 += 16) {
#pragma unroll
        for (int i = 0; i < 10; i++) {
            int e = tid + i*256;
            pool[(e & 15)*AS_STRIDE + (e >> 4)] = pa[i];
        }
#pragma unroll
        for (int i = 0; i < 4; i++) {
            int e = tid + i*256;
            pool[BS_BASE + (e & 15)*BS_STRIDE + (e >> 4)] = pb[i];
        }
        __syncthreads();
        int kn = k0 + 16;
        if (kn < C) {
#pragma unroll
            for (int i = 0; i < 10; i++) {
                int e = tid + i*256;
                int c = e & 15, r = e >> 4;
                pa[i] = (kn + c < C) ? feat[(size_t)sidx[r]*C + kn + c] : 0.f;
            }
#pragma unroll
            for (int i = 0; i < 4; i++) {
                int e = tid + i*256;
                int c = e & 15, r = e >> 4;
                pb[i] = (kn + c < C) ? wa[(size_t)(n0 + r)*C + kn + c] : 0.f;
            }
        }
#pragma unroll
        for (int k = 0; k < 16; k++) {
            const u64* bp = (const u64*)&pool[BS_BASE + k*BS_STRIDE + tx*8];
            u64 b2[4] = { bp[0], bp[1], bp[2], bp[3] };
#pragma unroll
            for (int i = 0; i < 5; i++) {
                float a = pool[k*AS_STRIDE + ty*5 + i];
                u64 a2 = f2_pack(a, a);
#pragma unroll
                for (int jp = 0; jp < 4; jp++)
                    acc2[i][jp] = f2_fma(a2, b2[jp], acc2[i][jp]);
            }
        }
        __syncthreads();
    }

#pragma unroll
    for (int i = 0; i < 5; i++) {
        int r = ty*5 + i;
        int p = r / KNN;
#pragma unroll
        for (int jp = 0; jp < 4; jp++) {
            float2 v = f2_unpack(acc2[i][jp]);
            pool[r*STG_STRIDE + tx*8 + 2*jp]     = v.x + sT[p*64 + tx*8 + 2*jp];
            pool[r*STG_STRIDE + tx*8 + 2*jp + 1] = v.y + sT[p*64 + tx*8 + 2*jp + 1];
        }
    }
    __syncthreads();

    int ol = tid & 63;
    int gi = tid >> 6;
    float s = 0.f, s2 = 0.f;
#pragma unroll
    for (int half = 0; half < 2; half++) {
        int p = gi + half*4;
        float mx = -INFINITY, mn = INFINITY;
#pragma unroll
        for (int k = 0; k < KNN; k++) {
            float v = pool[(p*KNN + k)*STG_STRIDE + ol];
            mx = fmaxf(mx, v); mn = fminf(mn, v);
            s += v; s2 += v*v;
        }
        size_t oi = (size_t)(p0 + p)*O + n0 + ol;
        hmax[oi] = mx;
        hmin[oi] = mn;
    }
    __syncthreads();
    sT[gi*64 + ol] = s;
    sT[256 + gi*64 + ol] = s2;
    __syncthreads();
    if (gi == 0) {
        float ts  = sT[ol] + sT[64+ol] + sT[128+ol] + sT[192+ol];
        float ts2 = sT[256+ol] + sT[320+ol] + sT[384+ol] + sT[448+ol];
        atomicAdd(&gsum[n0 + ol],  (double)ts);
        atomicAdd(&gsum2[n0 + ol], (double)ts2);
    }
}

__global__ void bn_params_kernel(const double* __restrict__ gsum, const double* __restrict__ gsum2,
                                 const float* __restrict__ g, const float* __restrict__ b,
                                 int O, double cnt,
                                 float* __restrict__ scale, float* __restrict__ shift) {
    int o = threadIdx.x;
    if (o >= O) return;
    double m   = gsum[o] / cnt;
    double var = gsum2[o] / cnt - m*m;
    float sc = g[o] * rsqrtf((float)var + BN_EPS);
    scale[o] = sc;
    shift[o] = b[o] - (float)m * sc;
}

__global__ void edge_finalize_kernel(const float* __restrict__ hmax, const float* __restrict__ hmin,
                                     const float* __restrict__ scale, const float* __restrict__ shift,
                                     float* __restrict__ out, int O) {
    int i = blockIdx.x*256 + threadIdx.x;
    if (i >= BNTOT*O) return;
    int o = i & (O - 1);
    float sc = scale[o];
    float v = (sc >= 0.f ? hmax[i] : hmin[i]) * sc + shift[o];
    out[i] = v >= 0.f ? v : NEG_SLOPE*v;
}

// h6: act + global max over n per (b,o)
__global__ __launch_bounds__(256)
void h6_finalize_kernel(const float* __restrict__ P,
                        const float* __restrict__ scale, const float* __restrict__ shift,
                        float* __restrict__ gmax) {
    int ol = threadIdx.x & 63;
    int gi = threadIdx.x >> 6;
    int o = blockIdx.x*64 + ol;
    int b = blockIdx.y;
    float sc = scale[o], sh = shift[o];
    float mx = -INFINITY;
    for (int n = gi*512; n < (gi+1)*512; n++) {
        float v = P[((size_t)(b*NPTS + n))*256 + o]*sc + sh;
        v = v >= 0.f ? v : NEG_SLOPE*v;
        mx = fmaxf(mx, v);
    }
    __shared__ float sm[4][64];
    sm[gi][ol] = mx;
    __syncthreads();
    if (gi == 0)
        gmax[b*256 + o] = fmaxf(fmaxf(sm[0][ol], sm[1][ol]), fmaxf(sm[2][ol], sm[3][ol]));
}

// final: act + transpose (B,N,256) -> (B,256,N)
__global__ void out_transpose_kernel(const float* __restrict__ P,
                                     const float* __restrict__ scale, const float* __restrict__ shift,
                                     float* __restrict__ out) {
    __shared__ float tile[32][33];
    int b  = blockIdx.z;
    int n0 = blockIdx.x*32, o0 = blockIdx.y*32;
    int tx = threadIdx.x, ty = threadIdx.y;
    int o = o0 + tx;
    float v = P[((size_t)(b*NPTS + n0 + ty))*256 + o]*scale[o] + shift[o];
    v = v >= 0.f ? v : NEG_SLOPE*v;
    tile[ty][tx] = v;
    __syncthreads();
    out[(size_t)b*256*NPTS + (size_t)(o0 + ty)*NPTS + n0 + tx] = tile[tx][ty];
}

// ---------------------------------------------------------------------------
// Host side
// ---------------------------------------------------------------------------
static void* sym(const void* s) { void* p = nullptr; cudaGetSymbolAddress(&p, s); return p; }

extern "C" void kernel_launch(void* const* d_in, const int* in_sizes, int n_in,
                              void* d_out, int out_size) {
    const float* x  = (const float*)d_in[0];
    const float* W[4] = { (const float*)d_in[1], (const float*)d_in[4],
                          (const float*)d_in[7], (const float*)d_in[10] };
    const float* G[4] = { (const float*)d_in[2], (const float*)d_in[5],
                          (const float*)d_in[8], (const float*)d_in[11] };
    const float* Bb[4] = { (const float*)d_in[3], (const float*)d_in[6],
                           (const float*)d_in[9], (const float*)d_in[12] };
    const float* W6 = (const float*)d_in[13];
    const float* g6 = (const float*)d_in[14];
    const float* b6 = (const float*)d_in[15];
    const float* W5 = (const float*)d_in[16];
    const float* g5 = (const float*)d_in[17];
    const float* b5 = (const float*)d_in[18];

    float*  f0   = (float*)sym(g_f0);
    float*  x1   = (float*)sym(g_x1);
    float*  x2   = (float*)sym(g_x2);
    float*  x3   = (float*)sym(g_x3);
    float*  x4   = (float*)sym(g_x4);
    float*  pd   = (float*)sym(g_pd);
    int*    idx  = (int*)  sym(g_idx);
    float*  wa   = (float*)sym(g_wa);
    float*  wd   = (float*)sym(g_wd);
    float*  Tb   = (float*)sym(g_T);
    float*  hmax = (float*)sym(g_hmax);
    float*  hmin = (float*)sym(g_hmin);
    float*  Pb   = (float*)sym(g_P);
    float*  gmax = (float*)sym(g_gmax);
    double* s0   = (double*)sym(g_sum);
    double* s2   = (double*)sym(g_sum2);
    float*  sc   = (float*)sym(g_scale);
    float*  sh   = (float*)sym(g_shift);

    // input transpose (B,3,N) -> (B,N,3)
    transpose_in_kernel<<<(NB*3*NPTS + 255)/256, 256>>>(x, f0);

    const float* feats[4] = { f0, x1, x2, x3 };
    float*       outs [4] = { x1, x2, x3, x4 };
    const int    Cs[4] = { 3, 64, 64, 128 };
    const int    Os[4] = { 64, 64, 128, 256 };

    for (int L = 0; L < 4; L++) {
        int C = Cs[L], O = Os[L];
        const float* feat = feats[L];

        // order: prep_w(2), dist(3), topk(4 on L0 -> ncu capture slot), gemmT(5)
        prep_w_kernel<<<(O*C + 255)/256, 256>>>(W[L], O, C, wa, wd, s0, s2);

        dim3 ggrid(NPAIRS, 1, NB);
        if (C == 3) dist_sym_kernel<4><<<ggrid, 256>>>(feat, pd, C);
        else        dist_sym_kernel<16><<<ggrid, 256>>>(feat, pd, C);
        topk_warp_kernel<<<BNTOT/TK_WARPS, TK_WARPS*32>>>(pd, idx);

        gemm_nt_kernel<<<dim3((BNTOT + 127)/128, O/64), 256>>>(
            feat, wd, Tb, BNTOT, O, C, nullptr, nullptr);

        fused_edge_kernel<<<dim3(BNTOT/FP, O/64), 256>>>(
            feat, wa, Tb, idx, C, O, hmax, hmin, s0, s2);
        bn_params_kernel<<<1, 256>>>(s0, s2, G[L], Bb[L], O, (double)MEDGE, sc, sh);
        edge_finalize_kernel<<<(BNTOT*O + 255)/256, 256>>>(hmax, hmin, sc, sh, outs[L], O);
    }

    // --- point conv h6 = lrelu(bn(x4 . W6^T)), then x5 = max over n ---
    zero_stats_kernel<<<1, 256>>>(s0, s2);
    gemm_nt_kernel<<<dim3(BNTOT/128, 256/64), 256>>>(x4, W6, Pb, BNTOT, 256, 256, s0, s2);
    bn_params_kernel<<<1, 256>>>(s0, s2, g6, b6, 256, (double)BNTOT, sc, sh);
    h6_finalize_kernel<<<dim3(256/64, NB), 256>>>(Pb, sc, sh, gmax);

    // --- final point conv over virtual concat + BN stats fused ---
    zero_stats_kernel<<<1, 256>>>(s0, s2);
    gemm_cat_kernel<<<dim3(BNTOT/128, 256/64), 256>>>(
        x1, x2, x3, x4, gmax, W5, Pb, s0, s2);
    bn_params_kernel<<<1, 256>>>(s0, s2, g5, b5, 256, (double)BNTOT, sc, sh);
    out_transpose_kernel<<<dim3(NPTS/32, 256/32, NB), dim3(32, 32)>>>(Pb, sc, sh, (float*)d_out);
}

// round 15
// speedup vs baseline: 1.3829x; 1.0669x over previous
#include <cuda_runtime.h>
#include <cuda_bf16.h>
#include <math.h>

// ---------------------------------------------------------------------------
// Problem constants
// ---------------------------------------------------------------------------
#define NB 8
#define NPTS 2048
#define BNTOT (NB*NPTS)          // 16384
#define KNN 20
#define MEDGE (BNTOT*KNN)        // 327680
#define NEG_SLOPE 0.2f
#define BN_EPS 1e-5f
#define NT 16                    // 2048/128 tiles per dim
#define NPAIRS (NT*(NT+1)/2)     // 136

typedef unsigned long long u64;

// ---------------------------------------------------------------------------
// Packed fp32x2 helpers: per-half rounding identical to scalar ops.
// ---------------------------------------------------------------------------
__device__ __forceinline__ u64 f2_pack(float lo, float hi) {
    u64 d;
    asm("mov.b64 %0, {%1, %2};" : "=l"(d)
        : "r"(__float_as_uint(lo)), "r"(__float_as_uint(hi)));
    return d;
}
__device__ __forceinline__ float2 f2_unpack(u64 d) {
    unsigned lo, hi;
    asm("mov.b64 {%0, %1}, %2;" : "=r"(lo), "=r"(hi) : "l"(d));
    return make_float2(__uint_as_float(lo), __uint_as_float(hi));
}
__device__ __forceinline__ u64 f2_fma(u64 a, u64 b, u64 c) {
    u64 d;
    asm("fma.rn.f32x2 %0, %1, %2, %3;" : "=l"(d) : "l"(a), "l"(b), "l"(c));
    return d;
}
__device__ __forceinline__ u64 f2_add(u64 a, u64 b) {
    u64 d;
    asm("add.rn.f32x2 %0, %1, %2;" : "=l"(d) : "l"(a), "l"(b));
    return d;
}

// ---------------------------------------------------------------------------
// Scratch (device globals -- no allocation allowed)
// ---------------------------------------------------------------------------
__device__ float g_f0  [BNTOT*3];
__device__ float g_x1  [BNTOT*64];
__device__ float g_x2  [BNTOT*64];
__device__ float g_x3  [BNTOT*128];
__device__ float g_x4  [BNTOT*256];
__device__ float g_pd  [(size_t)NB*NPTS*NPTS];       // 134 MB
__device__ int   g_idx [MEDGE];
__device__ float g_wa  [256*128];
__device__ float g_wd  [256*128];
__device__ float g_T   [BNTOT*256];
__device__ float g_hmax[BNTOT*256];
__device__ float g_hmin[BNTOT*256];
__device__ float g_P   [BNTOT*256];
__device__ float g_gmax[NB*256];
__device__ double g_sum [256];
__device__ double g_sum2[256];
__device__ float g_scale[256];
__device__ float g_shift[256];

// ---------------------------------------------------------------------------
// Small elementwise kernels
// ---------------------------------------------------------------------------
__global__ void transpose_in_kernel(const float* __restrict__ x, float* __restrict__ f) {
    int i = blockIdx.x*256 + threadIdx.x;                 // B*3*N = 49152
    if (i >= NB*3*NPTS) return;
    int b = i / (3*NPTS);
    int rem = i - b*3*NPTS;
    int c = rem / NPTS;
    int n = rem - c*NPTS;
    f[(b*NPTS + n)*3 + c] = x[i];
}

// prep_w also zeroes the BN stat accumulators (block 0) -- saves a launch.
__global__ void prep_w_kernel(const float* __restrict__ W, int O, int C,
                              float* __restrict__ wa, float* __restrict__ wd,
                              double* __restrict__ s0, double* __restrict__ s2) {
    int i = blockIdx.x*256 + threadIdx.x;
    if (blockIdx.x == 0) { s0[threadIdx.x] = 0.0; s2[threadIdx.x] = 0.0; }
    if (i >= O*C) return;
    int o = i / C, c = i - o*C;
    float a = W[o*2*C + c];
    wa[i] = a;
    wd[i] = W[o*2*C + C + c] - a;
}

// ---------------------------------------------------------------------------
// SYMMETRIC squared-distance kernel: pd[b,i,j] = -sum_c (x_i[c]-x_j[c])^2
// ---------------------------------------------------------------------------
template<int KS>
__global__ __launch_bounds__(256)
void dist_sym_kernel(const float* __restrict__ feat, float* __restrict__ pd, int C) {
    __shared__ __align__(16) float As[KS][132];
    __shared__ __align__(16) float Bs[KS][132];
    int b = blockIdx.z;
    int Lp = blockIdx.x;
    int ti = 0;
    while (Lp >= NT - ti) { Lp -= NT - ti; ti++; }
    int tj = ti + Lp;
    int m0 = ti*128, n0 = tj*128;
    bool diag = (ti == tj);

    const float* F = feat + (size_t)b*NPTS*C;
    int tid = threadIdx.x;
    int tx = tid & 15, ty = tid >> 4;

    u64 acc2[8][4];
#pragma unroll
    for (int i = 0; i < 8; i++)
#pragma unroll
        for (int j = 0; j < 4; j++) acc2[i][j] = 0ull;

    for (int k0 = 0; k0 < C; k0 += KS) {
#pragma unroll
        for (int e = tid; e < 128*KS; e += 256) {
            int c = e % KS, r = e / KS;
            float va = 0.f, vb = 0.f;
            if (k0 + c < C) {
                va = F[(size_t)(m0 + r)*C + k0 + c];
                vb = F[(size_t)(n0 + r)*C + k0 + c];
            }
            As[c][r] = va;
            Bs[c][r] = -vb;          // negate so inner loop uses add.f32x2
        }
        __syncthreads();
#pragma unroll
        for (int k = 0; k < KS; k++) {
            float af[8];
#pragma unroll
            for (int i = 0; i < 8; i++) af[i] = As[k][ty*8 + i];
            const u64* bp = (const u64*)&Bs[k][tx*8];
            u64 b2[4] = { bp[0], bp[1], bp[2], bp[3] };
#pragma unroll
            for (int i = 0; i < 8; i++) {
                u64 a2 = f2_pack(af[i], af[i]);
#pragma unroll
                for (int jp = 0; jp < 4; jp++) {
                    u64 d2 = f2_add(a2, b2[jp]);       // (a-b0, a-b1)
                    acc2[i][jp] = f2_fma(d2, d2, acc2[i][jp]);
                }
            }
        }
        __syncthreads();
    }

    float neg[8][8];
#pragma unroll
    for (int i = 0; i < 8; i++)
#pragma unroll
        for (int jp = 0; jp < 4; jp++) {
            float2 v = f2_unpack(acc2[i][jp]);
            neg[i][2*jp]   = -v.x;
            neg[i][2*jp+1] = -v.y;
        }

    float* pdb = pd + (size_t)b*NPTS*NPTS;
#pragma unroll
    for (int i = 0; i < 8; i++) {
        int m = m0 + ty*8 + i;
        float4 w0 = make_float4(neg[i][0], neg[i][1], neg[i][2], neg[i][3]);
        float4 w1 = make_float4(neg[i][4], neg[i][5], neg[i][6], neg[i][7]);
        float4* dst = (float4*)&pdb[(size_t)m*NPTS + n0 + tx*8];
        dst[0] = w0;
        dst[1] = w1;
    }
    if (!diag) {
#pragma unroll
        for (int j = 0; j < 8; j++) {
            int n = n0 + tx*8 + j;
            float4 w0 = make_float4(neg[0][j], neg[1][j], neg[2][j], neg[3][j]);
            float4 w1 = make_float4(neg[4][j], neg[5][j], neg[6][j], neg[7][j]);
            float4* dst = (float4*)&pdb[(size_t)n*NPTS + m0 + ty*8];
            dst[0] = w0;
            dst[1] = w1;
        }
    }
}

// ---------------------------------------------------------------------------
// WARP-PER-ROW top-K, values in SHARED memory; poison-based rescan.
// Lane l owns elements {off*32 + l}; 8 groups of 8 offsets per lane.
// Winner slot is poisoned to -INF (one STS) -> rescan is a bare max over 8
// slots, no exclusion-mask arithmetic. Group maxima live in lane-keyed smem
// (bank == lane, conflict-free; dynamic group index safe, no reg spill).
// Selection: global argmax, ties -> lowest global index (== jax top_k).
// idx bitwise identical to prior rounds.
// ---------------------------------------------------------------------------
#define TK_WARPS 4
__global__ __launch_bounds__(TK_WARPS*32)
void topk_warp_kernel(const float* __restrict__ pd, int* __restrict__ idx) {
    __shared__ float sv [TK_WARPS][NPTS];
    __shared__ float sgv[TK_WARPS][8][32];
    __shared__ int   sgm[TK_WARPS][8][32];
    int w = threadIdx.x >> 5, l = threadIdx.x & 31;
    int bn = blockIdx.x*TK_WARPS + w;
    const float* row = pd + (size_t)bn*NPTS;
    float* v = sv[w];

    // load row (coalesced) + per-lane group maxima in registers (static idx)
    float gv[8]; int gm[8];
#pragma unroll
    for (int g = 0; g < 8; g++) { gv[g] = -INFINITY; gm[g] = g*8; }
#pragma unroll
    for (int off = 0; off < 64; off++) {
        float x = row[off*32 + l];
        v[off*32 + l] = x;
        int g = off >> 3;                  // compile-time after unroll
        if (x > gv[g]) { gv[g] = x; gm[g] = off; }   // strict > keeps lowest off
    }
    // flush group maxima to lane-keyed smem (static stores)
#pragma unroll
    for (int g = 0; g < 8; g++) { sgv[w][g][l] = gv[g]; sgm[w][g][l] = gm[g]; }
    // warp-private smem, each lane touches only its own slots: no sync needed

    int my_out = 0;
    for (int it = 0; it < KNN; it++) {
        // lane-local best across 8 groups (ascending keeps lowest group/off)
        float bv = sgv[w][0][l]; int bg = 0;
#pragma unroll
        for (int g = 1; g < 8; g++) {
            float x = sgv[w][g][l];
            if (x > bv) { bv = x; bg = g; }
        }
        int bo = sgm[w][bg][l];
        float val = bv; int ix = bo*32 + l;          // global column index
#pragma unroll
        for (int s = 16; s > 0; s >>= 1) {
            float ov = __shfl_xor_sync(0xffffffff, val, s);
            int   oi = __shfl_xor_sync(0xffffffff, ix, s);
            if (ov > val || (ov == val && oi < ix)) { val = ov; ix = oi; }
        }
        if (l == it) my_out = ix;

        int owner = ix & 31;
        if (l == owner) {
            int off = ix >> 5;
            v[off*32 + l] = -INFINITY;               // poison winner slot
            int g = off >> 3;
            int base = g*8;
            float bv2 = -INFINITY; int bo2 = base;
#pragma unroll
            for (int m = 0; m < 8; m++) {
                float x = v[(base + m)*32 + l];      // LDS, dynamic base OK
                if (x > bv2) { bv2 = x; bo2 = base + m; }
            }
            sgv[w][g][l] = bv2;                      // dynamic g: smem, safe
            sgm[w][g][l] = bo2;
        }
    }
    if (l < KNN) idx[bn*KNN + l] = my_out;
}

// ---------------------------------------------------------------------------
// Generic NT GEMM: C[m,n] = sum_k A[m,k]*B[n,k], f32x2 inner, LDG prefetch.
// Optional fused per-channel sum/sumsq (BN stats) via block partials + atomics.
// ---------------------------------------------------------------------------
__global__ __launch_bounds__(256)
void gemm_nt_kernel(const float* __restrict__ A, const float* __restrict__ B,
                    float* __restrict__ C, int M, int N, int K,
                    double* __restrict__ gsum, double* __restrict__ gsum2) {
    __shared__ __align__(16) float As[16][129];
    __shared__ __align__(16) float Bs[16][66];
    int tid = threadIdx.x;
    int tx = tid & 15;
    int ty = tid >> 4;
    int m0 = blockIdx.x * 128;
    int n0 = blockIdx.y * 64;

    u64 acc2[8][2];
#pragma unroll
    for (int i = 0; i < 8; i++) { acc2[i][0] = 0ull; acc2[i][1] = 0ull; }

    float pa[8], pb[4];
#pragma unroll
    for (int i = 0; i < 8; i++) {
        int e = tid + i*256;
        int c = e & 15, r = e >> 4;
        int m = m0 + r;
        pa[i] = (m < M && c < K) ? A[(size_t)m*K + c] : 0.f;
    }
#pragma unroll
    for (int i = 0; i < 4; i++) {
        int e = tid + i*256;
        int c = e & 15, r = e >> 4;
        pb[i] = (c < K) ? B[(size_t)(n0 + r)*K + c] : 0.f;
    }

    for (int k0 = 0; k0 < K; k0 += 16) {
#pragma unroll
        for (int i = 0; i < 8; i++) {
            int e = tid + i*256;
            As[e & 15][e >> 4] = pa[i];
        }
#pragma unroll
        for (int i = 0; i < 4; i++) {
            int e = tid + i*256;
            Bs[e & 15][e >> 4] = pb[i];
        }
        __syncthreads();
        int kn = k0 + 16;
        if (kn < K) {
#pragma unroll
            for (int i = 0; i < 8; i++) {
                int e = tid + i*256;
                int c = e & 15, r = e >> 4;
                int m = m0 + r;
                pa[i] = (m < M && kn + c < K) ? A[(size_t)m*K + kn + c] : 0.f;
            }
#pragma unroll
            for (int i = 0; i < 4; i++) {
                int e = tid + i*256;
                int c = e & 15, r = e >> 4;
                pb[i] = (kn + c < K) ? B[(size_t)(n0 + r)*K + kn + c] : 0.f;
            }
        }
#pragma unroll
        for (int k = 0; k < 16; k++) {
            const u64* bp = (const u64*)&Bs[k][tx*4];
            u64 b0 = bp[0], b1 = bp[1];
#pragma unroll
            for (int i = 0; i < 8; i++) {
                float a = As[k][ty*8 + i];
                u64 a2 = f2_pack(a, a);
                acc2[i][0] = f2_fma(a2, b0, acc2[i][0]);
                acc2[i][1] = f2_fma(a2, b1, acc2[i][1]);
            }
        }
        __syncthreads();
    }

    float cs[4] = {0.f,0.f,0.f,0.f}, cq[4] = {0.f,0.f,0.f,0.f};
#pragma unroll
    for (int i = 0; i < 8; i++) {
        int m = m0 + ty*8 + i;
        if (m >= M) continue;
        float2 v0 = f2_unpack(acc2[i][0]);
        float2 v1 = f2_unpack(acc2[i][1]);
        float* dst = &C[(size_t)m*N + n0 + tx*4];
        dst[0] = v0.x; dst[1] = v0.y; dst[2] = v1.x; dst[3] = v1.y;
        cs[0] += v0.x; cq[0] += v0.x*v0.x;
        cs[1] += v0.y; cq[1] += v0.y*v0.y;
        cs[2] += v1.x; cq[2] += v1.x*v1.x;
        cs[3] += v1.y; cq[3] += v1.y*v1.y;
    }

    if (gsum) {
        float* sred = &As[0][0];
#pragma unroll
        for (int j = 0; j < 4; j++) {
            sred[ty*64 + tx*4 + j]        = cs[j];
            sred[1024 + ty*64 + tx*4 + j] = cq[j];
        }
        __syncthreads();
        if (tid < 64) {
            float S = 0.f, Q = 0.f;
#pragma unroll
            for (int t = 0; t < 16; t++) {
                S += sred[t*64 + tid];
                Q += sred[1024 + t*64 + tid];
            }
            atomicAdd(&gsum[n0 + tid],  (double)S);
            atomicAdd(&gsum2[n0 + tid], (double)Q);
        }
    }
}

// ---------------------------------------------------------------------------
// GEMM over the virtual concat [x1|x2|x3|x4|gmax] (K=768), fused BN stats.
// ---------------------------------------------------------------------------
__device__ __forceinline__ float cat_fetch(int m, int c,
                                           const float* __restrict__ x1,
                                           const float* __restrict__ x2,
                                           const float* __restrict__ x3,
                                           const float* __restrict__ x4,
                                           const float* __restrict__ gmax) {
    if (c < 64)   return x1[m*64 + c];
    if (c < 128)  return x2[m*64 + c - 64];
    if (c < 256)  return x3[m*128 + c - 128];
    if (c < 512)  return x4[m*256 + c - 256];
    return gmax[(m >> 11)*256 + c - 512];
}

__global__ __launch_bounds__(256)
void gemm_cat_kernel(const float* __restrict__ x1, const float* __restrict__ x2,
                     const float* __restrict__ x3, const float* __restrict__ x4,
                     const float* __restrict__ gmax,
                     const float* __restrict__ B,
                     float* __restrict__ C,
                     double* __restrict__ gsum, double* __restrict__ gsum2) {
    const int N = 256, K = 768;
    __shared__ __align__(16) float As[16][129];
    __shared__ __align__(16) float Bs[16][66];
    int tid = threadIdx.x;
    int tx = tid & 15;
    int ty = tid >> 4;
    int m0 = blockIdx.x * 128;
    int n0 = blockIdx.y * 64;

    u64 acc2[8][2];
#pragma unroll
    for (int i = 0; i < 8; i++) { acc2[i][0] = 0ull; acc2[i][1] = 0ull; }

    float pa[8], pb[4];
#pragma unroll
    for (int i = 0; i < 8; i++) {
        int e = tid + i*256;
        int c = e & 15, r = e >> 4;
        pa[i] = cat_fetch(m0 + r, c, x1, x2, x3, x4, gmax);
    }
#pragma unroll
    for (int i = 0; i < 4; i++) {
        int e = tid + i*256;
        int c = e & 15, r = e >> 4;
        pb[i] = B[(size_t)(n0 + r)*K + c];
    }

    for (int k0 = 0; k0 < K; k0 += 16) {
#pragma unroll
        for (int i = 0; i < 8; i++) {
            int e = tid + i*256;
            As[e & 15][e >> 4] = pa[i];
        }
#pragma unroll
        for (int i = 0; i < 4; i++) {
            int e = tid + i*256;
            Bs[e & 15][e >> 4] = pb[i];
        }
        __syncthreads();
        int kn = k0 + 16;
        if (kn < K) {
#pragma unroll
            for (int i = 0; i < 8; i++) {
                int e = tid + i*256;
                int c = e & 15, r = e >> 4;
                pa[i] = cat_fetch(m0 + r, kn + c, x1, x2, x3, x4, gmax);
            }
#pragma unroll
            for (int i = 0; i < 4; i++) {
                int e = tid + i*256;
                int c = e & 15, r = e >> 4;
                pb[i] = B[(size_t)(n0 + r)*K + kn + c];
            }
        }
#pragma unroll
        for (int k = 0; k < 16; k++) {
            const u64* bp = (const u64*)&Bs[k][tx*4];
            u64 b0 = bp[0], b1 = bp[1];
#pragma unroll
            for (int i = 0; i < 8; i++) {
                float a = As[k][ty*8 + i];
                u64 a2 = f2_pack(a, a);
                acc2[i][0] = f2_fma(a2, b0, acc2[i][0]);
                acc2[i][1] = f2_fma(a2, b1, acc2[i][1]);
            }
        }
        __syncthreads();
    }

    float cs[4] = {0.f,0.f,0.f,0.f}, cq[4] = {0.f,0.f,0.f,0.f};
#pragma unroll
    for (int i = 0; i < 8; i++) {
        int m = m0 + ty*8 + i;
        float2 v0 = f2_unpack(acc2[i][0]);
        float2 v1 = f2_unpack(acc2[i][1]);
        float* dst = &C[(size_t)m*N + n0 + tx*4];
        dst[0] = v0.x; dst[1] = v0.y; dst[2] = v1.x; dst[3] = v1.y;
        cs[0] += v0.x; cq[0] += v0.x*v0.x;
        cs[1] += v0.y; cq[1] += v0.y*v0.y;
        cs[2] += v1.x; cq[2] += v1.x*v1.x;
        cs[3] += v1.y; cq[3] += v1.y*v1.y;
    }

    float* sred = &As[0][0];
#pragma unroll
    for (int j = 0; j < 4; j++) {
        sred[ty*64 + tx*4 + j]        = cs[j];
        sred[1024 + ty*64 + tx*4 + j] = cq[j];
    }
    __syncthreads();
    if (tid < 64) {
        float S = 0.f, Q = 0.f;
#pragma unroll
        for (int t = 0; t < 16; t++) {
            S += sred[t*64 + tid];
            Q += sred[1024 + t*64 + tid];
        }
        atomicAdd(&gsum[n0 + tid],  (double)S);
        atomicAdd(&gsum2[n0 + tid], (double)Q);
    }
}

// ---------------------------------------------------------------------------
// FUSED edge-conv: 8 points x 20 neighbors (160 rows) x 64 channels, f32x2,
// register-prefetch pipelined gathered loads. (R11 form.)
// ---------------------------------------------------------------------------
#define FP    8
#define FROWS (FP*KNN)            // 160
#define AS_STRIDE 161             // 161 % 32 == 1  -> conflict-free
#define BS_BASE   (16*AS_STRIDE)  // 2576 floats (16B aligned)
#define BS_STRIDE 68              // rows 16B aligned
#define STG_STRIDE 66

__global__ __launch_bounds__(256)
void fused_edge_kernel(const float* __restrict__ feat,   // [BNTOT, C]
                       const float* __restrict__ wa,     // [O, C]
                       const float* __restrict__ T,      // [BNTOT, O]
                       const int* __restrict__ idx,      // [BNTOT, KNN]
                       int C, int O,
                       float* __restrict__ hmax, float* __restrict__ hmin,
                       double* __restrict__ gsum, double* __restrict__ gsum2) {
    __shared__ __align__(16) float pool[FROWS*STG_STRIDE];   // 10560 floats
    __shared__ int   sidx[FROWS];
    __shared__ float sT[FP*64];

    int tid = threadIdx.x;
    int p0  = blockIdx.x * FP;
    int n0  = blockIdx.y * 64;

    if (tid < FROWS) {
        int p  = tid / KNN;
        int k  = tid - p*KNN;
        int bn = p0 + p;
        sidx[tid] = (bn >> 11)*NPTS + idx[bn*KNN + k];
    }
    {
        int e = tid;
        sT[e] = T[(size_t)(p0 + (e >> 6))*O + n0 + (e & 63)];
        e += 256;
        sT[e] = T[(size_t)(p0 + (e >> 6))*O + n0 + (e & 63)];
    }
    __syncthreads();

    int tx = tid & 7;
    int ty = tid >> 3;

    u64 acc2[5][4];
#pragma unroll
    for (int i = 0; i < 5; i++)
#pragma unroll
        for (int j = 0; j < 4; j++) acc2[i][j] = 0ull;

    float pa[10], pb[4];
#pragma unroll
    for (int i = 0; i < 10; i++) {
        int e = tid + i*256;
        int c = e & 15, r = e >> 4;
        pa[i] = (c < C) ? feat[(size_t)sidx[r]*C + c] : 0.f;
    }
#pragma unroll
    for (int i = 0; i < 4; i++) {
        int e = tid + i*256;
        int c = e & 15, r = e >> 4;
        pb[i] = (c < C) ? wa[(size_t)(n0 + r)*C + c] : 0.f;
    }

    for (int k0 = 0; k0 < C; k0 += 16) {
#pragma unroll
        for (int i = 0; i < 10; i++) {
            int e = tid + i*256;
            pool[(e & 15)*AS_STRIDE + (e >> 4)] = pa[i];
        }
#pragma unroll
        for (int i = 0; i < 4; i++) {
            int e = tid + i*256;
            pool[BS_BASE + (e & 15)*BS_STRIDE + (e >> 4)] = pb[i];
        }
        __syncthreads();
        int kn = k0 + 16;
        if (kn < C) {
#pragma unroll
            for (int i = 0; i < 10; i++) {
                int e = tid + i*256;
                int c = e & 15, r = e >> 4;
                pa[i] = (kn + c < C) ? feat[(size_t)sidx[r]*C + kn + c] : 0.f;
            }
#pragma unroll
            for (int i = 0; i < 4; i++) {
                int e = tid + i*256;
                int c = e & 15, r = e >> 4;
                pb[i] = (kn + c < C) ? wa[(size_t)(n0 + r)*C + kn + c] : 0.f;
            }
        }
#pragma unroll
        for (int k = 0; k < 16; k++) {
            const u64* bp = (const u64*)&pool[BS_BASE + k*BS_STRIDE + tx*8];
            u64 b2[4] = { bp[0], bp[1], bp[2], bp[3] };
#pragma unroll
            for (int i = 0; i < 5; i++) {
                float a = pool[k*AS_STRIDE + ty*5 + i];
                u64 a2 = f2_pack(a, a);
#pragma unroll
                for (int jp = 0; jp < 4; jp++)
                    acc2[i][jp] = f2_fma(a2, b2[jp], acc2[i][jp]);
            }
        }
        __syncthreads();
    }

#pragma unroll
    for (int i = 0; i < 5; i++) {
        int r = ty*5 + i;
        int p = r / KNN;
#pragma unroll
        for (int jp = 0; jp < 4; jp++) {
            float2 v = f2_unpack(acc2[i][jp]);
            pool[r*STG_STRIDE + tx*8 + 2*jp]     = v.x + sT[p*64 + tx*8 + 2*jp];
            pool[r*STG_STRIDE + tx*8 + 2*jp + 1] = v.y + sT[p*64 + tx*8 + 2*jp + 1];
        }
    }
    __syncthreads();

    int ol = tid & 63;
    int gi = tid >> 6;
    float s = 0.f, s2 = 0.f;
#pragma unroll
    for (int half = 0; half < 2; half++) {
        int p = gi + half*4;
        float mx = -INFINITY, mn = INFINITY;
#pragma unroll
        for (int k = 0; k < KNN; k++) {
            float v = pool[(p*KNN + k)*STG_STRIDE + ol];
            mx = fmaxf(mx, v); mn = fminf(mn, v);
            s += v; s2 += v*v;
        }
        size_t oi = (size_t)(p0 + p)*O + n0 + ol;
        hmax[oi] = mx;
        hmin[oi] = mn;
    }
    __syncthreads();
    sT[gi*64 + ol] = s;
    sT[256 + gi*64 + ol] = s2;
    __syncthreads();
    if (gi == 0) {
        float ts  = sT[ol] + sT[64+ol] + sT[128+ol] + sT[192+ol];
        float ts2 = sT[256+ol] + sT[320+ol] + sT[384+ol] + sT[448+ol];
        atomicAdd(&gsum[n0 + ol],  (double)ts);
        atomicAdd(&gsum2[n0 + ol], (double)ts2);
    }
}

// bn_params: computes scale/shift, then ZEROES the accumulators for the next
// user (removes standalone zero_stats launches; replay-safe).
__global__ void bn_params_kernel(double* __restrict__ gsum, double* __restrict__ gsum2,
                                 const float* __restrict__ g, const float* __restrict__ b,
                                 int O, double cnt,
                                 float* __restrict__ scale, float* __restrict__ shift) {
    int o = threadIdx.x;
    if (o < O) {
        double m   = gsum[o] / cnt;
        double var = gsum2[o] / cnt - m*m;
        float sc = g[o] * rsqrtf((float)var + BN_EPS);
        scale[o] = sc;
        shift[o] = b[o] - (float)m * sc;
    }
    gsum[o] = 0.0;
    gsum2[o] = 0.0;
}

__global__ void edge_finalize_kernel(const float* __restrict__ hmax, const float* __restrict__ hmin,
                                     const float* __restrict__ scale, const float* __restrict__ shift,
                                     float* __restrict__ out, int O) {
    int i = blockIdx.x*256 + threadIdx.x;
    if (i >= BNTOT*O) return;
    int o = i & (O - 1);
    float sc = scale[o];
    float v = (sc >= 0.f ? hmax[i] : hmin[i]) * sc + shift[o];
    out[i] = v >= 0.f ? v : NEG_SLOPE*v;
}

// h6: act + global max over n per (b,o)
__global__ __launch_bounds__(256)
void h6_finalize_kernel(const float* __restrict__ P,
                        const float* __restrict__ scale, const float* __restrict__ shift,
                        float* __restrict__ gmax) {
    int ol = threadIdx.x & 63;
    int gi = threadIdx.x >> 6;
    int o = blockIdx.x*64 + ol;
    int b = blockIdx.y;
    float sc = scale[o], sh = shift[o];
    float mx = -INFINITY;
    for (int n = gi*512; n < (gi+1)*512; n++) {
        float v = P[((size_t)(b*NPTS + n))*256 + o]*sc + sh;
        v = v >= 0.f ? v : NEG_SLOPE*v;
        mx = fmaxf(mx, v);
    }
    __shared__ float sm[4][64];
    sm[gi][ol] = mx;
    __syncthreads();
    if (gi == 0)
        gmax[b*256 + o] = fmaxf(fmaxf(sm[0][ol], sm[1][ol]), fmaxf(sm[2][ol], sm[3][ol]));
}

// final: act + transpose (B,N,256) -> (B,256,N)
__global__ void out_transpose_kernel(const float* __restrict__ P,
                                     const float* __restrict__ scale, const float* __restrict__ shift,
                                     float* __restrict__ out) {
    __shared__ float tile[32][33];
    int b  = blockIdx.z;
    int n0 = blockIdx.x*32, o0 = blockIdx.y*32;
    int tx = threadIdx.x, ty = threadIdx.y;
    int o = o0 + tx;
    float v = P[((size_t)(b*NPTS + n0 + ty))*256 + o]*scale[o] + shift[o];
    v = v >= 0.f ? v : NEG_SLOPE*v;
    tile[ty][tx] = v;
    __syncthreads();
    out[(size_t)b*256*NPTS + (size_t)(o0 + ty)*NPTS + n0 + tx] = tile[tx][ty];
}

// ---------------------------------------------------------------------------
// Host side
// ---------------------------------------------------------------------------
static void* sym(const void* s) { void* p = nullptr; cudaGetSymbolAddress(&p, s); return p; }

extern "C" void kernel_launch(void* const* d_in, const int* in_sizes, int n_in,
                              void* d_out, int out_size) {
    const float* x  = (const float*)d_in[0];
    const float* W[4] = { (const float*)d_in[1], (const float*)d_in[4],
                          (const float*)d_in[7], (const float*)d_in[10] };
    const float* G[4] = { (const float*)d_in[2], (const float*)d_in[5],
                          (const float*)d_in[8], (const float*)d_in[11] };
    const float* Bb[4] = { (const float*)d_in[3], (const float*)d_in[6],
                           (const float*)d_in[9], (const float*)d_in[12] };
    const float* W6 = (const float*)d_in[13];
    const float* g6 = (const float*)d_in[14];
    const float* b6 = (const float*)d_in[15];
    const float* W5 = (const float*)d_in[16];
    const float* g5 = (const float*)d_in[17];
    const float* b5 = (const float*)d_in[18];

    float*  f0   = (float*)sym(g_f0);
    float*  x1   = (float*)sym(g_x1);
    float*  x2   = (float*)sym(g_x2);
    float*  x3   = (float*)sym(g_x3);
    float*  x4   = (float*)sym(g_x4);
    float*  pd   = (float*)sym(g_pd);
    int*    idx  = (int*)  sym(g_idx);
    float*  wa   = (float*)sym(g_wa);
    float*  wd   = (float*)sym(g_wd);
    float*  Tb   = (float*)sym(g_T);
    float*  hmax = (float*)sym(g_hmax);
    float*  hmin = (float*)sym(g_hmin);
    float*  Pb   = (float*)sym(g_P);
    float*  gmax = (float*)sym(g_gmax);
    double* s0   = (double*)sym(g_sum);
    double* s2   = (double*)sym(g_sum2);
    float*  sc   = (float*)sym(g_scale);
    float*  sh   = (float*)sym(g_shift);

    // input transpose (B,3,N) -> (B,N,3)
    transpose_in_kernel<<<(NB*3*NPTS + 255)/256, 256>>>(x, f0);

    const float* feats[4] = { f0, x1, x2, x3 };
    float*       outs [4] = { x1, x2, x3, x4 };
    const int    Cs[4] = { 3, 64, 64, 128 };
    const int    Os[4] = { 64, 64, 128, 256 };

    for (int L = 0; L < 4; L++) {
        int C = Cs[L], O = Os[L];
        const float* feat = feats[L];

        // order: prep_w(2), dist(3), topk(4 on L0 -> ncu capture slot), gemmT(5)
        prep_w_kernel<<<(O*C + 255)/256, 256>>>(W[L], O, C, wa, wd, s0, s2);

        dim3 ggrid(NPAIRS, 1, NB);
        if (C == 3) dist_sym_kernel<4><<<ggrid, 256>>>(feat, pd, C);
        else        dist_sym_kernel<16><<<ggrid, 256>>>(feat, pd, C);
        topk_warp_kernel<<<BNTOT/TK_WARPS, TK_WARPS*32>>>(pd, idx);

        gemm_nt_kernel<<<dim3((BNTOT + 127)/128, O/64), 256>>>(
            feat, wd, Tb, BNTOT, O, C, nullptr, nullptr);

        fused_edge_kernel<<<dim3(BNTOT/FP, O/64), 256>>>(
            feat, wa, Tb, idx, C, O, hmax, hmin, s0, s2);
        bn_params_kernel<<<1, 256>>>(s0, s2, G[L], Bb[L], O, (double)MEDGE, sc, sh);
        edge_finalize_kernel<<<(BNTOT*O + 255)/256, 256>>>(hmax, hmin, sc, sh, outs[L], O);
    }

    // --- point conv h6 = lrelu(bn(x4 . W6^T)), then x5 = max over n ---
    // (stats accumulators already zeroed by the last bn_params)
    gemm_nt_kernel<<<dim3(BNTOT/128, 256/64), 256>>>(x4, W6, Pb, BNTOT, 256, 256, s0, s2);
    bn_params_kernel<<<1, 256>>>(s0, s2, g6, b6, 256, (double)BNTOT, sc, sh);
    h6_finalize_kernel<<<dim3(256/64, NB), 256>>>(Pb, sc, sh, gmax);

    // --- final point conv over virtual concat + BN stats fused ---
    gemm_cat_kernel<<<dim3(BNTOT/128, 256/64), 256>>>(
        x1, x2, x3, x4, gmax, W5, Pb, s0, s2);
    bn_params_kernel<<<1, 256>>>(s0, s2, g5, b5, 256, (double)BNTOT, sc, sh);
    out_transpose_kernel<<<dim3(NPTS/32, 256/32, NB), dim3(32, 32)>>>(Pb, sc, sh, (float*)d_out);
}

// round 16
// speedup vs baseline: 1.5569x; 1.1258x over previous
#include <cuda_runtime.h>
#include <cuda_bf16.h>
#include <math.h>

// ---------------------------------------------------------------------------
// Problem constants
// ---------------------------------------------------------------------------
#define NB 8
#define NPTS 2048
#define BNTOT (NB*NPTS)          // 16384
#define KNN 20
#define MEDGE (BNTOT*KNN)        // 327680
#define NEG_SLOPE 0.2f
#define BN_EPS 1e-5f
#define NT 16                    // 2048/128 tiles per dim
#define NPAIRS (NT*(NT+1)/2)     // 136

typedef unsigned long long u64;

// ---------------------------------------------------------------------------
// Packed fp32x2 helpers: per-half rounding identical to scalar ops.
// ---------------------------------------------------------------------------
__device__ __forceinline__ u64 f2_pack(float lo, float hi) {
    u64 d;
    asm("mov.b64 %0, {%1, %2};" : "=l"(d)
        : "r"(__float_as_uint(lo)), "r"(__float_as_uint(hi)));
    return d;
}
__device__ __forceinline__ float2 f2_unpack(u64 d) {
    unsigned lo, hi;
    asm("mov.b64 {%0, %1}, %2;" : "=r"(lo), "=r"(hi) : "l"(d));
    return make_float2(__uint_as_float(lo), __uint_as_float(hi));
}
__device__ __forceinline__ u64 f2_fma(u64 a, u64 b, u64 c) {
    u64 d;
    asm("fma.rn.f32x2 %0, %1, %2, %3;" : "=l"(d) : "l"(a), "l"(b), "l"(c));
    return d;
}
__device__ __forceinline__ u64 f2_add(u64 a, u64 b) {
    u64 d;
    asm("add.rn.f32x2 %0, %1, %2;" : "=l"(d) : "l"(a), "l"(b));
    return d;
}

// ---------------------------------------------------------------------------
// Scratch (device globals -- no allocation allowed)
// ---------------------------------------------------------------------------
__device__ float g_f0  [BNTOT*3];
__device__ float g_x1  [BNTOT*64];
__device__ float g_x2  [BNTOT*64];
__device__ float g_x3  [BNTOT*128];
__device__ float g_x4  [BNTOT*256];
__device__ float g_pd  [(size_t)NB*NPTS*NPTS];       // 134 MB
__device__ int   g_idx [MEDGE];
__device__ float g_wa  [256*128];
__device__ float g_wd  [256*128];
__device__ float g_T   [BNTOT*256];
__device__ float g_hmax[BNTOT*256];
__device__ float g_hmin[BNTOT*256];
__device__ float g_P   [BNTOT*256];
__device__ float g_gmax[NB*256];
__device__ double g_sum [256];
__device__ double g_sum2[256];
__device__ float g_scale[256];
__device__ float g_shift[256];

// ---------------------------------------------------------------------------
// Small elementwise kernels
// ---------------------------------------------------------------------------
__global__ void transpose_in_kernel(const float* __restrict__ x, float* __restrict__ f) {
    int i = blockIdx.x*256 + threadIdx.x;                 // B*3*N = 49152
    if (i >= NB*3*NPTS) return;
    int b = i / (3*NPTS);
    int rem = i - b*3*NPTS;
    int c = rem / NPTS;
    int n = rem - c*NPTS;
    f[(b*NPTS + n)*3 + c] = x[i];
}

// prep_w also zeroes the BN stat accumulators (block 0) -- saves a launch.
__global__ void prep_w_kernel(const float* __restrict__ W, int O, int C,
                              float* __restrict__ wa, float* __restrict__ wd,
                              double* __restrict__ s0, double* __restrict__ s2) {
    int i = blockIdx.x*256 + threadIdx.x;
    if (blockIdx.x == 0) { s0[threadIdx.x] = 0.0; s2[threadIdx.x] = 0.0; }
    if (i >= O*C) return;
    int o = i / C, c = i - o*C;
    float a = W[o*2*C + c];
    wa[i] = a;
    wd[i] = W[o*2*C + C + c] - a;
}

// ---------------------------------------------------------------------------
// SYMMETRIC squared-distance kernel: pd[b,i,j] = -sum_c (x_i[c]-x_j[c])^2
// ---------------------------------------------------------------------------
template<int KS>
__global__ __launch_bounds__(256)
void dist_sym_kernel(const float* __restrict__ feat, float* __restrict__ pd, int C) {
    __shared__ __align__(16) float As[KS][132];
    __shared__ __align__(16) float Bs[KS][132];
    int b = blockIdx.z;
    int Lp = blockIdx.x;
    int ti = 0;
    while (Lp >= NT - ti) { Lp -= NT - ti; ti++; }
    int tj = ti + Lp;
    int m0 = ti*128, n0 = tj*128;
    bool diag = (ti == tj);

    const float* F = feat + (size_t)b*NPTS*C;
    int tid = threadIdx.x;
    int tx = tid & 15, ty = tid >> 4;

    u64 acc2[8][4];
#pragma unroll
    for (int i = 0; i < 8; i++)
#pragma unroll
        for (int j = 0; j < 4; j++) acc2[i][j] = 0ull;

    for (int k0 = 0; k0 < C; k0 += KS) {
#pragma unroll
        for (int e = tid; e < 128*KS; e += 256) {
            int c = e % KS, r = e / KS;
            float va = 0.f, vb = 0.f;
            if (k0 + c < C) {
                va = F[(size_t)(m0 + r)*C + k0 + c];
                vb = F[(size_t)(n0 + r)*C + k0 + c];
            }
            As[c][r] = va;
            Bs[c][r] = -vb;          // negate so inner loop uses add.f32x2
        }
        __syncthreads();
#pragma unroll
        for (int k = 0; k < KS; k++) {
            float af[8];
#pragma unroll
            for (int i = 0; i < 8; i++) af[i] = As[k][ty*8 + i];
            const u64* bp = (const u64*)&Bs[k][tx*8];
            u64 b2[4] = { bp[0], bp[1], bp[2], bp[3] };
#pragma unroll
            for (int i = 0; i < 8; i++) {
                u64 a2 = f2_pack(af[i], af[i]);
#pragma unroll
                for (int jp = 0; jp < 4; jp++) {
                    u64 d2 = f2_add(a2, b2[jp]);       // (a-b0, a-b1)
                    acc2[i][jp] = f2_fma(d2, d2, acc2[i][jp]);
                }
            }
        }
        __syncthreads();
    }

    float neg[8][8];
#pragma unroll
    for (int i = 0; i < 8; i++)
#pragma unroll
        for (int jp = 0; jp < 4; jp++) {
            float2 v = f2_unpack(acc2[i][jp]);
            neg[i][2*jp]   = -v.x;
            neg[i][2*jp+1] = -v.y;
        }

    float* pdb = pd + (size_t)b*NPTS*NPTS;
#pragma unroll
    for (int i = 0; i < 8; i++) {
        int m = m0 + ty*8 + i;
        float4 w0 = make_float4(neg[i][0], neg[i][1], neg[i][2], neg[i][3]);
        float4 w1 = make_float4(neg[i][4], neg[i][5], neg[i][6], neg[i][7]);
        float4* dst = (float4*)&pdb[(size_t)m*NPTS + n0 + tx*8];
        dst[0] = w0;
        dst[1] = w1;
    }
    if (!diag) {
#pragma unroll
        for (int j = 0; j < 8; j++) {
            int n = n0 + tx*8 + j;
            float4 w0 = make_float4(neg[0][j], neg[1][j], neg[2][j], neg[3][j]);
            float4 w1 = make_float4(neg[4][j], neg[5][j], neg[6][j], neg[7][j]);
            float4* dst = (float4*)&pdb[(size_t)n*NPTS + m0 + ty*8];
            dst[0] = w0;
            dst[1] = w1;
        }
    }
}

// ---------------------------------------------------------------------------
// WARP-PER-ROW top-K, smem values + poison rescan + REGISTER lane-best cache.
// Only the owner lane's candidate set changes per iteration, so each lane
// keeps its (best val, best idx) in registers; the owner re-derives its best
// from the 8 group maxima (lane-keyed smem) after poisoning the winner slot.
// Selection: global argmax, ties -> lowest global index (== jax top_k).
// idx bitwise identical to prior rounds.
// ---------------------------------------------------------------------------
#define TK_WARPS 4
__global__ __launch_bounds__(TK_WARPS*32)
void topk_warp_kernel(const float* __restrict__ pd, int* __restrict__ idx) {
    __shared__ float sv [TK_WARPS][NPTS];
    __shared__ float sgv[TK_WARPS][8][32];
    __shared__ int   sgm[TK_WARPS][8][32];
    int w = threadIdx.x >> 5, l = threadIdx.x & 31;
    int bn = blockIdx.x*TK_WARPS + w;
    const float* row = pd + (size_t)bn*NPTS;
    float* v = sv[w];

    // load row (coalesced) + per-lane group maxima in registers (static idx)
    float gv[8]; int gm[8];
#pragma unroll
    for (int g = 0; g < 8; g++) { gv[g] = -INFINITY; gm[g] = g*8; }
#pragma unroll
    for (int off = 0; off < 64; off++) {
        float x = row[off*32 + l];
        v[off*32 + l] = x;
        int g = off >> 3;                  // compile-time after unroll
        if (x > gv[g]) { gv[g] = x; gm[g] = off; }   // strict > keeps lowest off
    }
    // flush group maxima to lane-keyed smem + lane best in registers
    float myv = -INFINITY; int myoff = 0;
#pragma unroll
    for (int g = 0; g < 8; g++) {
        sgv[w][g][l] = gv[g]; sgm[w][g][l] = gm[g];
        if (gv[g] > myv) { myv = gv[g]; myoff = gm[g]; }  // ascending g keeps lowest
    }
    int myix = myoff*32 + l;
    // warp-private smem, each lane touches only its own slots: no sync needed

    int my_out = 0;
    for (int it = 0; it < KNN; it++) {
        float val = myv; int ix = myix;
#pragma unroll
        for (int s = 16; s > 0; s >>= 1) {
            float ov = __shfl_xor_sync(0xffffffff, val, s);
            int   oi = __shfl_xor_sync(0xffffffff, ix, s);
            if (ov > val || (ov == val && oi < ix)) { val = ov; ix = oi; }
        }
        if (l == it) my_out = ix;

        int owner = ix & 31;
        if (l == owner) {
            int off = ix >> 5;
            v[off*32 + l] = -INFINITY;               // poison winner slot
            int g = off >> 3;
            int base = g*8;
            float bv2 = -INFINITY; int bo2 = base;
#pragma unroll
            for (int m = 0; m < 8; m++) {
                float x = v[(base + m)*32 + l];      // LDS, dynamic base OK
                if (x > bv2) { bv2 = x; bo2 = base + m; }
            }
            sgv[w][g][l] = bv2;                      // dynamic g: smem, safe
            sgm[w][g][l] = bo2;
            // re-derive lane best from the 8 group maxima
            float nb = -INFINITY; int ng = 0;
#pragma unroll
            for (int g2 = 0; g2 < 8; g2++) {
                float x = sgv[w][g2][l];
                if (x > nb) { nb = x; ng = g2; }
            }
            myv = nb;
            myix = sgm[w][ng][l]*32 + l;
        }
    }
    if (l < KNN) idx[bn*KNN + l] = my_out;
}

// ---------------------------------------------------------------------------
// Generic NT GEMM: C[m,n] = sum_k A[m,k]*B[n,k], f32x2 inner, LDG prefetch.
// Optional fused per-channel sum/sumsq (BN stats) via block partials + atomics.
// ---------------------------------------------------------------------------
__global__ __launch_bounds__(256)
void gemm_nt_kernel(const float* __restrict__ A, const float* __restrict__ B,
                    float* __restrict__ C, int M, int N, int K,
                    double* __restrict__ gsum, double* __restrict__ gsum2) {
    __shared__ __align__(16) float As[16][129];
    __shared__ __align__(16) float Bs[16][66];
    int tid = threadIdx.x;
    int tx = tid & 15;
    int ty = tid >> 4;
    int m0 = blockIdx.x * 128;
    int n0 = blockIdx.y * 64;

    u64 acc2[8][2];
#pragma unroll
    for (int i = 0; i < 8; i++) { acc2[i][0] = 0ull; acc2[i][1] = 0ull; }

    float pa[8], pb[4];
#pragma unroll
    for (int i = 0; i < 8; i++) {
        int e = tid + i*256;
        int c = e & 15, r = e >> 4;
        int m = m0 + r;
        pa[i] = (m < M && c < K) ? A[(size_t)m*K + c] : 0.f;
    }
#pragma unroll
    for (int i = 0; i < 4; i++) {
        int e = tid + i*256;
        int c = e & 15, r = e >> 4;
        pb[i] = (c < K) ? B[(size_t)(n0 + r)*K + c] : 0.f;
    }

    for (int k0 = 0; k0 < K; k0 += 16) {
#pragma unroll
        for (int i = 0; i < 8; i++) {
            int e = tid + i*256;
            As[e & 15][e >> 4] = pa[i];
        }
#pragma unroll
        for (int i = 0; i < 4; i++) {
            int e = tid + i*256;
            Bs[e & 15][e >> 4] = pb[i];
        }
        __syncthreads();
        int kn = k0 + 16;
        if (kn < K) {
#pragma unroll
            for (int i = 0; i < 8; i++) {
                int e = tid + i*256;
                int c = e & 15, r = e >> 4;
                int m = m0 + r;
                pa[i] = (m < M && kn + c < K) ? A[(size_t)m*K + kn + c] : 0.f;
            }
#pragma unroll
            for (int i = 0; i < 4; i++) {
                int e = tid + i*256;
                int c = e & 15, r = e >> 4;
                pb[i] = (kn + c < K) ? B[(size_t)(n0 + r)*K + kn + c] : 0.f;
            }
        }
#pragma unroll
        for (int k = 0; k < 16; k++) {
            const u64* bp = (const u64*)&Bs[k][tx*4];
            u64 b0 = bp[0], b1 = bp[1];
#pragma unroll
            for (int i = 0; i < 8; i++) {
                float a = As[k][ty*8 + i];
                u64 a2 = f2_pack(a, a);
                acc2[i][0] = f2_fma(a2, b0, acc2[i][0]);
                acc2[i][1] = f2_fma(a2, b1, acc2[i][1]);
            }
        }
        __syncthreads();
    }

    float cs[4] = {0.f,0.f,0.f,0.f}, cq[4] = {0.f,0.f,0.f,0.f};
#pragma unroll
    for (int i = 0; i < 8; i++) {
        int m = m0 + ty*8 + i;
        if (m >= M) continue;
        float2 v0 = f2_unpack(acc2[i][0]);
        float2 v1 = f2_unpack(acc2[i][1]);
        float* dst = &C[(size_t)m*N + n0 + tx*4];
        dst[0] = v0.x; dst[1] = v0.y; dst[2] = v1.x; dst[3] = v1.y;
        cs[0] += v0.x; cq[0] += v0.x*v0.x;
        cs[1] += v0.y; cq[1] += v0.y*v0.y;
        cs[2] += v1.x; cq[2] += v1.x*v1.x;
        cs[3] += v1.y; cq[3] += v1.y*v1.y;
    }

    if (gsum) {
        float* sred = &As[0][0];
#pragma unroll
        for (int j = 0; j < 4; j++) {
            sred[ty*64 + tx*4 + j]        = cs[j];
            sred[1024 + ty*64 + tx*4 + j] = cq[j];
        }
        __syncthreads();
        if (tid < 64) {
            float S = 0.f, Q = 0.f;
#pragma unroll
            for (int t = 0; t < 16; t++) {
                S += sred[t*64 + tid];
                Q += sred[1024 + t*64 + tid];
            }
            atomicAdd(&gsum[n0 + tid],  (double)S);
            atomicAdd(&gsum2[n0 + tid], (double)Q);
        }
    }
}

// ---------------------------------------------------------------------------
// GEMM over the virtual concat [x1|x2|x3|x4|gmax] (K=768), fused BN stats.
// ---------------------------------------------------------------------------
__device__ __forceinline__ float cat_fetch(int m, int c,
                                           const float* __restrict__ x1,
                                           const float* __restrict__ x2,
                                           const float* __restrict__ x3,
                                           const float* __restrict__ x4,
                                           const float* __restrict__ gmax) {
    if (c < 64)   return x1[m*64 + c];
    if (c < 128)  return x2[m*64 + c - 64];
    if (c < 256)  return x3[m*128 + c - 128];
    if (c < 512)  return x4[m*256 + c - 256];
    return gmax[(m >> 11)*256 + c - 512];
}

__global__ __launch_bounds__(256)
void gemm_cat_kernel(const float* __restrict__ x1, const float* __restrict__ x2,
                     const float* __restrict__ x3, const float* __restrict__ x4,
                     const float* __restrict__ gmax,
                     const float* __restrict__ B,
                     float* __restrict__ C,
                     double* __restrict__ gsum, double* __restrict__ gsum2) {
    const int N = 256, K = 768;
    __shared__ __align__(16) float As[16][129];
    __shared__ __align__(16) float Bs[16][66];
    int tid = threadIdx.x;
    int tx = tid & 15;
    int ty = tid >> 4;
    int m0 = blockIdx.x * 128;
    int n0 = blockIdx.y * 64;

    u64 acc2[8][2];
#pragma unroll
    for (int i = 0; i < 8; i++) { acc2[i][0] = 0ull; acc2[i][1] = 0ull; }

    float pa[8], pb[4];
#pragma unroll
    for (int i = 0; i < 8; i++) {
        int e = tid + i*256;
        int c = e & 15, r = e >> 4;
        pa[i] = cat_fetch(m0 + r, c, x1, x2, x3, x4, gmax);
    }
#pragma unroll
    for (int i = 0; i < 4; i++) {
        int e = tid + i*256;
        int c = e & 15, r = e >> 4;
        pb[i] = B[(size_t)(n0 + r)*K + c];
    }

    for (int k0 = 0; k0 < K; k0 += 16) {
#pragma unroll
        for (int i = 0; i < 8; i++) {
            int e = tid + i*256;
            As[e & 15][e >> 4] = pa[i];
        }
#pragma unroll
        for (int i = 0; i < 4; i++) {
            int e = tid + i*256;
            Bs[e & 15][e >> 4] = pb[i];
        }
        __syncthreads();
        int kn = k0 + 16;
        if (kn < K) {
#pragma unroll
            for (int i = 0; i < 8; i++) {
                int e = tid + i*256;
                int c = e & 15, r = e >> 4;
                pa[i] = cat_fetch(m0 + r, kn + c, x1, x2, x3, x4, gmax);
            }
#pragma unroll
            for (int i = 0; i < 4; i++) {
                int e = tid + i*256;
                int c = e & 15, r = e >> 4;
                pb[i] = B[(size_t)(n0 + r)*K + kn + c];
            }
        }
#pragma unroll
        for (int k = 0; k < 16; k++) {
            const u64* bp = (const u64*)&Bs[k][tx*4];
            u64 b0 = bp[0], b1 = bp[1];
#pragma unroll
            for (int i = 0; i < 8; i++) {
                float a = As[k][ty*8 + i];
                u64 a2 = f2_pack(a, a);
                acc2[i][0] = f2_fma(a2, b0, acc2[i][0]);
                acc2[i][1] = f2_fma(a2, b1, acc2[i][1]);
            }
        }
        __syncthreads();
    }

    float cs[4] = {0.f,0.f,0.f,0.f}, cq[4] = {0.f,0.f,0.f,0.f};
#pragma unroll
    for (int i = 0; i < 8; i++) {
        int m = m0 + ty*8 + i;
        float2 v0 = f2_unpack(acc2[i][0]);
        float2 v1 = f2_unpack(acc2[i][1]);
        float* dst = &C[(size_t)m*N + n0 + tx*4];
        dst[0] = v0.x; dst[1] = v0.y; dst[2] = v1.x; dst[3] = v1.y;
        cs[0] += v0.x; cq[0] += v0.x*v0.x;
        cs[1] += v0.y; cq[1] += v0.y*v0.y;
        cs[2] += v1.x; cq[2] += v1.x*v1.x;
        cs[3] += v1.y; cq[3] += v1.y*v1.y;
    }

    float* sred = &As[0][0];
#pragma unroll
    for (int j = 0; j < 4; j++) {
        sred[ty*64 + tx*4 + j]        = cs[j];
        sred[1024 + ty*64 + tx*4 + j] = cq[j];
    }
    __syncthreads();
    if (tid < 64) {
        float S = 0.f, Q = 0.f;
#pragma unroll
        for (int t = 0; t < 16; t++) {
            S += sred[t*64 + tid];
            Q += sred[1024 + t*64 + tid];
        }
        atomicAdd(&gsum[n0 + tid],  (double)S);
        atomicAdd(&gsum2[n0 + tid], (double)Q);
    }
}

// ---------------------------------------------------------------------------
// FUSED edge-conv: 8 points x 20 neighbors (160 rows) x 64 channels, f32x2,
// register-prefetch pipelined gathered loads. B rows stored split-half so the
// two bf LDS.128 hit 32 distinct banks (conflict-free):
//   loc(n) = (n>>3)*4 + (n&3) + 32*((n>>2)&1)
// ---------------------------------------------------------------------------
#define FP    8
#define FROWS (FP*KNN)            // 160
#define AS_STRIDE 161             // 161 % 32 == 1  -> conflict-free
#define BS_BASE   (16*AS_STRIDE)  // 2576 floats (16B aligned)
#define BS_STRIDE 68              // rows 16B aligned
#define STG_STRIDE 66

__device__ __forceinline__ int b_loc(int n) {
    return ((n >> 3) << 2) + (n & 3) + (((n >> 2) & 1) << 5);
}

__global__ __launch_bounds__(256)
void fused_edge_kernel(const float* __restrict__ feat,   // [BNTOT, C]
                       const float* __restrict__ wa,     // [O, C]
                       const float* __restrict__ T,      // [BNTOT, O]
                       const int* __restrict__ idx,      // [BNTOT, KNN]
                       int C, int O,
                       float* __restrict__ hmax, float* __restrict__ hmin,
                       double* __restrict__ gsum, double* __restrict__ gsum2) {
    __shared__ __align__(16) float pool[FROWS*STG_STRIDE];   // 10560 floats
    __shared__ int   sidx[FROWS];
    __shared__ float sT[FP*64];

    int tid = threadIdx.x;
    int p0  = blockIdx.x * FP;
    int n0  = blockIdx.y * 64;

    if (tid < FROWS) {
        int p  = tid / KNN;
        int k  = tid - p*KNN;
        int bn = p0 + p;
        sidx[tid] = (bn >> 11)*NPTS + idx[bn*KNN + k];
    }
    {
        int e = tid;
        sT[e] = T[(size_t)(p0 + (e >> 6))*O + n0 + (e & 63)];
        e += 256;
        sT[e] = T[(size_t)(p0 + (e >> 6))*O + n0 + (e & 63)];
    }
    __syncthreads();

    int tx = tid & 7;
    int ty = tid >> 3;

    u64 acc2[5][4];
#pragma unroll
    for (int i = 0; i < 5; i++)
#pragma unroll
        for (int j = 0; j < 4; j++) acc2[i][j] = 0ull;

    float pa[10], pb[4];
#pragma unroll
    for (int i = 0; i < 10; i++) {
        int e = tid + i*256;
        int c = e & 15, r = e >> 4;
        pa[i] = (c < C) ? feat[(size_t)sidx[r]*C + c] : 0.f;
    }
#pragma unroll
    for (int i = 0; i < 4; i++) {
        int e = tid + i*256;
        int c = e & 15, r = e >> 4;
        pb[i] = (c < C) ? wa[(size_t)(n0 + r)*C + c] : 0.f;
    }

    for (int k0 = 0; k0 < C; k0 += 16) {
#pragma unroll
        for (int i = 0; i < 10; i++) {
            int e = tid + i*256;
            pool[(e & 15)*AS_STRIDE + (e >> 4)] = pa[i];
        }
#pragma unroll
        for (int i = 0; i < 4; i++) {
            int e = tid + i*256;
            pool[BS_BASE + (e & 15)*BS_STRIDE + b_loc(e >> 4)] = pb[i];
        }
        __syncthreads();
        int kn = k0 + 16;
        if (kn < C) {
#pragma unroll
            for (int i = 0; i < 10; i++) {
                int e = tid + i*256;
                int c = e & 15, r = e >> 4;
                pa[i] = (kn + c < C) ? feat[(size_t)sidx[r]*C + kn + c] : 0.f;
            }
#pragma unroll
            for (int i = 0; i < 4; i++) {
                int e = tid + i*256;
                int c = e & 15, r = e >> 4;
                pb[i] = (kn + c < C) ? wa[(size_t)(n0 + r)*C + kn + c] : 0.f;
            }
        }
#pragma unroll
        for (int k = 0; k < 16; k++) {
            // split-half B: two conflict-free LDS.128 at tx*4 and 32+tx*4
            const u64* bpl = (const u64*)&pool[BS_BASE + k*BS_STRIDE + tx*4];
            const u64* bph = (const u64*)&pool[BS_BASE + k*BS_STRIDE + 32 + tx*4];
            u64 b2[4] = { bpl[0], bpl[1], bph[0], bph[1] };
#pragma unroll
            for (int i = 0; i < 5; i++) {
                float a = pool[k*AS_STRIDE + ty*5 + i];
                u64 a2 = f2_pack(a, a);
#pragma unroll
                for (int jp = 0; jp < 4; jp++)
                    acc2[i][jp] = f2_fma(a2, b2[jp], acc2[i][jp]);
            }
        }
        __syncthreads();
    }

#pragma unroll
    for (int i = 0; i < 5; i++) {
        int r = ty*5 + i;
        int p = r / KNN;
#pragma unroll
        for (int jp = 0; jp < 4; jp++) {
            float2 v = f2_unpack(acc2[i][jp]);
            pool[r*STG_STRIDE + tx*8 + 2*jp]     = v.x + sT[p*64 + tx*8 + 2*jp];
            pool[r*STG_STRIDE + tx*8 + 2*jp + 1] = v.y + sT[p*64 + tx*8 + 2*jp + 1];
        }
    }
    __syncthreads();

    int ol = tid & 63;
    int gi = tid >> 6;
    float s = 0.f, s2 = 0.f;
#pragma unroll
    for (int half = 0; half < 2; half++) {
        int p = gi + half*4;
        float mx = -INFINITY, mn = INFINITY;
#pragma unroll
        for (int k = 0; k < KNN; k++) {
            float v = pool[(p*KNN + k)*STG_STRIDE + ol];
            mx = fmaxf(mx, v); mn = fminf(mn, v);
            s += v; s2 += v*v;
        }
        size_t oi = (size_t)(p0 + p)*O + n0 + ol;
        hmax[oi] = mx;
        hmin[oi] = mn;
    }
    __syncthreads();
    sT[gi*64 + ol] = s;
    sT[256 + gi*64 + ol] = s2;
    __syncthreads();
    if (gi == 0) {
        float ts  = sT[ol] + sT[64+ol] + sT[128+ol] + sT[192+ol];
        float ts2 = sT[256+ol] + sT[320+ol] + sT[384+ol] + sT[448+ol];
        atomicAdd(&gsum[n0 + ol],  (double)ts);
        atomicAdd(&gsum2[n0 + ol], (double)ts2);
    }
}

// bn_params: computes scale/shift, then ZEROES the accumulators for the next
// user (removes standalone zero_stats launches; replay-safe).
__global__ void bn_params_kernel(double* __restrict__ gsum, double* __restrict__ gsum2,
                                 const float* __restrict__ g, const float* __restrict__ b,
                                 int O, double cnt,
                                 float* __restrict__ scale, float* __restrict__ shift) {
    int o = threadIdx.x;
    if (o < O) {
        double m   = gsum[o] / cnt;
        double var = gsum2[o] / cnt - m*m;
        float sc = g[o] * rsqrtf((float)var + BN_EPS);
        scale[o] = sc;
        shift[o] = b[o] - (float)m * sc;
    }
    gsum[o] = 0.0;
    gsum2[o] = 0.0;
}

__global__ void edge_finalize_kernel(const float* __restrict__ hmax, const float* __restrict__ hmin,
                                     const float* __restrict__ scale, const float* __restrict__ shift,
                                     float* __restrict__ out, int O) {
    int i = blockIdx.x*256 + threadIdx.x;
    if (i >= BNTOT*O) return;
    int o = i & (O - 1);
    float sc = scale[o];
    float v = (sc >= 0.f ? hmax[i] : hmin[i]) * sc + shift[o];
    out[i] = v >= 0.f ? v : NEG_SLOPE*v;
}

// h6: act + global max over n per (b,o)
__global__ __launch_bounds__(256)
void h6_finalize_kernel(const float* __restrict__ P,
                        const float* __restrict__ scale, const float* __restrict__ shift,
                        float* __restrict__ gmax) {
    int ol = threadIdx.x & 63;
    int gi = threadIdx.x >> 6;
    int o = blockIdx.x*64 + ol;
    int b = blockIdx.y;
    float sc = scale[o], sh = shift[o];
    float mx = -INFINITY;
    for (int n = gi*512; n < (gi+1)*512; n++) {
        float v = P[((size_t)(b*NPTS + n))*256 + o]*sc + sh;
        v = v >= 0.f ? v : NEG_SLOPE*v;
        mx = fmaxf(mx, v);
    }
    __shared__ float sm[4][64];
    sm[gi][ol] = mx;
    __syncthreads();
    if (gi == 0)
        gmax[b*256 + o] = fmaxf(fmaxf(sm[0][ol], sm[1][ol]), fmaxf(sm[2][ol], sm[3][ol]));
}

// final: act + transpose (B,N,256) -> (B,256,N)
__global__ void out_transpose_kernel(const float* __restrict__ P,
                                     const float* __restrict__ scale, const float* __restrict__ shift,
                                     float* __restrict__ out) {
    __shared__ float tile[32][33];
    int b  = blockIdx.z;
    int n0 = blockIdx.x*32, o0 = blockIdx.y*32;
    int tx = threadIdx.x, ty = threadIdx.y;
    int o = o0 + tx;
    float v = P[((size_t)(b*NPTS + n0 + ty))*256 + o]*scale[o] + shift[o];
    v = v >= 0.f ? v : NEG_SLOPE*v;
    tile[ty][tx] = v;
    __syncthreads();
    out[(size_t)b*256*NPTS + (size_t)(o0 + ty)*NPTS + n0 + tx] = tile[tx][ty];
}

// ---------------------------------------------------------------------------
// Host side
// ---------------------------------------------------------------------------
static void* sym(const void* s) { void* p = nullptr; cudaGetSymbolAddress(&p, s); return p; }

extern "C" void kernel_launch(void* const* d_in, const int* in_sizes, int n_in,
                              void* d_out, int out_size) {
    const float* x  = (const float*)d_in[0];
    const float* W[4] = { (const float*)d_in[1], (const float*)d_in[4],
                          (const float*)d_in[7], (const float*)d_in[10] };
    const float* G[4] = { (const float*)d_in[2], (const float*)d_in[5],
                          (const float*)d_in[8], (const float*)d_in[11] };
    const float* Bb[4] = { (const float*)d_in[3], (const float*)d_in[6],
                           (const float*)d_in[9], (const float*)d_in[12] };
    const float* W6 = (const float*)d_in[13];
    const float* g6 = (const float*)d_in[14];
    const float* b6 = (const float*)d_in[15];
    const float* W5 = (const float*)d_in[16];
    const float* g5 = (const float*)d_in[17];
    const float* b5 = (const float*)d_in[18];

    float*  f0   = (float*)sym(g_f0);
    float*  x1   = (float*)sym(g_x1);
    float*  x2   = (float*)sym(g_x2);
    float*  x3   = (float*)sym(g_x3);
    float*  x4   = (float*)sym(g_x4);
    float*  pd   = (float*)sym(g_pd);
    int*    idx  = (int*)  sym(g_idx);
    float*  wa   = (float*)sym(g_wa);
    float*  wd   = (float*)sym(g_wd);
    float*  Tb   = (float*)sym(g_T);
    float*  hmax = (float*)sym(g_hmax);
    float*  hmin = (float*)sym(g_hmin);
    float*  Pb   = (float*)sym(g_P);
    float*  gmax = (float*)sym(g_gmax);
    double* s0   = (double*)sym(g_sum);
    double* s2   = (double*)sym(g_sum2);
    float*  sc   = (float*)sym(g_scale);
    float*  sh   = (float*)sym(g_shift);

    // input transpose (B,3,N) -> (B,N,3)
    transpose_in_kernel<<<(NB*3*NPTS + 255)/256, 256>>>(x, f0);

    const float* feats[4] = { f0, x1, x2, x3 };
    float*       outs [4] = { x1, x2, x3, x4 };
    const int    Cs[4] = { 3, 64, 64, 128 };
    const int    Os[4] = { 64, 64, 128, 256 };

    for (int L = 0; L < 4; L++) {
        int C = Cs[L], O = Os[L];
        const float* feat = feats[L];

        // order: prep_w(2), dist(3), topk(4 on L0 -> ncu capture slot), gemmT(5)
        prep_w_kernel<<<(O*C + 255)/256, 256>>>(W[L], O, C, wa, wd, s0, s2);

        dim3 ggrid(NPAIRS, 1, NB);
        if (C == 3) dist_sym_kernel<4><<<ggrid, 256>>>(feat, pd, C);
        else        dist_sym_kernel<16><<<ggrid, 256>>>(feat, pd, C);
        topk_warp_kernel<<<BNTOT/TK_WARPS, TK_WARPS*32>>>(pd, idx);

        gemm_nt_kernel<<<dim3((BNTOT + 127)/128, O/64), 256>>>(
            feat, wd, Tb, BNTOT, O, C, nullptr, nullptr);

        fused_edge_kernel<<<dim3(BNTOT/FP, O/64), 256>>>(
            feat, wa, Tb, idx, C, O, hmax, hmin, s0, s2);
        bn_params_kernel<<<1, 256>>>(s0, s2, G[L], Bb[L], O, (double)MEDGE, sc, sh);
        edge_finalize_kernel<<<(BNTOT*O + 255)/256, 256>>>(hmax, hmin, sc, sh, outs[L], O);
    }

    // --- point conv h6 = lrelu(bn(x4 . W6^T)), then x5 = max over n ---
    // (stats accumulators already zeroed by the last bn_params)
    gemm_nt_kernel<<<dim3(BNTOT/128, 256/64), 256>>>(x4, W6, Pb, BNTOT, 256, 256, s0, s2);
    bn_params_kernel<<<1, 256>>>(s0, s2, g6, b6, 256, (double)BNTOT, sc, sh);
    h6_finalize_kernel<<<dim3(256/64, NB), 256>>>(Pb, sc, sh, gmax);

    // --- final point conv over virtual concat + BN stats fused ---
    gemm_cat_kernel<<<dim3(BNTOT/128, 256/64), 256>>>(
        x1, x2, x3, x4, gmax, W5, Pb, s0, s2);
    bn_params_kernel<<<1, 256>>>(s0, s2, g5, b5, 256, (double)BNTOT, sc, sh);
    out_transpose_kernel<<<dim3(NPTS/32, 256/32, NB), dim3(32, 32)>>>(Pb, sc, sh, (float*)d_out);
}

// round 17
// speedup vs baseline: 1.5950x; 1.0245x over previous
#include <cuda_runtime.h>
#include <cuda_bf16.h>
#include <math.h>

// ---------------------------------------------------------------------------
// Problem constants
// ---------------------------------------------------------------------------
#define NB 8
#define NPTS 2048
#define BNTOT (NB*NPTS)          // 16384
#define KNN 20
#define MEDGE (BNTOT*KNN)        // 327680
#define NEG_SLOPE 0.2f
#define BN_EPS 1e-5f
#define NT 16                    // 2048/128 tiles per dim
#define NPAIRS (NT*(NT+1)/2)     // 136

typedef unsigned long long u64;

// ---------------------------------------------------------------------------
// Packed fp32x2 helpers: per-half rounding identical to scalar ops.
// ---------------------------------------------------------------------------
__device__ __forceinline__ u64 f2_pack(float lo, float hi) {
    u64 d;
    asm("mov.b64 %0, {%1, %2};" : "=l"(d)
        : "r"(__float_as_uint(lo)), "r"(__float_as_uint(hi)));
    return d;
}
__device__ __forceinline__ float2 f2_unpack(u64 d) {
    unsigned lo, hi;
    asm("mov.b64 {%0, %1}, %2;" : "=r"(lo), "=r"(hi) : "l"(d));
    return make_float2(__uint_as_float(lo), __uint_as_float(hi));
}
__device__ __forceinline__ u64 f2_fma(u64 a, u64 b, u64 c) {
    u64 d;
    asm("fma.rn.f32x2 %0, %1, %2, %3;" : "=l"(d) : "l"(a), "l"(b), "l"(c));
    return d;
}
__device__ __forceinline__ u64 f2_add(u64 a, u64 b) {
    u64 d;
    asm("add.rn.f32x2 %0, %1, %2;" : "=l"(d) : "l"(a), "l"(b));
    return d;
}

// Monotonic u32 key for float ordering (no +0.0 in pd -> float-equal == bit-equal)
__device__ __forceinline__ unsigned fkey(float f) {
    unsigned b = __float_as_uint(f);
    return b ^ (unsigned)(((int)b >> 31) | 0x80000000);
}

// ---------------------------------------------------------------------------
// Scratch (device globals -- no allocation allowed)
// ---------------------------------------------------------------------------
__device__ float g_f0  [BNTOT*3];
__device__ float g_x1  [BNTOT*64];
__device__ float g_x2  [BNTOT*64];
__device__ float g_x3  [BNTOT*128];
__device__ float g_x4  [BNTOT*256];
__device__ float g_pd  [(size_t)NB*NPTS*NPTS];       // 134 MB
__device__ int   g_idx [MEDGE];
__device__ float g_wa  [256*128];
__device__ float g_wd  [256*128];
__device__ float g_T   [BNTOT*256];
__device__ float g_hmax[BNTOT*256];
__device__ float g_hmin[BNTOT*256];
__device__ float g_P   [BNTOT*256];
__device__ float g_gmax[NB*256];
__device__ double g_sum [256];
__device__ double g_sum2[256];
__device__ float g_scale[256];
__device__ float g_shift[256];

// ---------------------------------------------------------------------------
// Small elementwise kernels
// ---------------------------------------------------------------------------
__global__ void transpose_in_kernel(const float* __restrict__ x, float* __restrict__ f) {
    int i = blockIdx.x*256 + threadIdx.x;                 // B*3*N = 49152
    if (i >= NB*3*NPTS) return;
    int b = i / (3*NPTS);
    int rem = i - b*3*NPTS;
    int c = rem / NPTS;
    int n = rem - c*NPTS;
    f[(b*NPTS + n)*3 + c] = x[i];
}

// prep_w also zeroes the BN stat accumulators (block 0) -- saves a launch.
__global__ void prep_w_kernel(const float* __restrict__ W, int O, int C,
                              float* __restrict__ wa, float* __restrict__ wd,
                              double* __restrict__ s0, double* __restrict__ s2) {
    int i = blockIdx.x*256 + threadIdx.x;
    if (blockIdx.x == 0) { s0[threadIdx.x] = 0.0; s2[threadIdx.x] = 0.0; }
    if (i >= O*C) return;
    int o = i / C, c = i - o*C;
    float a = W[o*2*C + c];
    wa[i] = a;
    wd[i] = W[o*2*C + C + c] - a;
}

// ---------------------------------------------------------------------------
// SYMMETRIC squared-distance kernel: pd[b,i,j] = -sum_c (x_i[c]-x_j[c])^2
// ---------------------------------------------------------------------------
template<int KS>
__global__ __launch_bounds__(256)
void dist_sym_kernel(const float* __restrict__ feat, float* __restrict__ pd, int C) {
    __shared__ __align__(16) float As[KS][132];
    __shared__ __align__(16) float Bs[KS][132];
    int b = blockIdx.z;
    int Lp = blockIdx.x;
    int ti = 0;
    while (Lp >= NT - ti) { Lp -= NT - ti; ti++; }
    int tj = ti + Lp;
    int m0 = ti*128, n0 = tj*128;
    bool diag = (ti == tj);

    const float* F = feat + (size_t)b*NPTS*C;
    int tid = threadIdx.x;
    int tx = tid & 15, ty = tid >> 4;

    u64 acc2[8][4];
#pragma unroll
    for (int i = 0; i < 8; i++)
#pragma unroll
        for (int j = 0; j < 4; j++) acc2[i][j] = 0ull;

    for (int k0 = 0; k0 < C; k0 += KS) {
#pragma unroll
        for (int e = tid; e < 128*KS; e += 256) {
            int c = e % KS, r = e / KS;
            float va = 0.f, vb = 0.f;
            if (k0 + c < C) {
                va = F[(size_t)(m0 + r)*C + k0 + c];
                vb = F[(size_t)(n0 + r)*C + k0 + c];
            }
            As[c][r] = va;
            Bs[c][r] = -vb;          // negate so inner loop uses add.f32x2
        }
        __syncthreads();
#pragma unroll
        for (int k = 0; k < KS; k++) {
            float af[8];
#pragma unroll
            for (int i = 0; i < 8; i++) af[i] = As[k][ty*8 + i];
            const u64* bp = (const u64*)&Bs[k][tx*8];
            u64 b2[4] = { bp[0], bp[1], bp[2], bp[3] };
#pragma unroll
            for (int i = 0; i < 8; i++) {
                u64 a2 = f2_pack(af[i], af[i]);
#pragma unroll
                for (int jp = 0; jp < 4; jp++) {
                    u64 d2 = f2_add(a2, b2[jp]);       // (a-b0, a-b1)
                    acc2[i][jp] = f2_fma(d2, d2, acc2[i][jp]);
                }
            }
        }
        __syncthreads();
    }

    float neg[8][8];
#pragma unroll
    for (int i = 0; i < 8; i++)
#pragma unroll
        for (int jp = 0; jp < 4; jp++) {
            float2 v = f2_unpack(acc2[i][jp]);
            neg[i][2*jp]   = -v.x;
            neg[i][2*jp+1] = -v.y;
        }

    float* pdb = pd + (size_t)b*NPTS*NPTS;
#pragma unroll
    for (int i = 0; i < 8; i++) {
        int m = m0 + ty*8 + i;
        float4 w0 = make_float4(neg[i][0], neg[i][1], neg[i][2], neg[i][3]);
        float4 w1 = make_float4(neg[i][4], neg[i][5], neg[i][6], neg[i][7]);
        float4* dst = (float4*)&pdb[(size_t)m*NPTS + n0 + tx*8];
        dst[0] = w0;
        dst[1] = w1;
    }
    if (!diag) {
#pragma unroll
        for (int j = 0; j < 8; j++) {
            int n = n0 + tx*8 + j;
            float4 w0 = make_float4(neg[0][j], neg[1][j], neg[2][j], neg[3][j]);
            float4 w1 = make_float4(neg[4][j], neg[5][j], neg[6][j], neg[7][j]);
            float4* dst = (float4*)&pdb[(size_t)n*NPTS + m0 + ty*8];
            dst[0] = w0;
            dst[1] = w1;
        }
    }
}

// ---------------------------------------------------------------------------
// WARP-PER-ROW top-K with monotonic u32 keys in smem + packed-u64 reduce.
// key = fkey(value) preserves float order; packed (key<<32)|~ix makes the
// warp argmax a single u64 max (value desc, index asc == jax top_k order).
// Poison = key 0 (below all real keys). idx bitwise identical.
// ---------------------------------------------------------------------------
#define TK_WARPS 4
__global__ __launch_bounds__(TK_WARPS*32)
void topk_warp_kernel(const float* __restrict__ pd, int* __restrict__ idx) {
    __shared__ unsigned sv [TK_WARPS][NPTS];
    __shared__ unsigned sgv[TK_WARPS][8][32];
    __shared__ int      sgm[TK_WARPS][8][32];
    int w = threadIdx.x >> 5, l = threadIdx.x & 31;
    int bn = blockIdx.x*TK_WARPS + w;
    const float* row = pd + (size_t)bn*NPTS;
    unsigned* v = sv[w];

    // load row (coalesced), convert to keys, per-lane group maxima
    unsigned gv[8]; int gm[8];
#pragma unroll
    for (int g = 0; g < 8; g++) { gv[g] = 0u; gm[g] = g*8; }
#pragma unroll
    for (int off = 0; off < 64; off++) {
        unsigned k = fkey(row[off*32 + l]);
        v[off*32 + l] = k;
        int g = off >> 3;                      // compile-time after unroll
        if (k > gv[g]) { gv[g] = k; gm[g] = off; }   // strict > keeps lowest off
    }
    unsigned myk = 0u; int myoff = 0;
#pragma unroll
    for (int g = 0; g < 8; g++) {
        sgv[w][g][l] = gv[g]; sgm[w][g][l] = gm[g];
        if (gv[g] > myk) { myk = gv[g]; myoff = gm[g]; }
    }
    u64 mykey = ((u64)myk << 32) | (unsigned)~(myoff*32 + l);
    // warp-private smem, each lane touches only its own slots: no sync needed

    int my_out = 0;
    for (int it = 0; it < KNN; it++) {
        u64 kk = mykey;
#pragma unroll
        for (int s = 16; s > 0; s >>= 1) {
            u64 ok = __shfl_xor_sync(0xffffffff, kk, s);
            if (ok > kk) kk = ok;
        }
        int ix = (int)~(unsigned)kk;           // winner global column index
        if (l == it) my_out = ix;

        int owner = ix & 31;
        if (l == owner) {
            int off = ix >> 5;
            v[off*32 + l] = 0u;                // poison winner slot
            int g = off >> 3;
            int base = g*8;
            unsigned bv2 = 0u; int bo2 = base;
#pragma unroll
            for (int m = 0; m < 8; m++) {
                unsigned x = v[(base + m)*32 + l];
                if (x > bv2) { bv2 = x; bo2 = base + m; }
            }
            sgv[w][g][l] = bv2;
            sgm[w][g][l] = bo2;
            unsigned nb = 0u; int ng = 0;
#pragma unroll
            for (int g2 = 0; g2 < 8; g2++) {
                unsigned x = sgv[w][g2][l];
                if (x > nb) { nb = x; ng = g2; }
            }
            mykey = ((u64)nb << 32) | (unsigned)~(sgm[w][ng][l]*32 + l);
        }
    }
    if (l < KNN) idx[bn*KNN + l] = my_out;
}

// ---------------------------------------------------------------------------
// Generic NT GEMM: C[m,n] = sum_k A[m,k]*B[n,k], f32x2 inner, LDG prefetch.
// Optional fused per-channel sum/sumsq (BN stats) via block partials + atomics.
// ---------------------------------------------------------------------------
__global__ __launch_bounds__(256)
void gemm_nt_kernel(const float* __restrict__ A, const float* __restrict__ B,
                    float* __restrict__ C, int M, int N, int K,
                    double* __restrict__ gsum, double* __restrict__ gsum2) {
    __shared__ __align__(16) float As[16][129];
    __shared__ __align__(16) float Bs[16][66];
    int tid = threadIdx.x;
    int tx = tid & 15;
    int ty = tid >> 4;
    int m0 = blockIdx.x * 128;
    int n0 = blockIdx.y * 64;

    u64 acc2[8][2];
#pragma unroll
    for (int i = 0; i < 8; i++) { acc2[i][0] = 0ull; acc2[i][1] = 0ull; }

    float pa[8], pb[4];
#pragma unroll
    for (int i = 0; i < 8; i++) {
        int e = tid + i*256;
        int c = e & 15, r = e >> 4;
        int m = m0 + r;
        pa[i] = (m < M && c < K) ? A[(size_t)m*K + c] : 0.f;
    }
#pragma unroll
    for (int i = 0; i < 4; i++) {
        int e = tid + i*256;
        int c = e & 15, r = e >> 4;
        pb[i] = (c < K) ? B[(size_t)(n0 + r)*K + c] : 0.f;
    }

    for (int k0 = 0; k0 < K; k0 += 16) {
#pragma unroll
        for (int i = 0; i < 8; i++) {
            int e = tid + i*256;
            As[e & 15][e >> 4] = pa[i];
        }
#pragma unroll
        for (int i = 0; i < 4; i++) {
            int e = tid + i*256;
            Bs[e & 15][e >> 4] = pb[i];
        }
        __syncthreads();
        int kn = k0 + 16;
        if (kn < K) {
#pragma unroll
            for (int i = 0; i < 8; i++) {
                int e = tid + i*256;
                int c = e & 15, r = e >> 4;
                int m = m0 + r;
                pa[i] = (m < M && kn + c < K) ? A[(size_t)m*K + kn + c] : 0.f;
            }
#pragma unroll
            for (int i = 0; i < 4; i++) {
                int e = tid + i*256;
                int c = e & 15, r = e >> 4;
                pb[i] = (kn + c < K) ? B[(size_t)(n0 + r)*K + kn + c] : 0.f;
            }
        }
#pragma unroll
        for (int k = 0; k < 16; k++) {
            const u64* bp = (const u64*)&Bs[k][tx*4];
            u64 b0 = bp[0], b1 = bp[1];
#pragma unroll
            for (int i = 0; i < 8; i++) {
                float a = As[k][ty*8 + i];
                u64 a2 = f2_pack(a, a);
                acc2[i][0] = f2_fma(a2, b0, acc2[i][0]);
                acc2[i][1] = f2_fma(a2, b1, acc2[i][1]);
            }
        }
        __syncthreads();
    }

    float cs[4] = {0.f,0.f,0.f,0.f}, cq[4] = {0.f,0.f,0.f,0.f};
#pragma unroll
    for (int i = 0; i < 8; i++) {
        int m = m0 + ty*8 + i;
        if (m >= M) continue;
        float2 v0 = f2_unpack(acc2[i][0]);
        float2 v1 = f2_unpack(acc2[i][1]);
        float* dst = &C[(size_t)m*N + n0 + tx*4];
        dst[0] = v0.x; dst[1] = v0.y; dst[2] = v1.x; dst[3] = v1.y;
        cs[0] += v0.x; cq[0] += v0.x*v0.x;
        cs[1] += v0.y; cq[1] += v0.y*v0.y;
        cs[2] += v1.x; cq[2] += v1.x*v1.x;
        cs[3] += v1.y; cq[3] += v1.y*v1.y;
    }

    if (gsum) {
        float* sred = &As[0][0];
#pragma unroll
        for (int j = 0; j < 4; j++) {
            sred[ty*64 + tx*4 + j]        = cs[j];
            sred[1024 + ty*64 + tx*4 + j] = cq[j];
        }
        __syncthreads();
        if (tid < 64) {
            float S = 0.f, Q = 0.f;
#pragma unroll
            for (int t = 0; t < 16; t++) {
                S += sred[t*64 + tid];
                Q += sred[1024 + t*64 + tid];
            }
            atomicAdd(&gsum[n0 + tid],  (double)S);
            atomicAdd(&gsum2[n0 + tid], (double)Q);
        }
    }
}

// ---------------------------------------------------------------------------
// GEMM over the virtual concat [x1|x2|x3|x4|gmax] (K=768), fused BN stats.
// ---------------------------------------------------------------------------
__device__ __forceinline__ float cat_fetch(int m, int c,
                                           const float* __restrict__ x1,
                                           const float* __restrict__ x2,
                                           const float* __restrict__ x3,
                                           const float* __restrict__ x4,
                                           const float* __restrict__ gmax) {
    if (c < 64)   return x1[m*64 + c];
    if (c < 128)  return x2[m*64 + c - 64];
    if (c < 256)  return x3[m*128 + c - 128];
    if (c < 512)  return x4[m*256 + c - 256];
    return gmax[(m >> 11)*256 + c - 512];
}

__global__ __launch_bounds__(256)
void gemm_cat_kernel(const float* __restrict__ x1, const float* __restrict__ x2,
                     const float* __restrict__ x3, const float* __restrict__ x4,
                     const float* __restrict__ gmax,
                     const float* __restrict__ B,
                     float* __restrict__ C,
                     double* __restrict__ gsum, double* __restrict__ gsum2) {
    const int N = 256, K = 768;
    __shared__ __align__(16) float As[16][129];
    __shared__ __align__(16) float Bs[16][66];
    int tid = threadIdx.x;
    int tx = tid & 15;
    int ty = tid >> 4;
    int m0 = blockIdx.x * 128;
    int n0 = blockIdx.y * 64;

    u64 acc2[8][2];
#pragma unroll
    for (int i = 0; i < 8; i++) { acc2[i][0] = 0ull; acc2[i][1] = 0ull; }

    float pa[8], pb[4];
#pragma unroll
    for (int i = 0; i < 8; i++) {
        int e = tid + i*256;
        int c = e & 15, r = e >> 4;
        pa[i] = cat_fetch(m0 + r, c, x1, x2, x3, x4, gmax);
    }
#pragma unroll
    for (int i = 0; i < 4; i++) {
        int e = tid + i*256;
        int c = e & 15, r = e >> 4;
        pb[i] = B[(size_t)(n0 + r)*K + c];
    }

    for (int k0 = 0; k0 < K; k0 += 16) {
#pragma unroll
        for (int i = 0; i < 8; i++) {
            int e = tid + i*256;
            As[e & 15][e >> 4] = pa[i];
        }
#pragma unroll
        for (int i = 0; i < 4; i++) {
            int e = tid + i*256;
            Bs[e & 15][e >> 4] = pb[i];
        }
        __syncthreads();
        int kn = k0 + 16;
        if (kn < K) {
#pragma unroll
            for (int i = 0; i < 8; i++) {
                int e = tid + i*256;
                int c = e & 15, r = e >> 4;
                pa[i] = cat_fetch(m0 + r, kn + c, x1, x2, x3, x4, gmax);
            }
#pragma unroll
            for (int i = 0; i < 4; i++) {
                int e = tid + i*256;
                int c = e & 15, r = e >> 4;
                pb[i] = B[(size_t)(n0 + r)*K + kn + c];
            }
        }
#pragma unroll
        for (int k = 0; k < 16; k++) {
            const u64* bp = (const u64*)&Bs[k][tx*4];
            u64 b0 = bp[0], b1 = bp[1];
#pragma unroll
            for (int i = 0; i < 8; i++) {
                float a = As[k][ty*8 + i];
                u64 a2 = f2_pack(a, a);
                acc2[i][0] = f2_fma(a2, b0, acc2[i][0]);
                acc2[i][1] = f2_fma(a2, b1, acc2[i][1]);
            }
        }
        __syncthreads();
    }

    float cs[4] = {0.f,0.f,0.f,0.f}, cq[4] = {0.f,0.f,0.f,0.f};
#pragma unroll
    for (int i = 0; i < 8; i++) {
        int m = m0 + ty*8 + i;
        float2 v0 = f2_unpack(acc2[i][0]);
        float2 v1 = f2_unpack(acc2[i][1]);
        float* dst = &C[(size_t)m*N + n0 + tx*4];
        dst[0] = v0.x; dst[1] = v0.y; dst[2] = v1.x; dst[3] = v1.y;
        cs[0] += v0.x; cq[0] += v0.x*v0.x;
        cs[1] += v0.y; cq[1] += v0.y*v0.y;
        cs[2] += v1.x; cq[2] += v1.x*v1.x;
        cs[3] += v1.y; cq[3] += v1.y*v1.y;
    }

    float* sred = &As[0][0];
#pragma unroll
    for (int j = 0; j < 4; j++) {
        sred[ty*64 + tx*4 + j]        = cs[j];
        sred[1024 + ty*64 + tx*4 + j] = cq[j];
    }
    __syncthreads();
    if (tid < 64) {
        float S = 0.f, Q = 0.f;
#pragma unroll
        for (int t = 0; t < 16; t++) {
            S += sred[t*64 + tid];
            Q += sred[1024 + t*64 + tid];
        }
        atomicAdd(&gsum[n0 + tid],  (double)S);
        atomicAdd(&gsum2[n0 + tid], (double)Q);
    }
}

// ---------------------------------------------------------------------------
// FUSED edge-conv: 8 points x 20 neighbors (160 rows) x 64 channels, f32x2.
// Warp w owns ALL 20 rows of point w -> the k-reduction is done entirely in
// registers + two shfl_xor steps (no smem staging, no extra barriers).
// B rows stored split-half (conflict-free LDS.128).
// ---------------------------------------------------------------------------
#define FP    8
#define FROWS (FP*KNN)            // 160
#define AS_STRIDE 161             // 161 % 32 == 1  -> conflict-free
#define BS_BASE   (16*AS_STRIDE)  // 2576 floats (16B aligned: 2576*4 = 644*16)
#define BS_STRIDE 68              // rows 16B aligned

__device__ __forceinline__ int b_loc(int n) {
    return ((n >> 3) << 2) + (n & 3) + (((n >> 2) & 1) << 5);
}

__global__ __launch_bounds__(256)
void fused_edge_kernel(const float* __restrict__ feat,   // [BNTOT, C]
                       const float* __restrict__ wa,     // [O, C]
                       const float* __restrict__ T,      // [BNTOT, O]
                       const int* __restrict__ idx,      // [BNTOT, KNN]
                       int C, int O,
                       float* __restrict__ hmax, float* __restrict__ hmin,
                       double* __restrict__ gsum, double* __restrict__ gsum2) {
    __shared__ __align__(16) float pool[BS_BASE + 16*BS_STRIDE];  // 3664 floats
    __shared__ int   sidx[FROWS];
    __shared__ float sT[FP*64];

    int tid = threadIdx.x;
    int p0  = blockIdx.x * FP;
    int n0  = blockIdx.y * 64;

    if (tid < FROWS) {
        int p  = tid / KNN;
        int k  = tid - p*KNN;
        int bn = p0 + p;
        sidx[tid] = (bn >> 11)*NPTS + idx[bn*KNN + k];
    }
    {
        int e = tid;
        sT[e] = T[(size_t)(p0 + (e >> 6))*O + n0 + (e & 63)];
        e += 256;
        sT[e] = T[(size_t)(p0 + (e >> 6))*O + n0 + (e & 63)];
    }
    __syncthreads();

    int tx = tid & 7;
    int ty = tid >> 3;

    u64 acc2[5][4];
#pragma unroll
    for (int i = 0; i < 5; i++)
#pragma unroll
        for (int j = 0; j < 4; j++) acc2[i][j] = 0ull;

    float pa[10], pb[4];
#pragma unroll
    for (int i = 0; i < 10; i++) {
        int e = tid + i*256;
        int c = e & 15, r = e >> 4;
        pa[i] = (c < C) ? feat[(size_t)sidx[r]*C + c] : 0.f;
    }
#pragma unroll
    for (int i = 0; i < 4; i++) {
        int e = tid + i*256;
        int c = e & 15, r = e >> 4;
        pb[i] = (c < C) ? wa[(size_t)(n0 + r)*C + c] : 0.f;
    }

    for (int k0 = 0; k0 < C; k0 += 16) {
#pragma unroll
        for (int i = 0; i < 10; i++) {
            int e = tid + i*256;
            pool[(e & 15)*AS_STRIDE + (e >> 4)] = pa[i];
        }
#pragma unroll
        for (int i = 0; i < 4; i++) {
            int e = tid + i*256;
            pool[BS_BASE + (e & 15)*BS_STRIDE + b_loc(e >> 4)] = pb[i];
        }
        __syncthreads();
        int kn = k0 + 16;
        if (kn < C) {
#pragma unroll
            for (int i = 0; i < 10; i++) {
                int e = tid + i*256;
                int c = e & 15, r = e >> 4;
                pa[i] = (kn + c < C) ? feat[(size_t)sidx[r]*C + kn + c] : 0.f;
            }
#pragma unroll
            for (int i = 0; i < 4; i++) {
                int e = tid + i*256;
                int c = e & 15, r = e >> 4;
                pb[i] = (kn + c < C) ? wa[(size_t)(n0 + r)*C + kn + c] : 0.f;
            }
        }
#pragma unroll
        for (int k = 0; k < 16; k++) {
            // split-half B: two conflict-free LDS.128 at tx*4 and 32+tx*4
            const u64* bpl = (const u64*)&pool[BS_BASE + k*BS_STRIDE + tx*4];
            const u64* bph = (const u64*)&pool[BS_BASE + k*BS_STRIDE + 32 + tx*4];
            u64 b2[4] = { bpl[0], bpl[1], bph[0], bph[1] };
#pragma unroll
            for (int i = 0; i < 5; i++) {
                float a = pool[k*AS_STRIDE + ty*5 + i];
                u64 a2 = f2_pack(a, a);
#pragma unroll
                for (int jp = 0; jp < 4; jp++)
                    acc2[i][jp] = f2_fma(a2, b2[jp], acc2[i][jp]);
            }
        }
        __syncthreads();
    }

    // ---- register epilogue: warp wp == point p0+wp ----
    int wp = tid >> 5;
    int lane = tid & 31;
    float t8[8];
#pragma unroll
    for (int j = 0; j < 8; j++) t8[j] = sT[wp*64 + tx*8 + j];

    float cmax[8], cmin[8], csum[8], csq[8];
#pragma unroll
    for (int j = 0; j < 8; j++) {
        cmax[j] = -INFINITY; cmin[j] = INFINITY; csum[j] = 0.f; csq[j] = 0.f;
    }
#pragma unroll
    for (int i = 0; i < 5; i++)
#pragma unroll
        for (int jp = 0; jp < 4; jp++) {
            float2 v = f2_unpack(acc2[i][jp]);
            float h0 = v.x + t8[2*jp];
            float h1 = v.y + t8[2*jp+1];
            cmax[2*jp]   = fmaxf(cmax[2*jp], h0);   cmin[2*jp]   = fminf(cmin[2*jp], h0);
            csum[2*jp]  += h0;                      csq[2*jp]    = fmaf(h0, h0, csq[2*jp]);
            cmax[2*jp+1] = fmaxf(cmax[2*jp+1], h1); cmin[2*jp+1] = fminf(cmin[2*jp+1], h1);
            csum[2*jp+1]+= h1;                      csq[2*jp+1]  = fmaf(h1, h1, csq[2*jp+1]);
        }
    // combine the 4 ty-subgroups within the warp (lanes xor 8, xor 16)
#pragma unroll
    for (int s = 8; s <= 16; s <<= 1)
#pragma unroll
        for (int j = 0; j < 8; j++) {
            cmax[j] = fmaxf(cmax[j], __shfl_xor_sync(0xffffffff, cmax[j], s));
            cmin[j] = fminf(cmin[j], __shfl_xor_sync(0xffffffff, cmin[j], s));
            csum[j] += __shfl_xor_sync(0xffffffff, csum[j], s);
            csq[j]  += __shfl_xor_sync(0xffffffff, csq[j],  s);
        }
    if (lane < 8) {
        size_t oi = (size_t)(p0 + wp)*O + n0 + tx*8;
        *(float4*)&hmax[oi]     = make_float4(cmax[0], cmax[1], cmax[2], cmax[3]);
        *(float4*)&hmax[oi + 4] = make_float4(cmax[4], cmax[5], cmax[6], cmax[7]);
        *(float4*)&hmin[oi]     = make_float4(cmin[0], cmin[1], cmin[2], cmin[3]);
        *(float4*)&hmin[oi + 4] = make_float4(cmin[4], cmin[5], cmin[6], cmin[7]);
#pragma unroll
        for (int j = 0; j < 8; j++) {
            pool[wp*64 + tx*8 + j]       = csum[j];
            pool[512 + wp*64 + tx*8 + j] = csq[j];
        }
    }
    __syncthreads();
    if (tid < 64) {
        float S = 0.f, Q = 0.f;
#pragma unroll
        for (int t = 0; t < 8; t++) {
            S += pool[t*64 + tid];
            Q += pool[512 + t*64 + tid];
        }
        atomicAdd(&gsum[n0 + tid],  (double)S);
        atomicAdd(&gsum2[n0 + tid], (double)Q);
    }
}

// bn_params: computes scale/shift, then ZEROES the accumulators for the next
// user (removes standalone zero_stats launches; replay-safe).
__global__ void bn_params_kernel(double* __restrict__ gsum, double* __restrict__ gsum2,
                                 const float* __restrict__ g, const float* __restrict__ b,
                                 int O, double cnt,
                                 float* __restrict__ scale, float* __restrict__ shift) {
    int o = threadIdx.x;
    if (o < O) {
        double m   = gsum[o] / cnt;
        double var = gsum2[o] / cnt - m*m;
        float sc = g[o] * rsqrtf((float)var + BN_EPS);
        scale[o] = sc;
        shift[o] = b[o] - (float)m * sc;
    }
    gsum[o] = 0.0;
    gsum2[o] = 0.0;
}

__global__ void edge_finalize_kernel(const float* __restrict__ hmax, const float* __restrict__ hmin,
                                     const float* __restrict__ scale, const float* __restrict__ shift,
                                     float* __restrict__ out, int O) {
    int i = blockIdx.x*256 + threadIdx.x;
    if (i >= BNTOT*O) return;
    int o = i & (O - 1);
    float sc = scale[o];
    float v = (sc >= 0.f ? hmax[i] : hmin[i]) * sc + shift[o];
    out[i] = v >= 0.f ? v : NEG_SLOPE*v;
}

// h6: act + global max over n per (b,o)
__global__ __launch_bounds__(256)
void h6_finalize_kernel(const float* __restrict__ P,
                        const float* __restrict__ scale, const float* __restrict__ shift,
                        float* __restrict__ gmax) {
    int ol = threadIdx.x & 63;
    int gi = threadIdx.x >> 6;
    int o = blockIdx.x*64 + ol;
    int b = blockIdx.y;
    float sc = scale[o], sh = shift[o];
    float mx = -INFINITY;
    for (int n = gi*512; n < (gi+1)*512; n++) {
        float v = P[((size_t)(b*NPTS + n))*256 + o]*sc + sh;
        v = v >= 0.f ? v : NEG_SLOPE*v;
        mx = fmaxf(mx, v);
    }
    __shared__ float sm[4][64];
    sm[gi][ol] = mx;
    __syncthreads();
    if (gi == 0)
        gmax[b*256 + o] = fmaxf(fmaxf(sm[0][ol], sm[1][ol]), fmaxf(sm[2][ol], sm[3][ol]));
}

// final: act + transpose (B,N,256) -> (B,256,N)
__global__ void out_transpose_kernel(const float* __restrict__ P,
                                     const float* __restrict__ scale, const float* __restrict__ shift,
                                     float* __restrict__ out) {
    __shared__ float tile[32][33];
    int b  = blockIdx.z;
    int n0 = blockIdx.x*32, o0 = blockIdx.y*32;
    int tx = threadIdx.x, ty = threadIdx.y;
    int o = o0 + tx;
    float v = P[((size_t)(b*NPTS + n0 + ty))*256 + o]*scale[o] + shift[o];
    v = v >= 0.f ? v : NEG_SLOPE*v;
    tile[ty][tx] = v;
    __syncthreads();
    out[(size_t)b*256*NPTS + (size_t)(o0 + ty)*NPTS + n0 + tx] = tile[tx][ty];
}

// ---------------------------------------------------------------------------
// Host side
// ---------------------------------------------------------------------------
static void* sym(const void* s) { void* p = nullptr; cudaGetSymbolAddress(&p, s); return p; }

extern "C" void kernel_launch(void* const* d_in, const int* in_sizes, int n_in,
                              void* d_out, int out_size) {
    const float* x  = (const float*)d_in[0];
    const float* W[4] = { (const float*)d_in[1], (const float*)d_in[4],
                          (const float*)d_in[7], (const float*)d_in[10] };
    const float* G[4] = { (const float*)d_in[2], (const float*)d_in[5],
                          (const float*)d_in[8], (const float*)d_in[11] };
    const float* Bb[4] = { (const float*)d_in[3], (const float*)d_in[6],
                           (const float*)d_in[9], (const float*)d_in[12] };
    const float* W6 = (const float*)d_in[13];
    const float* g6 = (const float*)d_in[14];
    const float* b6 = (const float*)d_in[15];
    const float* W5 = (const float*)d_in[16];
    const float* g5 = (const float*)d_in[17];
    const float* b5 = (const float*)d_in[18];

    float*  f0   = (float*)sym(g_f0);
    float*  x1   = (float*)sym(g_x1);
    float*  x2   = (float*)sym(g_x2);
    float*  x3   = (float*)sym(g_x3);
    float*  x4   = (float*)sym(g_x4);
    float*  pd   = (float*)sym(g_pd);
    int*    idx  = (int*)  sym(g_idx);
    float*  wa   = (float*)sym(g_wa);
    float*  wd   = (float*)sym(g_wd);
    float*  Tb   = (float*)sym(g_T);
    float*  hmax = (float*)sym(g_hmax);
    float*  hmin = (float*)sym(g_hmin);
    float*  Pb   = (float*)sym(g_P);
    float*  gmax = (float*)sym(g_gmax);
    double* s0   = (double*)sym(g_sum);
    double* s2   = (double*)sym(g_sum2);
    float*  sc   = (float*)sym(g_scale);
    float*  sh   = (float*)sym(g_shift);

    // input transpose (B,3,N) -> (B,N,3)
    transpose_in_kernel<<<(NB*3*NPTS + 255)/256, 256>>>(x, f0);

    const float* feats[4] = { f0, x1, x2, x3 };
    float*       outs [4] = { x1, x2, x3, x4 };
    const int    Cs[4] = { 3, 64, 64, 128 };
    const int    Os[4] = { 64, 64, 128, 256 };

    for (int L = 0; L < 4; L++) {
        int C = Cs[L], O = Os[L];
        const float* feat = feats[L];

        // order: prep_w(2), dist(3), topk(4 on L0 -> ncu capture slot), gemmT(5)
        prep_w_kernel<<<(O*C + 255)/256, 256>>>(W[L], O, C, wa, wd, s0, s2);

        dim3 ggrid(NPAIRS, 1, NB);
        if (C == 3) dist_sym_kernel<4><<<ggrid, 256>>>(feat, pd, C);
        else        dist_sym_kernel<16><<<ggrid, 256>>>(feat, pd, C);
        topk_warp_kernel<<<BNTOT/TK_WARPS, TK_WARPS*32>>>(pd, idx);

        gemm_nt_kernel<<<dim3((BNTOT + 127)/128, O/64), 256>>>(
            feat, wd, Tb, BNTOT, O, C, nullptr, nullptr);

        fused_edge_kernel<<<dim3(BNTOT/FP, O/64), 256>>>(
            feat, wa, Tb, idx, C, O, hmax, hmin, s0, s2);
        bn_params_kernel<<<1, 256>>>(s0, s2, G[L], Bb[L], O, (double)MEDGE, sc, sh);
        edge_finalize_kernel<<<(BNTOT*O + 255)/256, 256>>>(hmax, hmin, sc, sh, outs[L], O);
    }

    // --- point conv h6 = lrelu(bn(x4 . W6^T)), then x5 = max over n ---
    // (stats accumulators already zeroed by the last bn_params)
    gemm_nt_kernel<<<dim3(BNTOT/128, 256/64), 256>>>(x4, W6, Pb, BNTOT, 256, 256, s0, s2);
    bn_params_kernel<<<1, 256>>>(s0, s2, g6, b6, 256, (double)BNTOT, sc, sh);
    h6_finalize_kernel<<<dim3(256/64, NB), 256>>>(Pb, sc, sh, gmax);

    // --- final point conv over virtual concat + BN stats fused ---
    gemm_cat_kernel<<<dim3(BNTOT/128, 256/64), 256>>>(
        x1, x2, x3, x4, gmax, W5, Pb, s0, s2);
    bn_params_kernel<<<1, 256>>>(s0, s2, g5, b5, 256, (double)BNTOT, sc, sh);
    out_transpose_kernel<<<dim3(NPTS/32, 256/32, NB), dim3(32, 32)>>>(Pb, sc, sh, (float*)d_out);
}